// round 2
// baseline (speedup 1.0000x reference)
#include <cuda_runtime.h>
#include <cuda_bf16.h>
#include <stdint.h>

// ---------------------------------------------------------------------------
// Problem constants
// ---------------------------------------------------------------------------
#define N_ROBOT 100000
#define N_BALL  100000
#define D_IN    128
#define H_DIM   128
#define OUT_DIM 64

// ---------------------------------------------------------------------------
// Scratch (device globals; allocation is forbidden)
// Layout offsets in floats:
// ---------------------------------------------------------------------------
#define O_AGG_RR0  0ull                                   // 100000*128
#define O_AGG_BR0  (O_AGG_RR0 + 12800000ull)
#define O_AGG_RB0  (O_AGG_BR0 + 12800000ull)
#define O_R        (O_AGG_RB0 + 12800000ull)              // robot hidden
#define O_BL       (O_R       + 12800000ull)              // ball hidden
#define O_TRR      (O_BL      + 12800000ull)              // r @ Wl1_rr   [100000*64]
#define O_TBR      (O_TRR     + 6400000ull)               // bl @ Wl1_br  [100000*64]
#define O_AGG_RR1  (O_TBR     + 6400000ull)               // [100000*64]
#define O_AGG_BR1  (O_AGG_RR1 + 6400000ull)               // [100000*64]
#define O_WSUM0    (O_AGG_BR1 + 6400000ull)               // 128*128
#define O_BSUM0    (O_WSUM0   + 16384ull)                 // 128
#define O_WSUM1    (O_BSUM0   + 128ull)                   // 128*64
#define O_BSUM1    (O_WSUM1   + 8192ull)                  // 64
#define SCRATCH_FLOATS (O_BSUM1 + 64ull)

__device__ float g_scratch[SCRATCH_FLOATS];
__device__ int   g_cnt[3 * N_ROBOT];   // cnt_rr | cnt_br | cnt_rb

// ---------------------------------------------------------------------------
// Kernels
// ---------------------------------------------------------------------------

// In-degree counts per destination. Edge indices are int32 (harness narrows
// the reference's int64 to int32 per the metadata contract).
__global__ void count_kernel(const int* __restrict__ dst,
                             int* __restrict__ cnt, int E) {
    int i = blockIdx.x * blockDim.x + threadIdx.x;
    if (i < E) atomicAdd(&cnt[dst[i]], 1);
}

// Elementwise sum of two small tensors (weight/bias folding).
__global__ void add2_kernel(const float* __restrict__ a,
                            const float* __restrict__ b,
                            float* __restrict__ o, int n) {
    int i = blockIdx.x * blockDim.x + threadIdx.x;
    if (i < n) o[i] = a[i] + b[i];
}

// Scatter-mean: agg[dst] += x[src] / cnt[dst].
// One thread per (edge, float4-chunk). A warp covers contiguous chunks, so for
// W=128 a warp reads one full 512B row coalesced and issues 32 v4 REDs.
__global__ void scatter_mean_kernel(const int* __restrict__ src,
                                    const int* __restrict__ dst,
                                    const int* __restrict__ cnt,
                                    const float* __restrict__ x,
                                    float* __restrict__ agg,
                                    int E, int chunks /* = W/4 */) {
    long long idx = (long long)blockIdx.x * blockDim.x + threadIdx.x;
    long long total = (long long)E * chunks;
    if (idx >= total) return;
    int e = (int)(idx / chunks);
    int c = (int)(idx - (long long)e * chunks);
    int s = src[e];
    int d = dst[e];
    float inv = 1.0f / (float)cnt[d];   // cnt >= 1: this dst has >=1 edge
    int W = chunks * 4;
    float4 v = *(const float4*)(x + (size_t)s * W + c * 4);
    v.x *= inv; v.y *= inv; v.z *= inv; v.w *= inv;
    float* p = agg + (size_t)d * W + c * 4;
    asm volatile("red.global.add.v4.f32 [%0], {%1, %2, %3, %4};"
                 :: "l"(p), "f"(v.x), "f"(v.y), "f"(v.z), "f"(v.w)
                 : "memory");
}

// Fused multi-term SGEMM:
//   out = relu?( sum_t A_t @ W_t  + bias + add0 + add1 )
// A_t: [M,128] row-major, W_t: [128,N] row-major, N in {128, 64}.
// Block = 256 threads (16x16), tile 64 rows x N cols, 4x(N/16) per thread.
template <int N, bool RELU>
__global__ void __launch_bounds__(256)
gemm_fused(int M,
           const float* __restrict__ A0, const float* __restrict__ W0,
           const float* __restrict__ A1, const float* __restrict__ W1,
           const float* __restrict__ A2, const float* __restrict__ W2,
           const float* __restrict__ bias,
           const float* __restrict__ add0,
           const float* __restrict__ add1,
           float* __restrict__ out) {
    constexpr int TM = 64, KT = 16, K = 128;
    constexpr int CT = N / 16;                 // cols per thread: 8 or 4

    __shared__ float As[TM][KT + 1];           // +1 pad: conflict-free column reads
    __shared__ float Bs[KT][N];

    const int tid = threadIdx.x;
    const int tx = tid & 15;
    const int ty = tid >> 4;
    const int row0 = blockIdx.x * TM;

    float acc[4][CT];
#pragma unroll
    for (int r = 0; r < 4; r++)
#pragma unroll
        for (int c = 0; c < CT; c++) acc[r][c] = 0.0f;

    const float* Aarr[3] = {A0, A1, A2};
    const float* Warr[3] = {W0, W1, W2};

    for (int t = 0; t < 3; t++) {
        const float* A = Aarr[t];
        if (A == nullptr) break;
        const float* W = Warr[t];

        for (int k0 = 0; k0 < K; k0 += KT) {
            // --- load A tile: 64 x 16 (256 float4, one per thread) ---
            {
                int ar = tid >> 2;             // 0..63
                int ac = (tid & 3) << 2;       // 0,4,8,12
                int gr = row0 + ar;
                float4 v = make_float4(0.f, 0.f, 0.f, 0.f);
                if (gr < M) v = *(const float4*)(A + (size_t)gr * K + k0 + ac);
                As[ar][ac + 0] = v.x;
                As[ar][ac + 1] = v.y;
                As[ar][ac + 2] = v.z;
                As[ar][ac + 3] = v.w;
            }
            // --- load B tile: 16 x N (coalesced float4) ---
            {
                constexpr int F4 = KT * N / 4;  // 512 (N=128) or 256 (N=64)
#pragma unroll
                for (int i = tid; i < F4; i += 256) {
                    int br = i / (N / 4);
                    int bc = (i % (N / 4)) << 2;
                    *(float4*)&Bs[br][bc] =
                        *(const float4*)(W + (size_t)(k0 + br) * N + bc);
                }
            }
            __syncthreads();

#pragma unroll
            for (int kk = 0; kk < KT; kk++) {
                float a[4], b[CT];
#pragma unroll
                for (int r = 0; r < 4; r++) a[r] = As[ty * 4 + r][kk];
#pragma unroll
                for (int c = 0; c < CT; c++) b[c] = Bs[kk][tx * CT + c];
#pragma unroll
                for (int r = 0; r < 4; r++)
#pragma unroll
                    for (int c = 0; c < CT; c++)
                        acc[r][c] += a[r] * b[c];
            }
            __syncthreads();
        }
    }

    // --- epilogue: bias + elementwise adds + relu, float4 stores ---
#pragma unroll
    for (int r = 0; r < 4; r++) {
        int gr = row0 + ty * 4 + r;
        if (gr >= M) break;
#pragma unroll
        for (int j = 0; j < CT / 4; j++) {
            int gc = tx * CT + j * 4;
            float4 v = make_float4(acc[r][j * 4 + 0], acc[r][j * 4 + 1],
                                   acc[r][j * 4 + 2], acc[r][j * 4 + 3]);
            if (bias) {
                float4 bv = *(const float4*)(bias + gc);
                v.x += bv.x; v.y += bv.y; v.z += bv.z; v.w += bv.w;
            }
            if (add0) {
                float4 a0 = *(const float4*)(add0 + (size_t)gr * N + gc);
                v.x += a0.x; v.y += a0.y; v.z += a0.z; v.w += a0.w;
            }
            if (add1) {
                float4 a1 = *(const float4*)(add1 + (size_t)gr * N + gc);
                v.x += a1.x; v.y += a1.y; v.z += a1.z; v.w += a1.w;
            }
            if (RELU) {
                v.x = fmaxf(v.x, 0.f); v.y = fmaxf(v.y, 0.f);
                v.z = fmaxf(v.z, 0.f); v.w = fmaxf(v.w, 0.f);
            }
            *(float4*)(out + (size_t)gr * N + gc) = v;
        }
    }
}

// ---------------------------------------------------------------------------
// Launch
// ---------------------------------------------------------------------------
extern "C" void kernel_launch(void* const* d_in, const int* in_sizes, int n_in,
                              void* d_out, int out_size) {
    (void)n_in; (void)out_size;

    const float* x_robot = (const float*)d_in[0];
    const float* x_ball  = (const float*)d_in[1];
    const int* ei_rr = (const int*)d_in[2];
    const int* ei_rb = (const int*)d_in[3];
    const int* ei_br = (const int*)d_in[4];
    const float* Wl0_rr = (const float*)d_in[5];
    const float* Wr0_rr = (const float*)d_in[6];
    const float* b0_rr  = (const float*)d_in[7];
    const float* Wl0_rb = (const float*)d_in[8];
    const float* Wr0_rb = (const float*)d_in[9];
    const float* b0_rb  = (const float*)d_in[10];
    const float* Wl0_br = (const float*)d_in[11];
    const float* Wr0_br = (const float*)d_in[12];
    const float* b0_br  = (const float*)d_in[13];
    const float* Wl1_rr = (const float*)d_in[14];
    const float* Wr1_rr = (const float*)d_in[15];
    const float* b1_rr  = (const float*)d_in[16];
    // d_in[17..19] = Wl1_rb / Wr1_rb / b1_rb : unused (only robot output returned)
    const float* Wl1_br = (const float*)d_in[20];
    const float* Wr1_br = (const float*)d_in[21];
    const float* b1_br  = (const float*)d_in[22];

    float* out = (float*)d_out;

    const int E = in_sizes[2] / 2;

    float* S = nullptr;
    int*   C = nullptr;
    {
        void* p = nullptr;
        cudaGetSymbolAddress(&p, g_scratch);
        S = (float*)p;
        cudaGetSymbolAddress(&p, g_cnt);
        C = (int*)p;
    }

    float* agg_rr0 = S + O_AGG_RR0;
    float* agg_br0 = S + O_AGG_BR0;
    float* agg_rb0 = S + O_AGG_RB0;
    float* r_buf   = S + O_R;
    float* bl_buf  = S + O_BL;
    float* t_rr    = S + O_TRR;
    float* t_br    = S + O_TBR;
    float* agg_rr1 = S + O_AGG_RR1;
    float* agg_br1 = S + O_AGG_BR1;
    float* Wsum0   = S + O_WSUM0;
    float* bsum0   = S + O_BSUM0;
    float* Wsum1   = S + O_WSUM1;
    float* bsum1   = S + O_BSUM1;
    int* cnt_rr = C;
    int* cnt_br = C + N_ROBOT;
    int* cnt_rb = C + 2 * N_ROBOT;

    // ---- zero accumulators + counters ----
    cudaMemsetAsync(agg_rr0, 0, 3ull * 12800000ull * sizeof(float), 0); // rr0,br0,rb0
    cudaMemsetAsync(agg_rr1, 0, 2ull * 6400000ull * sizeof(float), 0);  // rr1,br1
    cudaMemsetAsync(C, 0, 3ull * N_ROBOT * sizeof(int), 0);

    const int cb = (E + 255) / 256;
    count_kernel<<<cb, 256>>>(ei_rr + E, cnt_rr, E);
    count_kernel<<<cb, 256>>>(ei_br + E, cnt_br, E);
    count_kernel<<<cb, 256>>>(ei_rb + E, cnt_rb, E);

    // ---- fold shared-destination weights ----
    add2_kernel<<<64, 256>>>(Wr0_rr, Wr0_br, Wsum0, 128 * 128);
    add2_kernel<<<1, 128>>>(b0_rr, b0_br, bsum0, 128);
    add2_kernel<<<32, 256>>>(Wr1_rr, Wr1_br, Wsum1, 128 * 64);
    add2_kernel<<<1, 64>>>(b1_rr, b1_br, bsum1, 64);

    // ---- layer 0 aggregations (width 128) ----
    {
        long long total = (long long)E * 32;
        int g = (int)((total + 255) / 256);
        scatter_mean_kernel<<<g, 256>>>(ei_rr, ei_rr + E, cnt_rr, x_robot, agg_rr0, E, 32);
        scatter_mean_kernel<<<g, 256>>>(ei_br, ei_br + E, cnt_br, x_ball,  agg_br0, E, 32);
        scatter_mean_kernel<<<g, 256>>>(ei_rb, ei_rb + E, cnt_rb, x_robot, agg_rb0, E, 32);
    }

    const int gemm_blocks = (N_ROBOT + 63) / 64;  // 1563

    // ---- layer 0 GEMMs ----
    gemm_fused<128, true><<<gemm_blocks, 256>>>(
        N_ROBOT, agg_rr0, Wl0_rr, agg_br0, Wl0_br, x_robot, Wsum0,
        bsum0, nullptr, nullptr, r_buf);
    gemm_fused<128, true><<<gemm_blocks, 256>>>(
        N_BALL, agg_rb0, Wl0_rb, x_ball, Wr0_rb, nullptr, nullptr,
        b0_rb, nullptr, nullptr, bl_buf);

    // ---- layer 1: transform first (width-64 aggregation) ----
    gemm_fused<64, false><<<gemm_blocks, 256>>>(
        N_ROBOT, r_buf, Wl1_rr, nullptr, nullptr, nullptr, nullptr,
        nullptr, nullptr, nullptr, t_rr);
    gemm_fused<64, false><<<gemm_blocks, 256>>>(
        N_BALL, bl_buf, Wl1_br, nullptr, nullptr, nullptr, nullptr,
        nullptr, nullptr, nullptr, t_br);

    {
        long long total = (long long)E * 16;
        int g = (int)((total + 255) / 256);
        scatter_mean_kernel<<<g, 256>>>(ei_rr, ei_rr + E, cnt_rr, t_rr, agg_rr1, E, 16);
        scatter_mean_kernel<<<g, 256>>>(ei_br, ei_br + E, cnt_br, t_br, agg_br1, E, 16);
    }

    // ---- final: out = r @ (Wr1_rr+Wr1_br) + bsum1 + agg_rr1 + agg_br1 ----
    gemm_fused<64, false><<<gemm_blocks, 256>>>(
        N_ROBOT, r_buf, Wsum1, nullptr, nullptr, nullptr, nullptr,
        bsum1, agg_rr1, agg_br1, out);
}

// round 5
// speedup vs baseline: 1.5321x; 1.5321x over previous
#include <cuda_runtime.h>
#include <cuda_bf16.h>
#include <stdint.h>

// ---------------------------------------------------------------------------
// Problem constants
// ---------------------------------------------------------------------------
#define N_ROBOT 100000
#define N_BALL  100000
#define D_IN    128
#define H_DIM   128
#define OUT_DIM 64

// ---------------------------------------------------------------------------
// Scratch (device globals; allocation is forbidden)
// ---------------------------------------------------------------------------
#define O_AGG_RR0  0ull
#define O_AGG_BR0  (O_AGG_RR0 + 12800000ull)
#define O_AGG_RB0  (O_AGG_BR0 + 12800000ull)
#define O_R        (O_AGG_RB0 + 12800000ull)
#define O_BL       (O_R       + 12800000ull)
#define O_TRR      (O_BL      + 12800000ull)
#define O_TBR      (O_TRR     + 6400000ull)
#define O_AGG_RR1  (O_TBR     + 6400000ull)
#define O_AGG_BR1  (O_AGG_RR1 + 6400000ull)
#define O_WSUM0    (O_AGG_BR1 + 6400000ull)
#define O_BSUM0    (O_WSUM0   + 16384ull)
#define O_WSUM1    (O_BSUM0   + 128ull)
#define O_BSUM1    (O_WSUM1   + 8192ull)
#define SCRATCH_FLOATS (O_BSUM1 + 64ull)

__device__ float g_scratch[SCRATCH_FLOATS];
__device__ int   g_cnt[3 * N_ROBOT];

// ---------------------------------------------------------------------------
// Helpers (baseline PTX only — the harness targets compute_103 WITHOUT the
// 'a' suffix, so no tcgen05 / arch-accelerated features anywhere).
// ---------------------------------------------------------------------------
__device__ __forceinline__ uint32_t smem_u32(const void* p) {
    uint32_t a;
    asm("{ .reg .u64 t; cvta.to.shared.u64 t, %1; cvt.u32.u64 %0, t; }"
        : "=r"(a) : "l"(p));
    return a;
}

#define LDSM_X4(r0, r1, r2, r3, addr) \
    asm volatile("ldmatrix.sync.aligned.m8n8.x4.shared.b16 {%0,%1,%2,%3}, [%4];" \
                 : "=r"(r0), "=r"(r1), "=r"(r2), "=r"(r3) : "r"(addr))

__device__ __forceinline__ void mma_bf16(float* c, const uint32_t* a,
                                         uint32_t b0, uint32_t b1) {
    asm volatile(
        "mma.sync.aligned.m16n8k16.row.col.f32.bf16.bf16.f32 "
        "{%0,%1,%2,%3}, {%4,%5,%6,%7}, {%8,%9}, {%0,%1,%2,%3};"
        : "+f"(c[0]), "+f"(c[1]), "+f"(c[2]), "+f"(c[3])
        : "r"(a[0]), "r"(a[1]), "r"(a[2]), "r"(a[3]), "r"(b0), "r"(b1));
}

// fp32 -> bf16 hi/lo split, two lanes packed per 32b reg (low half = even elem)
__device__ __forceinline__ void split_pack(float x0, float x1,
                                           uint32_t& hp, uint32_t& lp) {
    __nv_bfloat16 h0 = __float2bfloat16(x0);
    __nv_bfloat16 h1 = __float2bfloat16(x1);
    __nv_bfloat16 l0 = __float2bfloat16(x0 - __bfloat162float(h0));
    __nv_bfloat16 l1 = __float2bfloat16(x1 - __bfloat162float(h1));
    hp = ((uint32_t)__bfloat16_as_ushort(h1) << 16) | __bfloat16_as_ushort(h0);
    lp = ((uint32_t)__bfloat16_as_ushort(l1) << 16) | __bfloat16_as_ushort(l0);
}

// ---------------------------------------------------------------------------
// Small kernels
// ---------------------------------------------------------------------------
__global__ void count_kernel(const int* __restrict__ dst,
                             int* __restrict__ cnt, int E) {
    int i = blockIdx.x * blockDim.x + threadIdx.x;
    if (i < E) atomicAdd(&cnt[dst[i]], 1);
}

__global__ void add2_kernel(const float* __restrict__ a,
                            const float* __restrict__ b,
                            float* __restrict__ o, int n) {
    int i = blockIdx.x * blockDim.x + threadIdx.x;
    if (i < n) o[i] = a[i] + b[i];
}

__global__ void scatter_mean_kernel(const int* __restrict__ src,
                                    const int* __restrict__ dst,
                                    const int* __restrict__ cnt,
                                    const float* __restrict__ x,
                                    float* __restrict__ agg,
                                    int E, int chunks) {
    long long idx = (long long)blockIdx.x * blockDim.x + threadIdx.x;
    long long total = (long long)E * chunks;
    if (idx >= total) return;
    int e = (int)(idx / chunks);
    int c = (int)(idx - (long long)e * chunks);
    int s = src[e];
    int d = dst[e];
    float inv = 1.0f / (float)cnt[d];
    int W = chunks * 4;
    float4 v = *(const float4*)(x + (size_t)s * W + c * 4);
    v.x *= inv; v.y *= inv; v.z *= inv; v.w *= inv;
    float* p = agg + (size_t)d * W + c * 4;
    asm volatile("red.global.add.v4.f32 [%0], {%1, %2, %3, %4};"
                 :: "l"(p), "f"(v.x), "f"(v.y), "f"(v.z), "f"(v.w)
                 : "memory");
}

// ---------------------------------------------------------------------------
// HMMA (mma.sync bf16-split) fused GEMM:
//   out = relu?( sum_t A_t @ W_t + bias + add0 + add1 )
// A_t: [M,128] fp32 row-major; W_t: [128,N] fp32 row-major; N in {128,64}.
// fp32 emulated as 3 bf16 products (ah*bh + al*bh + ah*bl), fp32 accum in regs.
// Block: 256 thr (8 warps), tile 64 x N, warp grid 4x2 (each warp 16 x N/2).
// SMEM: A hi/lo [64][136] bf16, B hi/lo [N][136] bf16 (B transposed to n-major).
// Padded stride 272B => ldmatrix rows land on disjoint bank quads.
// ---------------------------------------------------------------------------
template <int N, int TERMS, bool RELU>
__global__ void __launch_bounds__(256)
gemm_hmma(int M,
          const float* __restrict__ A0, const float* __restrict__ W0,
          const float* __restrict__ A1, const float* __restrict__ W1,
          const float* __restrict__ A2, const float* __restrict__ W2,
          const float* __restrict__ bias,
          const float* __restrict__ add0,
          const float* __restrict__ add1,
          float* __restrict__ out) {
    extern __shared__ char smem[];
    constexpr int STRIDE = 136;                 // bf16 elems per row (272B)
    constexpr uint32_t ABYTES = 64 * STRIDE * 2;       // 17408
    constexpr uint32_t BBYTES = (uint32_t)N * STRIDE * 2;
    const uint32_t AH = smem_u32(smem);
    const uint32_t AL = AH + ABYTES;
    const uint32_t BH = AL + ABYTES;
    const uint32_t BL = BH + BBYTES;

    const int tid  = threadIdx.x;
    const int wid  = tid >> 5;
    const int lane = tid & 31;
    const int wr   = wid & 3;                   // warp row group (16 rows)
    const int wcg  = wid >> 2;                  // warp col group (N/2 cols)
    const int row0 = blockIdx.x * 64;

    constexpr int NOCT = N / 16;                // 8-col octets per warp
    float acc[NOCT][4];
#pragma unroll
    for (int o = 0; o < NOCT; o++)
#pragma unroll
        for (int j = 0; j < 4; j++) acc[o][j] = 0.0f;

    const float* Aarr[3] = {A0, A1, A2};
    const float* Warr[3] = {W0, W1, W2};

    // ldmatrix source addresses (fixed per thread; k advances by offset)
    // A x4: tiles = (rows0-7,k0),(rows8-15,k0),(rows0-7,k8),(rows8-15,k8)
    const int a_row = wr * 16 + ((lane >> 3) & 1) * 8 + (lane & 7);
    const int a_kof = (lane >> 4) * 8;
    // B x4: tiles = (oct n0,k0),(oct n0,k8),(oct n1,k0),(oct n1,k8)
    const int b_nof = ((lane >> 4) & 1) * 8 + (lane & 7);   // within 2-octet pair
    const int b_kof = ((lane >> 3) & 1) * 8;

#pragma unroll
    for (int t = 0; t < TERMS; t++) {
        const float* A = Aarr[t];
        const float* W = Warr[t];

        // ---- stage A: 64x128 fp32 -> hi/lo bf16 (2048 float4, 8/thread) ----
#pragma unroll
        for (int i = 0; i < 8; i++) {
            int idx = tid + i * 256;
            int r  = idx >> 5;                  // 0..63
            int c4 = idx & 31;                  // float4 index in row
            float4 v = make_float4(0.f, 0.f, 0.f, 0.f);
            if (row0 + r < M)
                v = *(const float4*)(A + (size_t)(row0 + r) * 128 + c4 * 4);
            uint32_t h01, l01, h23, l23;
            split_pack(v.x, v.y, h01, l01);
            split_pack(v.z, v.w, h23, l23);
            uint32_t off = (uint32_t)r * (STRIDE * 2) + (uint32_t)c4 * 8;
            asm volatile("st.shared.v2.b32 [%0], {%1,%2};"
                         :: "r"(AH + off), "r"(h01), "r"(h23) : "memory");
            asm volatile("st.shared.v2.b32 [%0], {%1,%2};"
                         :: "r"(AL + off), "r"(l01), "r"(l23) : "memory");
        }

        // ---- stage B: W[k][n] -> Bs[n][k] hi/lo (transpose) ----
        for (int idx = tid; idx < 128 * N; idx += 256) {
            int k = idx / N;
            int n = idx - k * N;
            float w = W[idx];
            __nv_bfloat16 h = __float2bfloat16(w);
            __nv_bfloat16 l = __float2bfloat16(w - __bfloat162float(h));
            uint32_t off = (uint32_t)n * (STRIDE * 2) + (uint32_t)k * 2;
            unsigned short hs = __bfloat16_as_ushort(h);
            unsigned short ls = __bfloat16_as_ushort(l);
            asm volatile("st.shared.b16 [%0], %1;" :: "r"(BH + off), "h"(hs) : "memory");
            asm volatile("st.shared.b16 [%0], %1;" :: "r"(BL + off), "h"(ls) : "memory");
        }
        __syncthreads();

        // ---- compute: 8 k-chunks x (NOCT octets) x 3 split products ----
#pragma unroll
        for (int k0 = 0; k0 < 128; k0 += 16) {
            uint32_t ah[4], al[4];
            {
                uint32_t aoff = (uint32_t)a_row * (STRIDE * 2)
                              + (uint32_t)(k0 + a_kof) * 2;
                LDSM_X4(ah[0], ah[1], ah[2], ah[3], AH + aoff);
                LDSM_X4(al[0], al[1], al[2], al[3], AL + aoff);
            }
#pragma unroll
            for (int op = 0; op < NOCT; op += 2) {
                int nbase = wcg * (N / 2) + op * 8;
                uint32_t boff = (uint32_t)(nbase + b_nof) * (STRIDE * 2)
                              + (uint32_t)(k0 + b_kof) * 2;
                uint32_t bh0, bh1, bh2, bh3, bl0, bl1, bl2, bl3;
                LDSM_X4(bh0, bh1, bh2, bh3, BH + boff);
                LDSM_X4(bl0, bl1, bl2, bl3, BL + boff);
                mma_bf16(acc[op],     ah, bh0, bh1);
                mma_bf16(acc[op],     al, bh0, bh1);
                mma_bf16(acc[op],     ah, bl0, bl1);
                mma_bf16(acc[op + 1], ah, bh2, bh3);
                mma_bf16(acc[op + 1], al, bh2, bh3);
                mma_bf16(acc[op + 1], ah, bl2, bl3);
            }
        }
        __syncthreads();   // before next term overwrites SMEM
    }

    // ---- epilogue: c-frag rows = wr*16 + lane/4 (+8), cols = 2*(lane%4) ----
    const int rA = row0 + wr * 16 + (lane >> 2);
    const int rB = rA + 8;
#pragma unroll
    for (int o = 0; o < NOCT; o++) {
        int col = wcg * (N / 2) + o * 8 + (lane & 3) * 2;
        float2 bv = make_float2(0.f, 0.f);
        if (bias) bv = *(const float2*)(bias + col);
        if (rA < M) {
            float2 v = make_float2(acc[o][0] + bv.x, acc[o][1] + bv.y);
            if (add0) {
                float2 a = *(const float2*)(add0 + (size_t)rA * N + col);
                v.x += a.x; v.y += a.y;
            }
            if (add1) {
                float2 a = *(const float2*)(add1 + (size_t)rA * N + col);
                v.x += a.x; v.y += a.y;
            }
            if (RELU) { v.x = fmaxf(v.x, 0.f); v.y = fmaxf(v.y, 0.f); }
            *(float2*)(out + (size_t)rA * N + col) = v;
        }
        if (rB < M) {
            float2 v = make_float2(acc[o][2] + bv.x, acc[o][3] + bv.y);
            if (add0) {
                float2 a = *(const float2*)(add0 + (size_t)rB * N + col);
                v.x += a.x; v.y += a.y;
            }
            if (add1) {
                float2 a = *(const float2*)(add1 + (size_t)rB * N + col);
                v.x += a.x; v.y += a.y;
            }
            if (RELU) { v.x = fmaxf(v.x, 0.f); v.y = fmaxf(v.y, 0.f); }
            *(float2*)(out + (size_t)rB * N + col) = v;
        }
    }
}

// ---------------------------------------------------------------------------
// Launch
// ---------------------------------------------------------------------------
extern "C" void kernel_launch(void* const* d_in, const int* in_sizes, int n_in,
                              void* d_out, int out_size) {
    (void)n_in; (void)out_size;

    const float* x_robot = (const float*)d_in[0];
    const float* x_ball  = (const float*)d_in[1];
    const int* ei_rr = (const int*)d_in[2];
    const int* ei_rb = (const int*)d_in[3];
    const int* ei_br = (const int*)d_in[4];
    const float* Wl0_rr = (const float*)d_in[5];
    const float* Wr0_rr = (const float*)d_in[6];
    const float* b0_rr  = (const float*)d_in[7];
    const float* Wl0_rb = (const float*)d_in[8];
    const float* Wr0_rb = (const float*)d_in[9];
    const float* b0_rb  = (const float*)d_in[10];
    const float* Wl0_br = (const float*)d_in[11];
    const float* Wr0_br = (const float*)d_in[12];
    const float* b0_br  = (const float*)d_in[13];
    const float* Wl1_rr = (const float*)d_in[14];
    const float* Wr1_rr = (const float*)d_in[15];
    const float* b1_rr  = (const float*)d_in[16];
    const float* Wl1_br = (const float*)d_in[20];
    const float* Wr1_br = (const float*)d_in[21];
    const float* b1_br  = (const float*)d_in[22];

    float* out = (float*)d_out;
    const int E = in_sizes[2] / 2;

    float* S = nullptr;
    int*   C = nullptr;
    {
        void* p = nullptr;
        cudaGetSymbolAddress(&p, g_scratch);
        S = (float*)p;
        cudaGetSymbolAddress(&p, g_cnt);
        C = (int*)p;
    }

    float* agg_rr0 = S + O_AGG_RR0;
    float* agg_br0 = S + O_AGG_BR0;
    float* agg_rb0 = S + O_AGG_RB0;
    float* r_buf   = S + O_R;
    float* bl_buf  = S + O_BL;
    float* t_rr    = S + O_TRR;
    float* t_br    = S + O_TBR;
    float* agg_rr1 = S + O_AGG_RR1;
    float* agg_br1 = S + O_AGG_BR1;
    float* Wsum0   = S + O_WSUM0;
    float* bsum0   = S + O_BSUM0;
    float* Wsum1   = S + O_WSUM1;
    float* bsum1   = S + O_BSUM1;
    int* cnt_rr = C;
    int* cnt_br = C + N_ROBOT;
    int* cnt_rb = C + 2 * N_ROBOT;

    // dynamic smem sizes: A hi/lo (2x17408) + B hi/lo (2x N*272)
    constexpr int SMEM128 = 2 * 17408 + 2 * 128 * 272;  // 104448
    constexpr int SMEM64  = 2 * 17408 + 2 * 64 * 272;   //  69632
    cudaFuncSetAttribute(gemm_hmma<128, 3, true>,
                         cudaFuncAttributeMaxDynamicSharedMemorySize, SMEM128);
    cudaFuncSetAttribute(gemm_hmma<128, 2, true>,
                         cudaFuncAttributeMaxDynamicSharedMemorySize, SMEM128);
    cudaFuncSetAttribute(gemm_hmma<64, 1, false>,
                         cudaFuncAttributeMaxDynamicSharedMemorySize, SMEM64);

    // ---- zero accumulators + counters ----
    cudaMemsetAsync(agg_rr0, 0, 3ull * 12800000ull * sizeof(float), 0);
    cudaMemsetAsync(agg_rr1, 0, 2ull * 6400000ull * sizeof(float), 0);
    cudaMemsetAsync(C, 0, 3ull * N_ROBOT * sizeof(int), 0);

    const int cb = (E + 255) / 256;
    count_kernel<<<cb, 256>>>(ei_rr + E, cnt_rr, E);
    count_kernel<<<cb, 256>>>(ei_br + E, cnt_br, E);
    count_kernel<<<cb, 256>>>(ei_rb + E, cnt_rb, E);

    // ---- fold shared-destination weights ----
    add2_kernel<<<64, 256>>>(Wr0_rr, Wr0_br, Wsum0, 128 * 128);
    add2_kernel<<<1, 128>>>(b0_rr, b0_br, bsum0, 128);
    add2_kernel<<<32, 256>>>(Wr1_rr, Wr1_br, Wsum1, 128 * 64);
    add2_kernel<<<1, 64>>>(b1_rr, b1_br, bsum1, 64);

    // ---- layer 0 aggregations (width 128) ----
    {
        long long total = (long long)E * 32;
        int g = (int)((total + 255) / 256);
        scatter_mean_kernel<<<g, 256>>>(ei_rr, ei_rr + E, cnt_rr, x_robot, agg_rr0, E, 32);
        scatter_mean_kernel<<<g, 256>>>(ei_br, ei_br + E, cnt_br, x_ball,  agg_br0, E, 32);
        scatter_mean_kernel<<<g, 256>>>(ei_rb, ei_rb + E, cnt_rb, x_robot, agg_rb0, E, 32);
    }

    const int gb = (N_ROBOT + 63) / 64;  // 1563

    // ---- layer 0 GEMMs (HMMA tensor path) ----
    gemm_hmma<128, 3, true><<<gb, 256, SMEM128>>>(
        N_ROBOT, agg_rr0, Wl0_rr, agg_br0, Wl0_br, x_robot, Wsum0,
        bsum0, nullptr, nullptr, r_buf);
    gemm_hmma<128, 2, true><<<gb, 256, SMEM128>>>(
        N_BALL, agg_rb0, Wl0_rb, x_ball, Wr0_rb, nullptr, nullptr,
        b0_rb, nullptr, nullptr, bl_buf);

    // ---- layer 1: transform first (width-64 aggregation) ----
    gemm_hmma<64, 1, false><<<gb, 256, SMEM64>>>(
        N_ROBOT, r_buf, Wl1_rr, nullptr, nullptr, nullptr, nullptr,
        nullptr, nullptr, nullptr, t_rr);
    gemm_hmma<64, 1, false><<<gb, 256, SMEM64>>>(
        N_BALL, bl_buf, Wl1_br, nullptr, nullptr, nullptr, nullptr,
        nullptr, nullptr, nullptr, t_br);

    {
        long long total = (long long)E * 16;
        int g = (int)((total + 255) / 256);
        scatter_mean_kernel<<<g, 256>>>(ei_rr, ei_rr + E, cnt_rr, t_rr, agg_rr1, E, 16);
        scatter_mean_kernel<<<g, 256>>>(ei_br, ei_br + E, cnt_br, t_br, agg_br1, E, 16);
    }

    // ---- final: out = r @ (Wr1_rr+Wr1_br) + bsum1 + agg_rr1 + agg_br1 ----
    gemm_hmma<64, 1, false><<<gb, 256, SMEM64>>>(
        N_ROBOT, r_buf, Wsum1, nullptr, nullptr, nullptr, nullptr,
        bsum1, agg_rr1, agg_br1, out);
}

// round 6
// speedup vs baseline: 2.0456x; 1.3352x over previous
#include <cuda_runtime.h>
#include <cuda_bf16.h>
#include <stdint.h>

// ---------------------------------------------------------------------------
// Problem constants
// ---------------------------------------------------------------------------
#define N_ROBOT 100000
#define N_BALL  100000
#define D_IN    128
#define H_DIM   128
#define OUT_DIM 64
#define E_MAX   600000

// ---------------------------------------------------------------------------
// Scratch (device globals; allocation is forbidden)
// ---------------------------------------------------------------------------
#define O_AGG_RR0  0ull
#define O_AGG_BR0  (O_AGG_RR0 + 12800000ull)
#define O_AGG_RB0  (O_AGG_BR0 + 12800000ull)
#define O_R        (O_AGG_RB0 + 12800000ull)
#define O_BL       (O_R       + 12800000ull)
#define O_TRR      (O_BL      + 12800000ull)
#define O_TBR      (O_TRR     + 6400000ull)
#define O_AGG_RR1  (O_TBR     + 6400000ull)
#define O_AGG_BR1  (O_AGG_RR1 + 6400000ull)
#define O_WSUM0    (O_AGG_BR1 + 6400000ull)
#define O_BSUM0    (O_WSUM0   + 16384ull)
#define O_WSUM1    (O_BSUM0   + 128ull)
#define O_BSUM1    (O_WSUM1   + 8192ull)
#define SCRATCH_FLOATS (O_BSUM1 + 64ull)

__device__ float g_scratch[SCRATCH_FLOATS];
__device__ int   g_cnt[3 * N_ROBOT];      // cnt_rr | cnt_br | cnt_rb (concatenated)
__device__ int   g_off[3 * N_ROBOT];      // exclusive scan of g_cnt (global over concat)
__device__ int   g_cursor[3 * N_ROBOT];   // fill cursors
__device__ int   g_csr[3 * E_MAX + 64];   // neighbor src ids, CSR order (global index space)
__device__ int   g_bsum[1024];            // scan partials

#define NSCAN   (3 * N_ROBOT)             // 300000
#define SCAN_BS 512
#define SCAN_NB ((NSCAN + SCAN_BS - 1) / SCAN_BS)   // 586

// ---------------------------------------------------------------------------
// Helpers (baseline PTX only — harness compiles for compute_103 w/o 'a';
// no tcgen05 anywhere, mma.sync/ldmatrix only).
// ---------------------------------------------------------------------------
__device__ __forceinline__ uint32_t smem_u32(const void* p) {
    uint32_t a;
    asm("{ .reg .u64 t; cvta.to.shared.u64 t, %1; cvt.u32.u64 %0, t; }"
        : "=r"(a) : "l"(p));
    return a;
}

#define LDSM_X4(r0, r1, r2, r3, addr) \
    asm volatile("ldmatrix.sync.aligned.m8n8.x4.shared.b16 {%0,%1,%2,%3}, [%4];" \
                 : "=r"(r0), "=r"(r1), "=r"(r2), "=r"(r3) : "r"(addr))

__device__ __forceinline__ void mma_bf16(float* c, const uint32_t* a,
                                         uint32_t b0, uint32_t b1) {
    asm volatile(
        "mma.sync.aligned.m16n8k16.row.col.f32.bf16.bf16.f32 "
        "{%0,%1,%2,%3}, {%4,%5,%6,%7}, {%8,%9}, {%0,%1,%2,%3};"
        : "+f"(c[0]), "+f"(c[1]), "+f"(c[2]), "+f"(c[3])
        : "r"(a[0]), "r"(a[1]), "r"(a[2]), "r"(a[3]), "r"(b0), "r"(b1));
}

__device__ __forceinline__ void split_pack(float x0, float x1,
                                           uint32_t& hp, uint32_t& lp) {
    __nv_bfloat16 h0 = __float2bfloat16(x0);
    __nv_bfloat16 h1 = __float2bfloat16(x1);
    __nv_bfloat16 l0 = __float2bfloat16(x0 - __bfloat162float(h0));
    __nv_bfloat16 l1 = __float2bfloat16(x1 - __bfloat162float(h1));
    hp = ((uint32_t)__bfloat16_as_ushort(h1) << 16) | __bfloat16_as_ushort(h0);
    lp = ((uint32_t)__bfloat16_as_ushort(l1) << 16) | __bfloat16_as_ushort(l0);
}

// ---------------------------------------------------------------------------
// Small kernels: counts, folding, CSR build
// ---------------------------------------------------------------------------
__global__ void count_kernel(const int* __restrict__ dst,
                             int* __restrict__ cnt, int E) {
    int i = blockIdx.x * blockDim.x + threadIdx.x;
    if (i < E) atomicAdd(&cnt[dst[i]], 1);
}

__global__ void add2_kernel(const float* __restrict__ a,
                            const float* __restrict__ b,
                            float* __restrict__ o, int n) {
    int i = blockIdx.x * blockDim.x + threadIdx.x;
    if (i < n) o[i] = a[i] + b[i];
}

// --- 3-kernel exclusive scan over g_cnt[0..NSCAN) -> g_off ---
__global__ void scan1_kernel(const int* __restrict__ cnt,
                             int* __restrict__ out, int* __restrict__ bsum) {
    __shared__ int sh[SCAN_BS];
    int gid = blockIdx.x * SCAN_BS + threadIdx.x;
    int v = (gid < NSCAN) ? cnt[gid] : 0;
    sh[threadIdx.x] = v;
    __syncthreads();
#pragma unroll
    for (int d = 1; d < SCAN_BS; d <<= 1) {
        int t = (threadIdx.x >= d) ? sh[threadIdx.x - d] : 0;
        __syncthreads();
        sh[threadIdx.x] += t;
        __syncthreads();
    }
    if (gid < NSCAN) out[gid] = sh[threadIdx.x] - v;   // exclusive
    if (threadIdx.x == SCAN_BS - 1) bsum[blockIdx.x] = sh[threadIdx.x];
}

__global__ void scan2_kernel(int* __restrict__ bsum) {   // 1 block, 1024 threads
    __shared__ int sh[1024];
    int i = threadIdx.x;
    int v = (i < SCAN_NB) ? bsum[i] : 0;
    sh[i] = v;
    __syncthreads();
#pragma unroll
    for (int d = 1; d < 1024; d <<= 1) {
        int t = (i >= d) ? sh[i - d] : 0;
        __syncthreads();
        sh[i] += t;
        __syncthreads();
    }
    if (i < SCAN_NB) bsum[i] = sh[i] - v;                // exclusive block offsets
}

__global__ void scan3_kernel(int* __restrict__ out, const int* __restrict__ bsum,
                             int* __restrict__ cursor) {
    int gid = blockIdx.x * SCAN_BS + threadIdx.x;
    if (gid < NSCAN) {
        int o = out[gid] + bsum[blockIdx.x];
        out[gid] = o;
        cursor[gid] = o;
    }
}

__global__ void fill_csr_kernel(const int* __restrict__ src,
                                const int* __restrict__ dst,
                                int* __restrict__ cursor,
                                int* __restrict__ csr, int E, int base) {
    int i = blockIdx.x * blockDim.x + threadIdx.x;
    if (i < E) {
        int pos = atomicAdd(&cursor[base + dst[i]], 1);
        csr[pos] = src[i];
    }
}

// ---------------------------------------------------------------------------
// CSR gather-mean: one warp per destination row.
//   out[d] = (1/deg) * sum_{s in N(d)} x[s]     (zeros when deg == 0)
// W=128: lane holds float4 (32*4). W=64: lane holds float2.
// ---------------------------------------------------------------------------
template <int W>
__global__ void __launch_bounds__(256)
gather_mean_kernel(const int* __restrict__ off, const int* __restrict__ cnt,
                   const int* __restrict__ csr, const float* __restrict__ x,
                   float* __restrict__ out, int n) {
    int warp = (blockIdx.x * blockDim.x + threadIdx.x) >> 5;
    int lane = threadIdx.x & 31;
    if (warp >= n) return;
    int start = off[warp];
    int deg   = cnt[warp];

    if (W == 128) {
        float4 acc = make_float4(0.f, 0.f, 0.f, 0.f);
        int i = 0;
        for (; i + 2 <= deg; i += 2) {
            int s0 = csr[start + i];
            int s1 = csr[start + i + 1];
            float4 v0 = *(const float4*)(x + (size_t)s0 * 128 + lane * 4);
            float4 v1 = *(const float4*)(x + (size_t)s1 * 128 + lane * 4);
            acc.x += v0.x + v1.x; acc.y += v0.y + v1.y;
            acc.z += v0.z + v1.z; acc.w += v0.w + v1.w;
        }
        if (i < deg) {
            int s = csr[start + i];
            float4 v = *(const float4*)(x + (size_t)s * 128 + lane * 4);
            acc.x += v.x; acc.y += v.y; acc.z += v.z; acc.w += v.w;
        }
        float inv = (deg > 0) ? (1.0f / (float)deg) : 0.0f;
        acc.x *= inv; acc.y *= inv; acc.z *= inv; acc.w *= inv;
        *(float4*)(out + (size_t)warp * 128 + lane * 4) = acc;
    } else {
        float2 acc = make_float2(0.f, 0.f);
        int i = 0;
        for (; i + 2 <= deg; i += 2) {
            int s0 = csr[start + i];
            int s1 = csr[start + i + 1];
            float2 v0 = *(const float2*)(x + (size_t)s0 * 64 + lane * 2);
            float2 v1 = *(const float2*)(x + (size_t)s1 * 64 + lane * 2);
            acc.x += v0.x + v1.x; acc.y += v0.y + v1.y;
        }
        if (i < deg) {
            int s = csr[start + i];
            float2 v = *(const float2*)(x + (size_t)s * 64 + lane * 2);
            acc.x += v.x; acc.y += v.y;
        }
        float inv = (deg > 0) ? (1.0f / (float)deg) : 0.0f;
        acc.x *= inv; acc.y *= inv;
        *(float2*)(out + (size_t)warp * 64 + lane * 2) = acc;
    }
}

// ---------------------------------------------------------------------------
// HMMA (mma.sync bf16-split) fused GEMM — unchanged from round 5 (verified).
//   out = relu?( sum_t A_t @ W_t + bias + add0 + add1 )
// ---------------------------------------------------------------------------
template <int N, int TERMS, bool RELU>
__global__ void __launch_bounds__(256)
gemm_hmma(int M,
          const float* __restrict__ A0, const float* __restrict__ W0,
          const float* __restrict__ A1, const float* __restrict__ W1,
          const float* __restrict__ A2, const float* __restrict__ W2,
          const float* __restrict__ bias,
          const float* __restrict__ add0,
          const float* __restrict__ add1,
          float* __restrict__ out) {
    extern __shared__ char smem[];
    constexpr int STRIDE = 136;
    constexpr uint32_t ABYTES = 64 * STRIDE * 2;
    constexpr uint32_t BBYTES = (uint32_t)N * STRIDE * 2;
    const uint32_t AH = smem_u32(smem);
    const uint32_t AL = AH + ABYTES;
    const uint32_t BH = AL + ABYTES;
    const uint32_t BL = BH + BBYTES;

    const int tid  = threadIdx.x;
    const int wid  = tid >> 5;
    const int lane = tid & 31;
    const int wr   = wid & 3;
    const int wcg  = wid >> 2;
    const int row0 = blockIdx.x * 64;

    constexpr int NOCT = N / 16;
    float acc[NOCT][4];
#pragma unroll
    for (int o = 0; o < NOCT; o++)
#pragma unroll
        for (int j = 0; j < 4; j++) acc[o][j] = 0.0f;

    const float* Aarr[3] = {A0, A1, A2};
    const float* Warr[3] = {W0, W1, W2};

    const int a_row = wr * 16 + ((lane >> 3) & 1) * 8 + (lane & 7);
    const int a_kof = (lane >> 4) * 8;
    const int b_nof = ((lane >> 4) & 1) * 8 + (lane & 7);
    const int b_kof = ((lane >> 3) & 1) * 8;

#pragma unroll
    for (int t = 0; t < TERMS; t++) {
        const float* A = Aarr[t];
        const float* W = Warr[t];

#pragma unroll
        for (int i = 0; i < 8; i++) {
            int idx = tid + i * 256;
            int r  = idx >> 5;
            int c4 = idx & 31;
            float4 v = make_float4(0.f, 0.f, 0.f, 0.f);
            if (row0 + r < M)
                v = *(const float4*)(A + (size_t)(row0 + r) * 128 + c4 * 4);
            uint32_t h01, l01, h23, l23;
            split_pack(v.x, v.y, h01, l01);
            split_pack(v.z, v.w, h23, l23);
            uint32_t off = (uint32_t)r * (STRIDE * 2) + (uint32_t)c4 * 8;
            asm volatile("st.shared.v2.b32 [%0], {%1,%2};"
                         :: "r"(AH + off), "r"(h01), "r"(h23) : "memory");
            asm volatile("st.shared.v2.b32 [%0], {%1,%2};"
                         :: "r"(AL + off), "r"(l01), "r"(l23) : "memory");
        }

        for (int idx = tid; idx < 128 * N; idx += 256) {
            int k = idx / N;
            int n = idx - k * N;
            float w = W[idx];
            __nv_bfloat16 h = __float2bfloat16(w);
            __nv_bfloat16 l = __float2bfloat16(w - __bfloat162float(h));
            uint32_t off = (uint32_t)n * (STRIDE * 2) + (uint32_t)k * 2;
            unsigned short hs = __bfloat16_as_ushort(h);
            unsigned short ls = __bfloat16_as_ushort(l);
            asm volatile("st.shared.b16 [%0], %1;" :: "r"(BH + off), "h"(hs) : "memory");
            asm volatile("st.shared.b16 [%0], %1;" :: "r"(BL + off), "h"(ls) : "memory");
        }
        __syncthreads();

#pragma unroll
        for (int k0 = 0; k0 < 128; k0 += 16) {
            uint32_t ah[4], al[4];
            {
                uint32_t aoff = (uint32_t)a_row * (STRIDE * 2)
                              + (uint32_t)(k0 + a_kof) * 2;
                LDSM_X4(ah[0], ah[1], ah[2], ah[3], AH + aoff);
                LDSM_X4(al[0], al[1], al[2], al[3], AL + aoff);
            }
#pragma unroll
            for (int op = 0; op < NOCT; op += 2) {
                int nbase = wcg * (N / 2) + op * 8;
                uint32_t boff = (uint32_t)(nbase + b_nof) * (STRIDE * 2)
                              + (uint32_t)(k0 + b_kof) * 2;
                uint32_t bh0, bh1, bh2, bh3, bl0, bl1, bl2, bl3;
                LDSM_X4(bh0, bh1, bh2, bh3, BH + boff);
                LDSM_X4(bl0, bl1, bl2, bl3, BL + boff);
                mma_bf16(acc[op],     ah, bh0, bh1);
                mma_bf16(acc[op],     al, bh0, bh1);
                mma_bf16(acc[op],     ah, bl0, bl1);
                mma_bf16(acc[op + 1], ah, bh2, bh3);
                mma_bf16(acc[op + 1], al, bh2, bh3);
                mma_bf16(acc[op + 1], ah, bl2, bl3);
            }
        }
        __syncthreads();
    }

    const int rA = row0 + wr * 16 + (lane >> 2);
    const int rB = rA + 8;
#pragma unroll
    for (int o = 0; o < NOCT; o++) {
        int col = wcg * (N / 2) + o * 8 + (lane & 3) * 2;
        float2 bv = make_float2(0.f, 0.f);
        if (bias) bv = *(const float2*)(bias + col);
        if (rA < M) {
            float2 v = make_float2(acc[o][0] + bv.x, acc[o][1] + bv.y);
            if (add0) {
                float2 a = *(const float2*)(add0 + (size_t)rA * N + col);
                v.x += a.x; v.y += a.y;
            }
            if (add1) {
                float2 a = *(const float2*)(add1 + (size_t)rA * N + col);
                v.x += a.x; v.y += a.y;
            }
            if (RELU) { v.x = fmaxf(v.x, 0.f); v.y = fmaxf(v.y, 0.f); }
            *(float2*)(out + (size_t)rA * N + col) = v;
        }
        if (rB < M) {
            float2 v = make_float2(acc[o][2] + bv.x, acc[o][3] + bv.y);
            if (add0) {
                float2 a = *(const float2*)(add0 + (size_t)rB * N + col);
                v.x += a.x; v.y += a.y;
            }
            if (add1) {
                float2 a = *(const float2*)(add1 + (size_t)rB * N + col);
                v.x += a.x; v.y += a.y;
            }
            if (RELU) { v.x = fmaxf(v.x, 0.f); v.y = fmaxf(v.y, 0.f); }
            *(float2*)(out + (size_t)rB * N + col) = v;
        }
    }
}

// ---------------------------------------------------------------------------
// Launch
// ---------------------------------------------------------------------------
extern "C" void kernel_launch(void* const* d_in, const int* in_sizes, int n_in,
                              void* d_out, int out_size) {
    (void)n_in; (void)out_size;

    const float* x_robot = (const float*)d_in[0];
    const float* x_ball  = (const float*)d_in[1];
    const int* ei_rr = (const int*)d_in[2];
    const int* ei_rb = (const int*)d_in[3];
    const int* ei_br = (const int*)d_in[4];
    const float* Wl0_rr = (const float*)d_in[5];
    const float* Wr0_rr = (const float*)d_in[6];
    const float* b0_rr  = (const float*)d_in[7];
    const float* Wl0_rb = (const float*)d_in[8];
    const float* Wr0_rb = (const float*)d_in[9];
    const float* b0_rb  = (const float*)d_in[10];
    const float* Wl0_br = (const float*)d_in[11];
    const float* Wr0_br = (const float*)d_in[12];
    const float* b0_br  = (const float*)d_in[13];
    const float* Wl1_rr = (const float*)d_in[14];
    const float* Wr1_rr = (const float*)d_in[15];
    const float* b1_rr  = (const float*)d_in[16];
    const float* Wl1_br = (const float*)d_in[20];
    const float* Wr1_br = (const float*)d_in[21];
    const float* b1_br  = (const float*)d_in[22];

    float* out = (float*)d_out;
    const int E = in_sizes[2] / 2;

    float* S = nullptr;
    int *C = nullptr, *OFF = nullptr, *CUR = nullptr, *CSR = nullptr, *BS = nullptr;
    {
        void* p = nullptr;
        cudaGetSymbolAddress(&p, g_scratch); S = (float*)p;
        cudaGetSymbolAddress(&p, g_cnt);     C = (int*)p;
        cudaGetSymbolAddress(&p, g_off);     OFF = (int*)p;
        cudaGetSymbolAddress(&p, g_cursor);  CUR = (int*)p;
        cudaGetSymbolAddress(&p, g_csr);     CSR = (int*)p;
        cudaGetSymbolAddress(&p, g_bsum);    BS = (int*)p;
    }

    float* agg_rr0 = S + O_AGG_RR0;
    float* agg_br0 = S + O_AGG_BR0;
    float* agg_rb0 = S + O_AGG_RB0;
    float* r_buf   = S + O_R;
    float* bl_buf  = S + O_BL;
    float* t_rr    = S + O_TRR;
    float* t_br    = S + O_TBR;
    float* agg_rr1 = S + O_AGG_RR1;
    float* agg_br1 = S + O_AGG_BR1;
    float* Wsum0   = S + O_WSUM0;
    float* bsum0   = S + O_BSUM0;
    float* Wsum1   = S + O_WSUM1;
    float* bsum1   = S + O_BSUM1;

    constexpr int SMEM128 = 2 * 17408 + 2 * 128 * 272;  // 104448
    constexpr int SMEM64  = 2 * 17408 + 2 * 64 * 272;   //  69632
    cudaFuncSetAttribute(gemm_hmma<128, 3, true>,
                         cudaFuncAttributeMaxDynamicSharedMemorySize, SMEM128);
    cudaFuncSetAttribute(gemm_hmma<128, 2, true>,
                         cudaFuncAttributeMaxDynamicSharedMemorySize, SMEM128);
    cudaFuncSetAttribute(gemm_hmma<64, 1, false>,
                         cudaFuncAttributeMaxDynamicSharedMemorySize, SMEM64);

    // ---- counts (only small memset now; no 205MB agg zeroing) ----
    cudaMemsetAsync(C, 0, 3ull * N_ROBOT * sizeof(int), 0);
    const int cb = (E + 255) / 256;
    count_kernel<<<cb, 256>>>(ei_rr + E, C, E);                  // type 0: rr -> robot
    count_kernel<<<cb, 256>>>(ei_br + E, C + N_ROBOT, E);        // type 1: br -> robot
    count_kernel<<<cb, 256>>>(ei_rb + E, C + 2 * N_ROBOT, E);    // type 2: rb -> ball

    // ---- CSR build: scan + fill ----
    scan1_kernel<<<SCAN_NB, SCAN_BS>>>(C, OFF, BS);
    scan2_kernel<<<1, 1024>>>(BS);
    scan3_kernel<<<SCAN_NB, SCAN_BS>>>(OFF, BS, CUR);
    fill_csr_kernel<<<cb, 256>>>(ei_rr, ei_rr + E, CUR, CSR, E, 0);
    fill_csr_kernel<<<cb, 256>>>(ei_br, ei_br + E, CUR, CSR, E, N_ROBOT);
    fill_csr_kernel<<<cb, 256>>>(ei_rb, ei_rb + E, CUR, CSR, E, 2 * N_ROBOT);

    // ---- fold shared-destination weights ----
    add2_kernel<<<64, 256>>>(Wr0_rr, Wr0_br, Wsum0, 128 * 128);
    add2_kernel<<<1, 128>>>(b0_rr, b0_br, bsum0, 128);
    add2_kernel<<<32, 256>>>(Wr1_rr, Wr1_br, Wsum1, 128 * 64);
    add2_kernel<<<1, 64>>>(b1_rr, b1_br, bsum1, 64);

    // ---- layer 0 aggregations: CSR gather (width 128) ----
    const int gwb = (N_ROBOT * 32 + 255) / 256;   // warp per dst row
    gather_mean_kernel<128><<<gwb, 256>>>(OFF, C, CSR, x_robot, agg_rr0, N_ROBOT);
    gather_mean_kernel<128><<<gwb, 256>>>(OFF + N_ROBOT, C + N_ROBOT, CSR,
                                          x_ball, agg_br0, N_ROBOT);
    gather_mean_kernel<128><<<gwb, 256>>>(OFF + 2 * N_ROBOT, C + 2 * N_ROBOT, CSR,
                                          x_robot, agg_rb0, N_BALL);

    const int gb = (N_ROBOT + 63) / 64;  // 1563

    // ---- layer 0 GEMMs (HMMA tensor path) ----
    gemm_hmma<128, 3, true><<<gb, 256, SMEM128>>>(
        N_ROBOT, agg_rr0, Wl0_rr, agg_br0, Wl0_br, x_robot, Wsum0,
        bsum0, nullptr, nullptr, r_buf);
    gemm_hmma<128, 2, true><<<gb, 256, SMEM128>>>(
        N_BALL, agg_rb0, Wl0_rb, x_ball, Wr0_rb, nullptr, nullptr,
        b0_rb, nullptr, nullptr, bl_buf);

    // ---- layer 1: transform first (width-64 aggregation) ----
    gemm_hmma<64, 1, false><<<gb, 256, SMEM64>>>(
        N_ROBOT, r_buf, Wl1_rr, nullptr, nullptr, nullptr, nullptr,
        nullptr, nullptr, nullptr, t_rr);
    gemm_hmma<64, 1, false><<<gb, 256, SMEM64>>>(
        N_BALL, bl_buf, Wl1_br, nullptr, nullptr, nullptr, nullptr,
        nullptr, nullptr, nullptr, t_br);

    // ---- layer 1 aggregations: reuse rr/br CSR (width 64) ----
    gather_mean_kernel<64><<<gwb, 256>>>(OFF, C, CSR, t_rr, agg_rr1, N_ROBOT);
    gather_mean_kernel<64><<<gwb, 256>>>(OFF + N_ROBOT, C + N_ROBOT, CSR,
                                         t_br, agg_br1, N_ROBOT);

    // ---- final: out = r @ (Wr1_rr+Wr1_br) + bsum1 + agg_rr1 + agg_br1 ----
    gemm_hmma<64, 1, false><<<gb, 256, SMEM64>>>(
        N_ROBOT, r_buf, Wsum1, nullptr, nullptr, nullptr, nullptr,
        bsum1, agg_rr1, agg_br1, out);
}

// round 7
// speedup vs baseline: 2.2022x; 1.0766x over previous
#include <cuda_runtime.h>
#include <cuda_bf16.h>
#include <stdint.h>

// ---------------------------------------------------------------------------
// Problem constants
// ---------------------------------------------------------------------------
#define N_ROBOT 100000
#define N_BALL  100000
#define E_MAX   600000

// ---------------------------------------------------------------------------
// Scratch (device globals; allocation is forbidden)
// ---------------------------------------------------------------------------
#define O_TRR    0ull                             // t_rr = r @ Wl1_rr   [100000*64]
#define O_TBR    (O_TRR + 6400000ull)             // t_br = bl @ Wl1_br  [100000*64]
#define O_FR     (O_TBR + 6400000ull)             // f_r  = r @ Wsum1    [100000*64]
#define O_WSUM0  (O_FR  + 6400000ull)             // 128*128
#define O_BSUM0  (O_WSUM0 + 16384ull)             // 128
#define O_WSUM1  (O_BSUM0 + 128ull)               // 128*64
#define O_BSUM1  (O_WSUM1 + 8192ull)              // 64
#define SCRATCH_FLOATS (O_BSUM1 + 64ull)

__device__ float g_scratch[SCRATCH_FLOATS];
__device__ int   g_cnt[3 * N_ROBOT];      // cnt_rr | cnt_br | cnt_rb
__device__ int   g_off[3 * N_ROBOT];      // exclusive scan (global over concat)
__device__ int   g_cursor[3 * N_ROBOT];
__device__ int   g_csr[3 * E_MAX + 64];
__device__ int   g_bsum[1024];

#define NSCAN   (3 * N_ROBOT)
#define SCAN_BS 512
#define SCAN_NB ((NSCAN + SCAN_BS - 1) / SCAN_BS)   // 586

// ---------------------------------------------------------------------------
// Helpers (baseline PTX only — harness compiles compute_103 w/o 'a').
// ---------------------------------------------------------------------------
__device__ __forceinline__ uint32_t smem_u32(const void* p) {
    uint32_t a;
    asm("{ .reg .u64 t; cvta.to.shared.u64 t, %1; cvt.u32.u64 %0, t; }"
        : "=r"(a) : "l"(p));
    return a;
}

#define LDSM_X4(r0, r1, r2, r3, addr) \
    asm volatile("ldmatrix.sync.aligned.m8n8.x4.shared.b16 {%0,%1,%2,%3}, [%4];" \
                 : "=r"(r0), "=r"(r1), "=r"(r2), "=r"(r3) : "r"(addr))

__device__ __forceinline__ void mma_bf16(float* c, const uint32_t* a,
                                         uint32_t b0, uint32_t b1) {
    asm volatile(
        "mma.sync.aligned.m16n8k16.row.col.f32.bf16.bf16.f32 "
        "{%0,%1,%2,%3}, {%4,%5,%6,%7}, {%8,%9}, {%0,%1,%2,%3};"
        : "+f"(c[0]), "+f"(c[1]), "+f"(c[2]), "+f"(c[3])
        : "r"(a[0]), "r"(a[1]), "r"(a[2]), "r"(a[3]), "r"(b0), "r"(b1));
}

__device__ __forceinline__ void split_pack(float x0, float x1,
                                           uint32_t& hp, uint32_t& lp) {
    __nv_bfloat16 h0 = __float2bfloat16(x0);
    __nv_bfloat16 h1 = __float2bfloat16(x1);
    __nv_bfloat16 l0 = __float2bfloat16(x0 - __bfloat162float(h0));
    __nv_bfloat16 l1 = __float2bfloat16(x1 - __bfloat162float(h1));
    hp = ((uint32_t)__bfloat16_as_ushort(h1) << 16) | __bfloat16_as_ushort(h0);
    lp = ((uint32_t)__bfloat16_as_ushort(l1) << 16) | __bfloat16_as_ushort(l0);
}

// SMEM layout constants (shared by both fused kernels)
//   A hi [64][136]bf16 | A lo | B area (69632 B)
#define STRIDE_B 272u                 // bytes per tile row
#define A_BYTES  17408u               // 64 * 272
#define SMEM_TOTAL (2 * 17408 + 69632)   // 104448

// ---------------------------------------------------------------------------
// Stage loaders + mainloop (device inline)
// ---------------------------------------------------------------------------
__device__ __forceinline__ void store_a_pair(uint32_t AH, uint32_t AL,
                                             uint32_t off, const float4& v) {
    uint32_t h01, l01, h23, l23;
    split_pack(v.x, v.y, h01, l01);
    split_pack(v.z, v.w, h23, l23);
    asm volatile("st.shared.v2.b32 [%0], {%1,%2};"
                 :: "r"(AH + off), "r"(h01), "r"(h23) : "memory");
    asm volatile("st.shared.v2.b32 [%0], {%1,%2};"
                 :: "r"(AL + off), "r"(l01), "r"(l23) : "memory");
}

// A tile directly from dense rows.
__device__ __forceinline__ void load_A_direct(const float* __restrict__ A,
                                              int row0, int M,
                                              uint32_t AH, uint32_t AL, int tid) {
#pragma unroll
    for (int i = 0; i < 8; i++) {
        int idx = tid + i * 256;
        int r  = idx >> 5;
        int c4 = idx & 31;
        float4 v = make_float4(0.f, 0.f, 0.f, 0.f);
        if (row0 + r < M)
            v = *(const float4*)(A + (size_t)(row0 + r) * 128 + c4 * 4);
        store_a_pair(AH, AL, (uint32_t)r * STRIDE_B + (uint32_t)c4 * 8, v);
    }
}

// A tile = CSR mean-gather (warp per row, lane per float4 chunk).
__device__ __forceinline__ void load_A_gather(const float* __restrict__ x,
                                              const int* __restrict__ off,
                                              const int* __restrict__ cnt,
                                              const int* __restrict__ csr,
                                              int row0, int M,
                                              uint32_t AH, uint32_t AL,
                                              int wid, int lane) {
#pragma unroll
    for (int i = 0; i < 8; i++) {
        int r  = wid + i * 8;
        int gr = row0 + r;
        float4 a = make_float4(0.f, 0.f, 0.f, 0.f);
        if (gr < M) {
            int st = off[gr];
            int dg = cnt[gr];
            int j = 0;
            for (; j + 2 <= dg; j += 2) {
                int s0 = csr[st + j];
                int s1 = csr[st + j + 1];
                float4 v0 = *(const float4*)(x + (size_t)s0 * 128 + lane * 4);
                float4 v1 = *(const float4*)(x + (size_t)s1 * 128 + lane * 4);
                a.x += v0.x + v1.x; a.y += v0.y + v1.y;
                a.z += v0.z + v1.z; a.w += v0.w + v1.w;
            }
            if (j < dg) {
                int s = csr[st + j];
                float4 v = *(const float4*)(x + (size_t)s * 128 + lane * 4);
                a.x += v.x; a.y += v.y; a.z += v.z; a.w += v.w;
            }
            float inv = (dg > 0) ? (1.0f / (float)dg) : 0.0f;
            a.x *= inv; a.y *= inv; a.z *= inv; a.w *= inv;
        }
        store_a_pair(AH, AL, (uint32_t)r * STRIDE_B + (uint32_t)lane * 8, a);
    }
}

// B tile: W[k][n] fp32 -> hi/lo bf16 n-major.
template <int N>
__device__ __forceinline__ void load_B(const float* __restrict__ W,
                                       uint32_t BH, uint32_t BL, int tid) {
    for (int idx = tid; idx < 128 * N; idx += 256) {
        int k = idx / N;
        int n = idx - k * N;
        float w = W[idx];
        __nv_bfloat16 h = __float2bfloat16(w);
        __nv_bfloat16 l = __float2bfloat16(w - __bfloat162float(h));
        uint32_t off = (uint32_t)n * STRIDE_B + (uint32_t)k * 2;
        unsigned short hs = __bfloat16_as_ushort(h);
        unsigned short ls = __bfloat16_as_ushort(l);
        asm volatile("st.shared.b16 [%0], %1;" :: "r"(BH + off), "h"(hs) : "memory");
        asm volatile("st.shared.b16 [%0], %1;" :: "r"(BL + off), "h"(ls) : "memory");
    }
}

// 64xN x 128 bf16-split mainloop, accumulating into acc[N/16][4].
template <int N>
__device__ __forceinline__ void mainloop(uint32_t AH, uint32_t AL,
                                         uint32_t BH, uint32_t BL,
                                         float (*acc)[4],
                                         int a_row, int a_kof,
                                         int b_nof, int b_kof, int wcg) {
    constexpr int NOCT = N / 16;
#pragma unroll
    for (int k0 = 0; k0 < 128; k0 += 16) {
        uint32_t ah[4], al[4];
        uint32_t aoff = (uint32_t)a_row * STRIDE_B + (uint32_t)(k0 + a_kof) * 2;
        LDSM_X4(ah[0], ah[1], ah[2], ah[3], AH + aoff);
        LDSM_X4(al[0], al[1], al[2], al[3], AL + aoff);
#pragma unroll
        for (int op = 0; op < NOCT; op += 2) {
            int nbase = wcg * (N / 2) + op * 8;
            uint32_t boff = (uint32_t)(nbase + b_nof) * STRIDE_B
                          + (uint32_t)(k0 + b_kof) * 2;
            uint32_t bh0, bh1, bh2, bh3, bl0, bl1, bl2, bl3;
            LDSM_X4(bh0, bh1, bh2, bh3, BH + boff);
            LDSM_X4(bl0, bl1, bl2, bl3, BL + boff);
            mma_bf16(acc[op],     ah, bh0, bh1);
            mma_bf16(acc[op],     al, bh0, bh1);
            mma_bf16(acc[op],     ah, bl0, bl1);
            mma_bf16(acc[op + 1], ah, bh2, bh3);
            mma_bf16(acc[op + 1], al, bh2, bh3);
            mma_bf16(acc[op + 1], ah, bl2, bl3);
        }
    }
}

// ---------------------------------------------------------------------------
// Small kernels: counts, folding, CSR build
// ---------------------------------------------------------------------------
__global__ void count_kernel(const int* __restrict__ dst,
                             int* __restrict__ cnt, int E) {
    int i = blockIdx.x * blockDim.x + threadIdx.x;
    if (i < E) atomicAdd(&cnt[dst[i]], 1);
}

__global__ void add2_kernel(const float* __restrict__ a,
                            const float* __restrict__ b,
                            float* __restrict__ o, int n) {
    int i = blockIdx.x * blockDim.x + threadIdx.x;
    if (i < n) o[i] = a[i] + b[i];
}

__global__ void scan1_kernel(const int* __restrict__ cnt,
                             int* __restrict__ out, int* __restrict__ bsum) {
    __shared__ int sh[SCAN_BS];
    int gid = blockIdx.x * SCAN_BS + threadIdx.x;
    int v = (gid < NSCAN) ? cnt[gid] : 0;
    sh[threadIdx.x] = v;
    __syncthreads();
#pragma unroll
    for (int d = 1; d < SCAN_BS; d <<= 1) {
        int t = (threadIdx.x >= d) ? sh[threadIdx.x - d] : 0;
        __syncthreads();
        sh[threadIdx.x] += t;
        __syncthreads();
    }
    if (gid < NSCAN) out[gid] = sh[threadIdx.x] - v;
    if (threadIdx.x == SCAN_BS - 1) bsum[blockIdx.x] = sh[threadIdx.x];
}

__global__ void scan2_kernel(int* __restrict__ bsum) {
    __shared__ int sh[1024];
    int i = threadIdx.x;
    int v = (i < SCAN_NB) ? bsum[i] : 0;
    sh[i] = v;
    __syncthreads();
#pragma unroll
    for (int d = 1; d < 1024; d <<= 1) {
        int t = (i >= d) ? sh[i - d] : 0;
        __syncthreads();
        sh[i] += t;
        __syncthreads();
    }
    if (i < SCAN_NB) bsum[i] = sh[i] - v;
}

__global__ void scan3_kernel(int* __restrict__ out, const int* __restrict__ bsum,
                             int* __restrict__ cursor) {
    int gid = blockIdx.x * SCAN_BS + threadIdx.x;
    if (gid < NSCAN) {
        int o = out[gid] + bsum[blockIdx.x];
        out[gid] = o;
        cursor[gid] = o;
    }
}

__global__ void fill_csr_kernel(const int* __restrict__ src,
                                const int* __restrict__ dst,
                                int* __restrict__ cursor,
                                int* __restrict__ csr, int E, int base) {
    int i = blockIdx.x * blockDim.x + threadIdx.x;
    if (i < E) {
        int pos = atomicAdd(&cursor[base + dst[i]], 1);
        csr[pos] = src[i];
    }
}

// ---------------------------------------------------------------------------
// Fused robot layer-0 + layer-1 transforms:
//   r    = relu( mean_rr(x_robot)@Wl0_rr + mean_br(x_ball)@Wl0_br
//              + x_robot@Wsum0 + bsum0 )          (kept in SMEM only)
//   t_rr = r @ Wl1_rr
//   f_r  = r @ Wsum1
// ---------------------------------------------------------------------------
__global__ void __launch_bounds__(256)
robot_fused_kernel(const float* __restrict__ x_robot,
                   const float* __restrict__ x_ball,
                   const int* __restrict__ off, const int* __restrict__ cnt,
                   const int* __restrict__ csr,
                   const float* __restrict__ Wl0_rr,
                   const float* __restrict__ Wl0_br,
                   const float* __restrict__ Wsum0,
                   const float* __restrict__ bsum0,
                   const float* __restrict__ Wl1_rr,
                   const float* __restrict__ Wsum1,
                   float* __restrict__ t_rr,
                   float* __restrict__ f_r) {
    extern __shared__ char smem[];
    const uint32_t AH = smem_u32(smem);
    const uint32_t AL = AH + A_BYTES;
    const uint32_t BB = AL + A_BYTES;     // 69632-byte B area

    const int tid  = threadIdx.x;
    const int wid  = tid >> 5;
    const int lane = tid & 31;
    const int wr   = wid & 3;
    const int wcg  = wid >> 2;
    const int row0 = blockIdx.x * 64;
    const int M    = N_ROBOT;

    const int a_row = wr * 16 + ((lane >> 3) & 1) * 8 + (lane & 7);
    const int a_kof = (lane >> 4) * 8;
    const int b_nof = ((lane >> 4) & 1) * 8 + (lane & 7);
    const int b_kof = ((lane >> 3) & 1) * 8;

    float acc[8][4];
#pragma unroll
    for (int o = 0; o < 8; o++)
#pragma unroll
        for (int j = 0; j < 4; j++) acc[o][j] = 0.0f;

    // ---- stage 1: three terms, N=128 ----
    // term 0: mean over rr neighbors of x_robot
    load_A_gather(x_robot, off, cnt, csr, row0, M, AH, AL, wid, lane);
    load_B<128>(Wl0_rr, BB, BB + 34816, tid);
    __syncthreads();
    mainloop<128>(AH, AL, BB, BB + 34816, acc, a_row, a_kof, b_nof, b_kof, wcg);
    __syncthreads();
    // term 1: mean over br neighbors of x_ball
    load_A_gather(x_ball, off + N_ROBOT, cnt + N_ROBOT, csr, row0, M, AH, AL, wid, lane);
    load_B<128>(Wl0_br, BB, BB + 34816, tid);
    __syncthreads();
    mainloop<128>(AH, AL, BB, BB + 34816, acc, a_row, a_kof, b_nof, b_kof, wcg);
    __syncthreads();
    // term 2: x_robot direct
    load_A_direct(x_robot, row0, M, AH, AL, tid);
    load_B<128>(Wsum0, BB, BB + 34816, tid);
    __syncthreads();
    mainloop<128>(AH, AL, BB, BB + 34816, acc, a_row, a_kof, b_nof, b_kof, wcg);
    __syncthreads();

    // ---- epilogue 1: bias + relu, write r tile to SMEM (bf16 hi/lo) ----
    {
        const int rAl = wr * 16 + (lane >> 2);   // local rows 0..63
        const int rBl = rAl + 8;
#pragma unroll
        for (int o = 0; o < 8; o++) {
            int col = wcg * 64 + o * 8 + (lane & 3) * 2;
            float2 bv = *(const float2*)(bsum0 + col);
            float v0 = fmaxf(acc[o][0] + bv.x, 0.f);
            float v1 = fmaxf(acc[o][1] + bv.y, 0.f);
            float v2 = fmaxf(acc[o][2] + bv.x, 0.f);
            float v3 = fmaxf(acc[o][3] + bv.y, 0.f);
            uint32_t h, l;
            uint32_t offA = (uint32_t)rAl * STRIDE_B + (uint32_t)col * 2;
            split_pack(v0, v1, h, l);
            asm volatile("st.shared.b32 [%0], %1;" :: "r"(AH + offA), "r"(h) : "memory");
            asm volatile("st.shared.b32 [%0], %1;" :: "r"(AL + offA), "r"(l) : "memory");
            uint32_t offB = (uint32_t)rBl * STRIDE_B + (uint32_t)col * 2;
            split_pack(v2, v3, h, l);
            asm volatile("st.shared.b32 [%0], %1;" :: "r"(AH + offB), "r"(h) : "memory");
            asm volatile("st.shared.b32 [%0], %1;" :: "r"(AL + offB), "r"(l) : "memory");
        }
    }
    // ---- stage 2 B: Wl1_rr (slot 0) and Wsum1 (slot 1), N=64 ----
    load_B<64>(Wl1_rr, BB,             BB + 17408, tid);
    load_B<64>(Wsum1,  BB + 2 * 17408, BB + 3 * 17408, tid);
    __syncthreads();

    float acc2a[4][4], acc2b[4][4];
#pragma unroll
    for (int o = 0; o < 4; o++)
#pragma unroll
        for (int j = 0; j < 4; j++) { acc2a[o][j] = 0.f; acc2b[o][j] = 0.f; }

    mainloop<64>(AH, AL, BB,             BB + 17408,     acc2a,
                 a_row, a_kof, b_nof, b_kof, wcg);
    mainloop<64>(AH, AL, BB + 2 * 17408, BB + 3 * 17408, acc2b,
                 a_row, a_kof, b_nof, b_kof, wcg);

    // ---- epilogue 2: store t_rr and f_r ----
    const int rA = row0 + wr * 16 + (lane >> 2);
    const int rB = rA + 8;
#pragma unroll
    for (int o = 0; o < 4; o++) {
        int col = wcg * 32 + o * 8 + (lane & 3) * 2;
        if (rA < M) {
            *(float2*)(t_rr + (size_t)rA * 64 + col) = make_float2(acc2a[o][0], acc2a[o][1]);
            *(float2*)(f_r  + (size_t)rA * 64 + col) = make_float2(acc2b[o][0], acc2b[o][1]);
        }
        if (rB < M) {
            *(float2*)(t_rr + (size_t)rB * 64 + col) = make_float2(acc2a[o][2], acc2a[o][3]);
            *(float2*)(f_r  + (size_t)rB * 64 + col) = make_float2(acc2b[o][2], acc2b[o][3]);
        }
    }
}

// ---------------------------------------------------------------------------
// Fused ball layer-0 + layer-1 transform:
//   bl   = relu( mean_rb(x_robot)@Wl0_rb + x_ball@Wr0_rb + b0_rb )
//   t_br = bl @ Wl1_br
// ---------------------------------------------------------------------------
__global__ void __launch_bounds__(256)
ball_fused_kernel(const float* __restrict__ x_robot,
                  const float* __restrict__ x_ball,
                  const int* __restrict__ off, const int* __restrict__ cnt,
                  const int* __restrict__ csr,
                  const float* __restrict__ Wl0_rb,
                  const float* __restrict__ Wr0_rb,
                  const float* __restrict__ b0_rb,
                  const float* __restrict__ Wl1_br,
                  float* __restrict__ t_br) {
    extern __shared__ char smem[];
    const uint32_t AH = smem_u32(smem);
    const uint32_t AL = AH + A_BYTES;
    const uint32_t BB = AL + A_BYTES;

    const int tid  = threadIdx.x;
    const int wid  = tid >> 5;
    const int lane = tid & 31;
    const int wr   = wid & 3;
    const int wcg  = wid >> 2;
    const int row0 = blockIdx.x * 64;
    const int M    = N_BALL;

    const int a_row = wr * 16 + ((lane >> 3) & 1) * 8 + (lane & 7);
    const int a_kof = (lane >> 4) * 8;
    const int b_nof = ((lane >> 4) & 1) * 8 + (lane & 7);
    const int b_kof = ((lane >> 3) & 1) * 8;

    float acc[8][4];
#pragma unroll
    for (int o = 0; o < 8; o++)
#pragma unroll
        for (int j = 0; j < 4; j++) acc[o][j] = 0.0f;

    // term 0: mean over rb neighbors of x_robot
    load_A_gather(x_robot, off, cnt, csr, row0, M, AH, AL, wid, lane);
    load_B<128>(Wl0_rb, BB, BB + 34816, tid);
    __syncthreads();
    mainloop<128>(AH, AL, BB, BB + 34816, acc, a_row, a_kof, b_nof, b_kof, wcg);
    __syncthreads();
    // term 1: x_ball direct
    load_A_direct(x_ball, row0, M, AH, AL, tid);
    load_B<128>(Wr0_rb, BB, BB + 34816, tid);
    __syncthreads();
    mainloop<128>(AH, AL, BB, BB + 34816, acc, a_row, a_kof, b_nof, b_kof, wcg);
    __syncthreads();

    // epilogue 1 -> SMEM bl tile
    {
        const int rAl = wr * 16 + (lane >> 2);
        const int rBl = rAl + 8;
#pragma unroll
        for (int o = 0; o < 8; o++) {
            int col = wcg * 64 + o * 8 + (lane & 3) * 2;
            float2 bv = *(const float2*)(b0_rb + col);
            float v0 = fmaxf(acc[o][0] + bv.x, 0.f);
            float v1 = fmaxf(acc[o][1] + bv.y, 0.f);
            float v2 = fmaxf(acc[o][2] + bv.x, 0.f);
            float v3 = fmaxf(acc[o][3] + bv.y, 0.f);
            uint32_t h, l;
            uint32_t offA = (uint32_t)rAl * STRIDE_B + (uint32_t)col * 2;
            split_pack(v0, v1, h, l);
            asm volatile("st.shared.b32 [%0], %1;" :: "r"(AH + offA), "r"(h) : "memory");
            asm volatile("st.shared.b32 [%0], %1;" :: "r"(AL + offA), "r"(l) : "memory");
            uint32_t offB = (uint32_t)rBl * STRIDE_B + (uint32_t)col * 2;
            split_pack(v2, v3, h, l);
            asm volatile("st.shared.b32 [%0], %1;" :: "r"(AH + offB), "r"(h) : "memory");
            asm volatile("st.shared.b32 [%0], %1;" :: "r"(AL + offB), "r"(l) : "memory");
        }
    }
    load_B<64>(Wl1_br, BB, BB + 17408, tid);
    __syncthreads();

    float acc2[4][4];
#pragma unroll
    for (int o = 0; o < 4; o++)
#pragma unroll
        for (int j = 0; j < 4; j++) acc2[o][j] = 0.f;

    mainloop<64>(AH, AL, BB, BB + 17408, acc2, a_row, a_kof, b_nof, b_kof, wcg);

    const int rA = row0 + wr * 16 + (lane >> 2);
    const int rB = rA + 8;
#pragma unroll
    for (int o = 0; o < 4; o++) {
        int col = wcg * 32 + o * 8 + (lane & 3) * 2;
        if (rA < M)
            *(float2*)(t_br + (size_t)rA * 64 + col) = make_float2(acc2[o][0], acc2[o][1]);
        if (rB < M)
            *(float2*)(t_br + (size_t)rB * 64 + col) = make_float2(acc2[o][2], acc2[o][3]);
    }
}

// ---------------------------------------------------------------------------
// Final: out[d] = mean_rr(t_rr) + mean_br(t_br) + f_r[d] + bsum1
// One warp per robot row, lane holds float2.
// ---------------------------------------------------------------------------
__global__ void __launch_bounds__(256)
final_kernel(const int* __restrict__ off_rr, const int* __restrict__ cnt_rr,
             const int* __restrict__ off_br, const int* __restrict__ cnt_br,
             const int* __restrict__ csr,
             const float* __restrict__ t_rr, const float* __restrict__ t_br,
             const float* __restrict__ f_r, const float* __restrict__ bsum1,
             float* __restrict__ out) {
    int warp = (blockIdx.x * blockDim.x + threadIdx.x) >> 5;
    int lane = threadIdx.x & 31;
    if (warp >= N_ROBOT) return;

    float2 res = *(const float2*)(f_r + (size_t)warp * 64 + lane * 2);
    float2 bv  = *(const float2*)(bsum1 + lane * 2);
    res.x += bv.x; res.y += bv.y;

    {
        int st = off_rr[warp], dg = cnt_rr[warp];
        float2 a = make_float2(0.f, 0.f);
        int j = 0;
        for (; j + 2 <= dg; j += 2) {
            int s0 = csr[st + j], s1 = csr[st + j + 1];
            float2 v0 = *(const float2*)(t_rr + (size_t)s0 * 64 + lane * 2);
            float2 v1 = *(const float2*)(t_rr + (size_t)s1 * 64 + lane * 2);
            a.x += v0.x + v1.x; a.y += v0.y + v1.y;
        }
        if (j < dg) {
            int s = csr[st + j];
            float2 v = *(const float2*)(t_rr + (size_t)s * 64 + lane * 2);
            a.x += v.x; a.y += v.y;
        }
        float inv = (dg > 0) ? (1.0f / (float)dg) : 0.0f;
        res.x += a.x * inv; res.y += a.y * inv;
    }
    {
        int st = off_br[warp], dg = cnt_br[warp];
        float2 a = make_float2(0.f, 0.f);
        int j = 0;
        for (; j + 2 <= dg; j += 2) {
            int s0 = csr[st + j], s1 = csr[st + j + 1];
            float2 v0 = *(const float2*)(t_br + (size_t)s0 * 64 + lane * 2);
            float2 v1 = *(const float2*)(t_br + (size_t)s1 * 64 + lane * 2);
            a.x += v0.x + v1.x; a.y += v0.y + v1.y;
        }
        if (j < dg) {
            int s = csr[st + j];
            float2 v = *(const float2*)(t_br + (size_t)s * 64 + lane * 2);
            a.x += v.x; a.y += v.y;
        }
        float inv = (dg > 0) ? (1.0f / (float)dg) : 0.0f;
        res.x += a.x * inv; res.y += a.y * inv;
    }
    *(float2*)(out + (size_t)warp * 64 + lane * 2) = res;
}

// ---------------------------------------------------------------------------
// Launch
// ---------------------------------------------------------------------------
extern "C" void kernel_launch(void* const* d_in, const int* in_sizes, int n_in,
                              void* d_out, int out_size) {
    (void)n_in; (void)out_size;

    const float* x_robot = (const float*)d_in[0];
    const float* x_ball  = (const float*)d_in[1];
    const int* ei_rr = (const int*)d_in[2];
    const int* ei_rb = (const int*)d_in[3];
    const int* ei_br = (const int*)d_in[4];
    const float* Wl0_rr = (const float*)d_in[5];
    const float* Wr0_rr = (const float*)d_in[6];
    const float* b0_rr  = (const float*)d_in[7];
    const float* Wl0_rb = (const float*)d_in[8];
    const float* Wr0_rb = (const float*)d_in[9];
    const float* b0_rb  = (const float*)d_in[10];
    const float* Wl0_br = (const float*)d_in[11];
    const float* Wr0_br = (const float*)d_in[12];
    const float* b0_br  = (const float*)d_in[13];
    const float* Wl1_rr = (const float*)d_in[14];
    const float* Wr1_rr = (const float*)d_in[15];
    const float* b1_rr  = (const float*)d_in[16];
    const float* Wl1_br = (const float*)d_in[20];
    const float* Wr1_br = (const float*)d_in[21];
    const float* b1_br  = (const float*)d_in[22];

    float* out = (float*)d_out;
    const int E = in_sizes[2] / 2;

    float* S = nullptr;
    int *C = nullptr, *OFF = nullptr, *CUR = nullptr, *CSR = nullptr, *BS = nullptr;
    {
        void* p = nullptr;
        cudaGetSymbolAddress(&p, g_scratch); S = (float*)p;
        cudaGetSymbolAddress(&p, g_cnt);     C = (int*)p;
        cudaGetSymbolAddress(&p, g_off);     OFF = (int*)p;
        cudaGetSymbolAddress(&p, g_cursor);  CUR = (int*)p;
        cudaGetSymbolAddress(&p, g_csr);     CSR = (int*)p;
        cudaGetSymbolAddress(&p, g_bsum);    BS = (int*)p;
    }

    float* t_rr  = S + O_TRR;
    float* t_br  = S + O_TBR;
    float* f_r   = S + O_FR;
    float* Wsum0 = S + O_WSUM0;
    float* bsum0 = S + O_BSUM0;
    float* Wsum1 = S + O_WSUM1;
    float* bsum1 = S + O_BSUM1;

    cudaFuncSetAttribute(robot_fused_kernel,
                         cudaFuncAttributeMaxDynamicSharedMemorySize, SMEM_TOTAL);
    cudaFuncSetAttribute(ball_fused_kernel,
                         cudaFuncAttributeMaxDynamicSharedMemorySize, SMEM_TOTAL);

    // ---- counts ----
    cudaMemsetAsync(C, 0, 3ull * N_ROBOT * sizeof(int), 0);
    const int cb = (E + 255) / 256;
    count_kernel<<<cb, 256>>>(ei_rr + E, C, E);                  // rr -> robot
    count_kernel<<<cb, 256>>>(ei_br + E, C + N_ROBOT, E);        // br -> robot
    count_kernel<<<cb, 256>>>(ei_rb + E, C + 2 * N_ROBOT, E);    // rb -> ball

    // ---- CSR build ----
    scan1_kernel<<<SCAN_NB, SCAN_BS>>>(C, OFF, BS);
    scan2_kernel<<<1, 1024>>>(BS);
    scan3_kernel<<<SCAN_NB, SCAN_BS>>>(OFF, BS, CUR);
    fill_csr_kernel<<<cb, 256>>>(ei_rr, ei_rr + E, CUR, CSR, E, 0);
    fill_csr_kernel<<<cb, 256>>>(ei_br, ei_br + E, CUR, CSR, E, N_ROBOT);
    fill_csr_kernel<<<cb, 256>>>(ei_rb, ei_rb + E, CUR, CSR, E, 2 * N_ROBOT);

    // ---- fold shared-destination weights ----
    add2_kernel<<<64, 256>>>(Wr0_rr, Wr0_br, Wsum0, 128 * 128);
    add2_kernel<<<1, 128>>>(b0_rr, b0_br, bsum0, 128);
    add2_kernel<<<32, 256>>>(Wr1_rr, Wr1_br, Wsum1, 128 * 64);
    add2_kernel<<<1, 64>>>(b1_rr, b1_br, bsum1, 64);

    // ---- fused compute ----
    const int gb = (N_ROBOT + 63) / 64;  // 1563
    robot_fused_kernel<<<gb, 256, SMEM_TOTAL>>>(
        x_robot, x_ball, OFF, C, CSR,
        Wl0_rr, Wl0_br, Wsum0, bsum0, Wl1_rr, Wsum1, t_rr, f_r);
    ball_fused_kernel<<<gb, 256, SMEM_TOTAL>>>(
        x_robot, x_ball, OFF + 2 * N_ROBOT, C + 2 * N_ROBOT, CSR,
        Wl0_rb, Wr0_rb, b0_rb, Wl1_br, t_br);

    // ---- final combine (fused layer-1 gathers) ----
    const int fb = (N_ROBOT * 32 + 255) / 256;   // 12500
    final_kernel<<<fb, 256>>>(OFF, C, OFF + N_ROBOT, C + N_ROBOT, CSR,
                              t_rr, t_br, f_r, bsum1, out);
}

// round 8
// speedup vs baseline: 2.4983x; 1.1345x over previous
#include <cuda_runtime.h>
#include <cuda_bf16.h>
#include <stdint.h>

// ---------------------------------------------------------------------------
// Problem constants
// ---------------------------------------------------------------------------
#define N_ROBOT 100000
#define N_BALL  100000
#define E_MAX   600000

// ---------------------------------------------------------------------------
// Scratch (device globals; allocation is forbidden)
// Pre-split weight buffers: [n][136] bf16 hi-plane then lo-plane, ready for
// direct float4 copy into the SMEM B area.
//   N=128 buffer: 2*128*136 bf16 = 17408 floats
//   N=64  buffer: 2* 64*136 bf16 =  8704 floats
// ---------------------------------------------------------------------------
#define O_TRR     0ull                            // [100000*64]
#define O_TBR     (O_TRR + 6400000ull)
#define O_FR      (O_TBR + 6400000ull)
#define O_BSUM0   (O_FR  + 6400000ull)            // 128
#define O_BSUM1   (O_BSUM0 + 128ull)              // 64
#define O_WB0_RR  (O_BSUM1 + 64ull)               // 17408 each (N=128)
#define O_WB0_BR  (O_WB0_RR + 17408ull)
#define O_WBSUM0  (O_WB0_BR + 17408ull)
#define O_WB0_RB  (O_WBSUM0 + 17408ull)
#define O_WBR0_RB (O_WB0_RB + 17408ull)
#define O_WB1_RR  (O_WBR0_RB + 17408ull)          // 8704 each (N=64)
#define O_WBSUM1  (O_WB1_RR + 8704ull)
#define O_WB1_BR  (O_WBSUM1 + 8704ull)
#define SCRATCH_FLOATS (O_WB1_BR + 8704ull)

__device__ float g_scratch[SCRATCH_FLOATS];
__device__ int   g_cnt[3 * N_ROBOT];
__device__ int   g_off[3 * N_ROBOT];
__device__ int   g_cursor[3 * N_ROBOT];
__device__ int   g_csr[3 * E_MAX + 64];
__device__ int   g_bsum[1024];

#define NSCAN   (3 * N_ROBOT)
#define SCAN_BS 512
#define SCAN_NB ((NSCAN + SCAN_BS - 1) / SCAN_BS)

// ---------------------------------------------------------------------------
// Helpers (baseline PTX only — harness targets compute_103 w/o 'a').
// ---------------------------------------------------------------------------
__device__ __forceinline__ uint32_t smem_u32(const void* p) {
    uint32_t a;
    asm("{ .reg .u64 t; cvta.to.shared.u64 t, %1; cvt.u32.u64 %0, t; }"
        : "=r"(a) : "l"(p));
    return a;
}

#define LDSM_X4(r0, r1, r2, r3, addr) \
    asm volatile("ldmatrix.sync.aligned.m8n8.x4.shared.b16 {%0,%1,%2,%3}, [%4];" \
                 : "=r"(r0), "=r"(r1), "=r"(r2), "=r"(r3) : "r"(addr))

__device__ __forceinline__ void mma_bf16(float* c, const uint32_t* a,
                                         uint32_t b0, uint32_t b1) {
    asm volatile(
        "mma.sync.aligned.m16n8k16.row.col.f32.bf16.bf16.f32 "
        "{%0,%1,%2,%3}, {%4,%5,%6,%7}, {%8,%9}, {%0,%1,%2,%3};"
        : "+f"(c[0]), "+f"(c[1]), "+f"(c[2]), "+f"(c[3])
        : "r"(a[0]), "r"(a[1]), "r"(a[2]), "r"(a[3]), "r"(b0), "r"(b1));
}

__device__ __forceinline__ void split_pack(float x0, float x1,
                                           uint32_t& hp, uint32_t& lp) {
    __nv_bfloat16 h0 = __float2bfloat16(x0);
    __nv_bfloat16 h1 = __float2bfloat16(x1);
    __nv_bfloat16 l0 = __float2bfloat16(x0 - __bfloat162float(h0));
    __nv_bfloat16 l1 = __float2bfloat16(x1 - __bfloat162float(h1));
    hp = ((uint32_t)__bfloat16_as_ushort(h1) << 16) | __bfloat16_as_ushort(h0);
    lp = ((uint32_t)__bfloat16_as_ushort(l1) << 16) | __bfloat16_as_ushort(l0);
}

// SMEM layout constants
#define STRIDE_B 272u                 // bytes per tile row (136 bf16)
#define A_BYTES  17408u               // 64 * 272
#define SMEM_TOTAL (2 * 17408 + 69632)   // 104448

// ---------------------------------------------------------------------------
// Stage loaders + mainloop
// ---------------------------------------------------------------------------
__device__ __forceinline__ void store_a_pair(uint32_t AH, uint32_t AL,
                                             uint32_t off, const float4& v) {
    uint32_t h01, l01, h23, l23;
    split_pack(v.x, v.y, h01, l01);
    split_pack(v.z, v.w, h23, l23);
    asm volatile("st.shared.v2.b32 [%0], {%1,%2};"
                 :: "r"(AH + off), "r"(h01), "r"(h23) : "memory");
    asm volatile("st.shared.v2.b32 [%0], {%1,%2};"
                 :: "r"(AL + off), "r"(l01), "r"(l23) : "memory");
}

__device__ __forceinline__ void load_A_direct(const float* __restrict__ A,
                                              int row0, int M,
                                              uint32_t AH, uint32_t AL, int tid) {
#pragma unroll
    for (int i = 0; i < 8; i++) {
        int idx = tid + i * 256;
        int r  = idx >> 5;
        int c4 = idx & 31;
        float4 v = make_float4(0.f, 0.f, 0.f, 0.f);
        if (row0 + r < M)
            v = *(const float4*)(A + (size_t)(row0 + r) * 128 + c4 * 4);
        store_a_pair(AH, AL, (uint32_t)r * STRIDE_B + (uint32_t)c4 * 8, v);
    }
}

__device__ __forceinline__ void load_A_gather(const float* __restrict__ x,
                                              const int* __restrict__ off,
                                              const int* __restrict__ cnt,
                                              const int* __restrict__ csr,
                                              int row0, int M,
                                              uint32_t AH, uint32_t AL,
                                              int wid, int lane) {
#pragma unroll
    for (int i = 0; i < 8; i++) {
        int r  = wid + i * 8;
        int gr = row0 + r;
        float4 a = make_float4(0.f, 0.f, 0.f, 0.f);
        if (gr < M) {
            int st = off[gr];
            int dg = cnt[gr];
            int j = 0;
            for (; j + 2 <= dg; j += 2) {
                int s0 = csr[st + j];
                int s1 = csr[st + j + 1];
                float4 v0 = *(const float4*)(x + (size_t)s0 * 128 + lane * 4);
                float4 v1 = *(const float4*)(x + (size_t)s1 * 128 + lane * 4);
                a.x += v0.x + v1.x; a.y += v0.y + v1.y;
                a.z += v0.z + v1.z; a.w += v0.w + v1.w;
            }
            if (j < dg) {
                int s = csr[st + j];
                float4 v = *(const float4*)(x + (size_t)s * 128 + lane * 4);
                a.x += v.x; a.y += v.y; a.z += v.z; a.w += v.w;
            }
            float inv = (dg > 0) ? (1.0f / (float)dg) : 0.0f;
            a.x *= inv; a.y *= inv; a.z *= inv; a.w *= inv;
        }
        store_a_pair(AH, AL, (uint32_t)r * STRIDE_B + (uint32_t)lane * 8, a);
    }
}

// B tile: straight float4 copy of a pre-split weight buffer into SMEM.
template <int N>
__device__ __forceinline__ void load_B_pre(const float* __restrict__ src,
                                           uint32_t BB, int tid) {
    constexpr int T4 = (2 * N * 136 * 2) / 16;   // float4 count: 34*N
    const float4* s = (const float4*)src;
#pragma unroll
    for (int i = tid; i < T4; i += 256) {
        float4 v = s[i];
        asm volatile("st.shared.v4.b32 [%0], {%1,%2,%3,%4};"
                     :: "r"(BB + (uint32_t)i * 16),
                        "r"(__float_as_uint(v.x)), "r"(__float_as_uint(v.y)),
                        "r"(__float_as_uint(v.z)), "r"(__float_as_uint(v.w))
                     : "memory");
    }
}

template <int N>
__device__ __forceinline__ void mainloop(uint32_t AH, uint32_t AL,
                                         uint32_t BH, uint32_t BL,
                                         float (*acc)[4],
                                         int a_row, int a_kof,
                                         int b_nof, int b_kof, int wcg) {
    constexpr int NOCT = N / 16;
#pragma unroll
    for (int k0 = 0; k0 < 128; k0 += 16) {
        uint32_t ah[4], al[4];
        uint32_t aoff = (uint32_t)a_row * STRIDE_B + (uint32_t)(k0 + a_kof) * 2;
        LDSM_X4(ah[0], ah[1], ah[2], ah[3], AH + aoff);
        LDSM_X4(al[0], al[1], al[2], al[3], AL + aoff);
#pragma unroll
        for (int op = 0; op < NOCT; op += 2) {
            int nbase = wcg * (N / 2) + op * 8;
            uint32_t boff = (uint32_t)(nbase + b_nof) * STRIDE_B
                          + (uint32_t)(k0 + b_kof) * 2;
            uint32_t bh0, bh1, bh2, bh3, bl0, bl1, bl2, bl3;
            LDSM_X4(bh0, bh1, bh2, bh3, BH + boff);
            LDSM_X4(bl0, bl1, bl2, bl3, BL + boff);
            mma_bf16(acc[op],     ah, bh0, bh1);
            mma_bf16(acc[op],     al, bh0, bh1);
            mma_bf16(acc[op],     ah, bl0, bl1);
            mma_bf16(acc[op + 1], ah, bh2, bh3);
            mma_bf16(acc[op + 1], al, bh2, bh3);
            mma_bf16(acc[op + 1], ah, bl2, bl3);
        }
    }
}

// ---------------------------------------------------------------------------
// Small kernels
// ---------------------------------------------------------------------------
__global__ void count_kernel(const int* __restrict__ dst,
                             int* __restrict__ cnt, int E) {
    int i = blockIdx.x * blockDim.x + threadIdx.x;
    if (i < E) atomicAdd(&cnt[dst[i]], 1);
}

__global__ void add2_kernel(const float* __restrict__ a,
                            const float* __restrict__ b,
                            float* __restrict__ o, int n) {
    int i = blockIdx.x * blockDim.x + threadIdx.x;
    if (i < n) o[i] = a[i] + b[i];
}

// One-time weight split (+ optional fold): W[k][n] fp32 ->
// out bf16 [n][136] hi-plane then lo-plane.
template <int N, bool FOLD>
__global__ void splitw_kernel(const float* __restrict__ A,
                              const float* __restrict__ B2,
                              float* __restrict__ outf) {
    int e = blockIdx.x * blockDim.x + threadIdx.x;
    if (e >= 128 * N) return;
    int k = e / N;
    int n = e - k * N;
    float w = A[e];
    if (FOLD) w += B2[e];
    __nv_bfloat16 h = __float2bfloat16(w);
    __nv_bfloat16 l = __float2bfloat16(w - __bfloat162float(h));
    __nv_bfloat16* out = (__nv_bfloat16*)outf;
    out[n * 136 + k] = h;
    out[N * 136 + n * 136 + k] = l;
}

__global__ void scan1_kernel(const int* __restrict__ cnt,
                             int* __restrict__ out, int* __restrict__ bsum) {
    __shared__ int sh[SCAN_BS];
    int gid = blockIdx.x * SCAN_BS + threadIdx.x;
    int v = (gid < NSCAN) ? cnt[gid] : 0;
    sh[threadIdx.x] = v;
    __syncthreads();
#pragma unroll
    for (int d = 1; d < SCAN_BS; d <<= 1) {
        int t = (threadIdx.x >= d) ? sh[threadIdx.x - d] : 0;
        __syncthreads();
        sh[threadIdx.x] += t;
        __syncthreads();
    }
    if (gid < NSCAN) out[gid] = sh[threadIdx.x] - v;
    if (threadIdx.x == SCAN_BS - 1) bsum[blockIdx.x] = sh[threadIdx.x];
}

__global__ void scan2_kernel(int* __restrict__ bsum) {
    __shared__ int sh[1024];
    int i = threadIdx.x;
    int v = (i < SCAN_NB) ? bsum[i] : 0;
    sh[i] = v;
    __syncthreads();
#pragma unroll
    for (int d = 1; d < 1024; d <<= 1) {
        int t = (i >= d) ? sh[i - d] : 0;
        __syncthreads();
        sh[i] += t;
        __syncthreads();
    }
    if (i < SCAN_NB) bsum[i] = sh[i] - v;
}

__global__ void scan3_kernel(int* __restrict__ out, const int* __restrict__ bsum,
                             int* __restrict__ cursor) {
    int gid = blockIdx.x * SCAN_BS + threadIdx.x;
    if (gid < NSCAN) {
        int o = out[gid] + bsum[blockIdx.x];
        out[gid] = o;
        cursor[gid] = o;
    }
}

__global__ void fill_csr_kernel(const int* __restrict__ src,
                                const int* __restrict__ dst,
                                int* __restrict__ cursor,
                                int* __restrict__ csr, int E, int base) {
    int i = blockIdx.x * blockDim.x + threadIdx.x;
    if (i < E) {
        int pos = atomicAdd(&cursor[base + dst[i]], 1);
        csr[pos] = src[i];
    }
}

// ---------------------------------------------------------------------------
// Fused robot kernel (pre-split weights)
// ---------------------------------------------------------------------------
__global__ void __launch_bounds__(256)
robot_fused_kernel(const float* __restrict__ x_robot,
                   const float* __restrict__ x_ball,
                   const int* __restrict__ off, const int* __restrict__ cnt,
                   const int* __restrict__ csr,
                   const float* __restrict__ WB0_rr,
                   const float* __restrict__ WB0_br,
                   const float* __restrict__ WBsum0,
                   const float* __restrict__ bsum0,
                   const float* __restrict__ WB1_rr,
                   const float* __restrict__ WBsum1,
                   float* __restrict__ t_rr,
                   float* __restrict__ f_r) {
    extern __shared__ char smem[];
    const uint32_t AH = smem_u32(smem);
    const uint32_t AL = AH + A_BYTES;
    const uint32_t BB = AL + A_BYTES;

    const int tid  = threadIdx.x;
    const int wid  = tid >> 5;
    const int lane = tid & 31;
    const int wr   = wid & 3;
    const int wcg  = wid >> 2;
    const int row0 = blockIdx.x * 64;
    const int M    = N_ROBOT;

    const int a_row = wr * 16 + ((lane >> 3) & 1) * 8 + (lane & 7);
    const int a_kof = (lane >> 4) * 8;
    const int b_nof = ((lane >> 4) & 1) * 8 + (lane & 7);
    const int b_kof = ((lane >> 3) & 1) * 8;

    float acc[8][4];
#pragma unroll
    for (int o = 0; o < 8; o++)
#pragma unroll
        for (int j = 0; j < 4; j++) acc[o][j] = 0.0f;

    // term 0: mean_rr(x_robot) @ Wl0_rr
    load_A_gather(x_robot, off, cnt, csr, row0, M, AH, AL, wid, lane);
    load_B_pre<128>(WB0_rr, BB, tid);
    __syncthreads();
    mainloop<128>(AH, AL, BB, BB + 34816, acc, a_row, a_kof, b_nof, b_kof, wcg);
    __syncthreads();
    // term 1: mean_br(x_ball) @ Wl0_br
    load_A_gather(x_ball, off + N_ROBOT, cnt + N_ROBOT, csr, row0, M, AH, AL, wid, lane);
    load_B_pre<128>(WB0_br, BB, tid);
    __syncthreads();
    mainloop<128>(AH, AL, BB, BB + 34816, acc, a_row, a_kof, b_nof, b_kof, wcg);
    __syncthreads();
    // term 2: x_robot @ Wsum0
    load_A_direct(x_robot, row0, M, AH, AL, tid);
    load_B_pre<128>(WBsum0, BB, tid);
    __syncthreads();
    mainloop<128>(AH, AL, BB, BB + 34816, acc, a_row, a_kof, b_nof, b_kof, wcg);
    __syncthreads();

    // epilogue 1: bias + relu -> SMEM r tile (bf16 hi/lo)
    {
        const int rAl = wr * 16 + (lane >> 2);
        const int rBl = rAl + 8;
#pragma unroll
        for (int o = 0; o < 8; o++) {
            int col = wcg * 64 + o * 8 + (lane & 3) * 2;
            float2 bv = *(const float2*)(bsum0 + col);
            float v0 = fmaxf(acc[o][0] + bv.x, 0.f);
            float v1 = fmaxf(acc[o][1] + bv.y, 0.f);
            float v2 = fmaxf(acc[o][2] + bv.x, 0.f);
            float v3 = fmaxf(acc[o][3] + bv.y, 0.f);
            uint32_t h, l;
            uint32_t offA = (uint32_t)rAl * STRIDE_B + (uint32_t)col * 2;
            split_pack(v0, v1, h, l);
            asm volatile("st.shared.b32 [%0], %1;" :: "r"(AH + offA), "r"(h) : "memory");
            asm volatile("st.shared.b32 [%0], %1;" :: "r"(AL + offA), "r"(l) : "memory");
            uint32_t offB = (uint32_t)rBl * STRIDE_B + (uint32_t)col * 2;
            split_pack(v2, v3, h, l);
            asm volatile("st.shared.b32 [%0], %1;" :: "r"(AH + offB), "r"(h) : "memory");
            asm volatile("st.shared.b32 [%0], %1;" :: "r"(AL + offB), "r"(l) : "memory");
        }
    }
    // stage 2 B: Wl1_rr (slot 0), Wsum1 (slot 1)
    load_B_pre<64>(WB1_rr, BB, tid);
    load_B_pre<64>(WBsum1, BB + 2 * 17408, tid);
    __syncthreads();

    float acc2a[4][4], acc2b[4][4];
#pragma unroll
    for (int o = 0; o < 4; o++)
#pragma unroll
        for (int j = 0; j < 4; j++) { acc2a[o][j] = 0.f; acc2b[o][j] = 0.f; }

    mainloop<64>(AH, AL, BB,             BB + 17408,     acc2a,
                 a_row, a_kof, b_nof, b_kof, wcg);
    mainloop<64>(AH, AL, BB + 2 * 17408, BB + 3 * 17408, acc2b,
                 a_row, a_kof, b_nof, b_kof, wcg);

    const int rA = row0 + wr * 16 + (lane >> 2);
    const int rB = rA + 8;
#pragma unroll
    for (int o = 0; o < 4; o++) {
        int col = wcg * 32 + o * 8 + (lane & 3) * 2;
        if (rA < M) {
            *(float2*)(t_rr + (size_t)rA * 64 + col) = make_float2(acc2a[o][0], acc2a[o][1]);
            *(float2*)(f_r  + (size_t)rA * 64 + col) = make_float2(acc2b[o][0], acc2b[o][1]);
        }
        if (rB < M) {
            *(float2*)(t_rr + (size_t)rB * 64 + col) = make_float2(acc2a[o][2], acc2a[o][3]);
            *(float2*)(f_r  + (size_t)rB * 64 + col) = make_float2(acc2b[o][2], acc2b[o][3]);
        }
    }
}

// ---------------------------------------------------------------------------
// Fused ball kernel (pre-split weights)
// ---------------------------------------------------------------------------
__global__ void __launch_bounds__(256)
ball_fused_kernel(const float* __restrict__ x_robot,
                  const float* __restrict__ x_ball,
                  const int* __restrict__ off, const int* __restrict__ cnt,
                  const int* __restrict__ csr,
                  const float* __restrict__ WB0_rb,
                  const float* __restrict__ WBr0_rb,
                  const float* __restrict__ b0_rb,
                  const float* __restrict__ WB1_br,
                  float* __restrict__ t_br) {
    extern __shared__ char smem[];
    const uint32_t AH = smem_u32(smem);
    const uint32_t AL = AH + A_BYTES;
    const uint32_t BB = AL + A_BYTES;

    const int tid  = threadIdx.x;
    const int wid  = tid >> 5;
    const int lane = tid & 31;
    const int wr   = wid & 3;
    const int wcg  = wid >> 2;
    const int row0 = blockIdx.x * 64;
    const int M    = N_BALL;

    const int a_row = wr * 16 + ((lane >> 3) & 1) * 8 + (lane & 7);
    const int a_kof = (lane >> 4) * 8;
    const int b_nof = ((lane >> 4) & 1) * 8 + (lane & 7);
    const int b_kof = ((lane >> 3) & 1) * 8;

    float acc[8][4];
#pragma unroll
    for (int o = 0; o < 8; o++)
#pragma unroll
        for (int j = 0; j < 4; j++) acc[o][j] = 0.0f;

    load_A_gather(x_robot, off, cnt, csr, row0, M, AH, AL, wid, lane);
    load_B_pre<128>(WB0_rb, BB, tid);
    __syncthreads();
    mainloop<128>(AH, AL, BB, BB + 34816, acc, a_row, a_kof, b_nof, b_kof, wcg);
    __syncthreads();
    load_A_direct(x_ball, row0, M, AH, AL, tid);
    load_B_pre<128>(WBr0_rb, BB, tid);
    __syncthreads();
    mainloop<128>(AH, AL, BB, BB + 34816, acc, a_row, a_kof, b_nof, b_kof, wcg);
    __syncthreads();

    {
        const int rAl = wr * 16 + (lane >> 2);
        const int rBl = rAl + 8;
#pragma unroll
        for (int o = 0; o < 8; o++) {
            int col = wcg * 64 + o * 8 + (lane & 3) * 2;
            float2 bv = *(const float2*)(b0_rb + col);
            float v0 = fmaxf(acc[o][0] + bv.x, 0.f);
            float v1 = fmaxf(acc[o][1] + bv.y, 0.f);
            float v2 = fmaxf(acc[o][2] + bv.x, 0.f);
            float v3 = fmaxf(acc[o][3] + bv.y, 0.f);
            uint32_t h, l;
            uint32_t offA = (uint32_t)rAl * STRIDE_B + (uint32_t)col * 2;
            split_pack(v0, v1, h, l);
            asm volatile("st.shared.b32 [%0], %1;" :: "r"(AH + offA), "r"(h) : "memory");
            asm volatile("st.shared.b32 [%0], %1;" :: "r"(AL + offA), "r"(l) : "memory");
            uint32_t offB = (uint32_t)rBl * STRIDE_B + (uint32_t)col * 2;
            split_pack(v2, v3, h, l);
            asm volatile("st.shared.b32 [%0], %1;" :: "r"(AH + offB), "r"(h) : "memory");
            asm volatile("st.shared.b32 [%0], %1;" :: "r"(AL + offB), "r"(l) : "memory");
        }
    }
    load_B_pre<64>(WB1_br, BB, tid);
    __syncthreads();

    float acc2[4][4];
#pragma unroll
    for (int o = 0; o < 4; o++)
#pragma unroll
        for (int j = 0; j < 4; j++) acc2[o][j] = 0.f;

    mainloop<64>(AH, AL, BB, BB + 17408, acc2, a_row, a_kof, b_nof, b_kof, wcg);

    const int rA = row0 + wr * 16 + (lane >> 2);
    const int rB = rA + 8;
#pragma unroll
    for (int o = 0; o < 4; o++) {
        int col = wcg * 32 + o * 8 + (lane & 3) * 2;
        if (rA < M)
            *(float2*)(t_br + (size_t)rA * 64 + col) = make_float2(acc2[o][0], acc2[o][1]);
        if (rB < M)
            *(float2*)(t_br + (size_t)rB * 64 + col) = make_float2(acc2[o][2], acc2[o][3]);
    }
}

// ---------------------------------------------------------------------------
// Final: out[d] = mean_rr(t_rr) + mean_br(t_br) + f_r[d] + bsum1
// ---------------------------------------------------------------------------
__global__ void __launch_bounds__(256)
final_kernel(const int* __restrict__ off_rr, const int* __restrict__ cnt_rr,
             const int* __restrict__ off_br, const int* __restrict__ cnt_br,
             const int* __restrict__ csr,
             const float* __restrict__ t_rr, const float* __restrict__ t_br,
             const float* __restrict__ f_r, const float* __restrict__ bsum1,
             float* __restrict__ out) {
    int warp = (blockIdx.x * blockDim.x + threadIdx.x) >> 5;
    int lane = threadIdx.x & 31;
    if (warp >= N_ROBOT) return;

    float2 res = *(const float2*)(f_r + (size_t)warp * 64 + lane * 2);
    float2 bv  = *(const float2*)(bsum1 + lane * 2);
    res.x += bv.x; res.y += bv.y;

    {
        int st = off_rr[warp], dg = cnt_rr[warp];
        float2 a = make_float2(0.f, 0.f);
        int j = 0;
        for (; j + 2 <= dg; j += 2) {
            int s0 = csr[st + j], s1 = csr[st + j + 1];
            float2 v0 = *(const float2*)(t_rr + (size_t)s0 * 64 + lane * 2);
            float2 v1 = *(const float2*)(t_rr + (size_t)s1 * 64 + lane * 2);
            a.x += v0.x + v1.x; a.y += v0.y + v1.y;
        }
        if (j < dg) {
            int s = csr[st + j];
            float2 v = *(const float2*)(t_rr + (size_t)s * 64 + lane * 2);
            a.x += v.x; a.y += v.y;
        }
        float inv = (dg > 0) ? (1.0f / (float)dg) : 0.0f;
        res.x += a.x * inv; res.y += a.y * inv;
    }
    {
        int st = off_br[warp], dg = cnt_br[warp];
        float2 a = make_float2(0.f, 0.f);
        int j = 0;
        for (; j + 2 <= dg; j += 2) {
            int s0 = csr[st + j], s1 = csr[st + j + 1];
            float2 v0 = *(const float2*)(t_br + (size_t)s0 * 64 + lane * 2);
            float2 v1 = *(const float2*)(t_br + (size_t)s1 * 64 + lane * 2);
            a.x += v0.x + v1.x; a.y += v0.y + v1.y;
        }
        if (j < dg) {
            int s = csr[st + j];
            float2 v = *(const float2*)(t_br + (size_t)s * 64 + lane * 2);
            a.x += v.x; a.y += v.y;
        }
        float inv = (dg > 0) ? (1.0f / (float)dg) : 0.0f;
        res.x += a.x * inv; res.y += a.y * inv;
    }
    *(float2*)(out + (size_t)warp * 64 + lane * 2) = res;
}

// ---------------------------------------------------------------------------
// Launch
// ---------------------------------------------------------------------------
extern "C" void kernel_launch(void* const* d_in, const int* in_sizes, int n_in,
                              void* d_out, int out_size) {
    (void)n_in; (void)out_size;

    const float* x_robot = (const float*)d_in[0];
    const float* x_ball  = (const float*)d_in[1];
    const int* ei_rr = (const int*)d_in[2];
    const int* ei_rb = (const int*)d_in[3];
    const int* ei_br = (const int*)d_in[4];
    const float* Wl0_rr = (const float*)d_in[5];
    const float* Wr0_rr = (const float*)d_in[6];
    const float* b0_rr  = (const float*)d_in[7];
    const float* Wl0_rb = (const float*)d_in[8];
    const float* Wr0_rb = (const float*)d_in[9];
    const float* b0_rb  = (const float*)d_in[10];
    const float* Wl0_br = (const float*)d_in[11];
    const float* Wr0_br = (const float*)d_in[12];
    const float* b0_br  = (const float*)d_in[13];
    const float* Wl1_rr = (const float*)d_in[14];
    const float* Wr1_rr = (const float*)d_in[15];
    const float* b1_rr  = (const float*)d_in[16];
    const float* Wl1_br = (const float*)d_in[20];
    const float* Wr1_br = (const float*)d_in[21];
    const float* b1_br  = (const float*)d_in[22];

    float* out = (float*)d_out;
    const int E = in_sizes[2] / 2;

    float* S = nullptr;
    int *C = nullptr, *OFF = nullptr, *CUR = nullptr, *CSR = nullptr, *BS = nullptr;
    {
        void* p = nullptr;
        cudaGetSymbolAddress(&p, g_scratch); S = (float*)p;
        cudaGetSymbolAddress(&p, g_cnt);     C = (int*)p;
        cudaGetSymbolAddress(&p, g_off);     OFF = (int*)p;
        cudaGetSymbolAddress(&p, g_cursor);  CUR = (int*)p;
        cudaGetSymbolAddress(&p, g_csr);     CSR = (int*)p;
        cudaGetSymbolAddress(&p, g_bsum);    BS = (int*)p;
    }

    float* t_rr    = S + O_TRR;
    float* t_br    = S + O_TBR;
    float* f_r     = S + O_FR;
    float* bsum0   = S + O_BSUM0;
    float* bsum1   = S + O_BSUM1;
    float* WB0_rr  = S + O_WB0_RR;
    float* WB0_br  = S + O_WB0_BR;
    float* WBsum0  = S + O_WBSUM0;
    float* WB0_rb  = S + O_WB0_RB;
    float* WBr0_rb = S + O_WBR0_RB;
    float* WB1_rr  = S + O_WB1_RR;
    float* WBsum1  = S + O_WBSUM1;
    float* WB1_br  = S + O_WB1_BR;

    cudaFuncSetAttribute(robot_fused_kernel,
                         cudaFuncAttributeMaxDynamicSharedMemorySize, SMEM_TOTAL);
    cudaFuncSetAttribute(ball_fused_kernel,
                         cudaFuncAttributeMaxDynamicSharedMemorySize, SMEM_TOTAL);

    // ---- counts ----
    cudaMemsetAsync(C, 0, 3ull * N_ROBOT * sizeof(int), 0);
    const int cb = (E + 255) / 256;
    count_kernel<<<cb, 256>>>(ei_rr + E, C, E);
    count_kernel<<<cb, 256>>>(ei_br + E, C + N_ROBOT, E);
    count_kernel<<<cb, 256>>>(ei_rb + E, C + 2 * N_ROBOT, E);

    // ---- CSR build ----
    scan1_kernel<<<SCAN_NB, SCAN_BS>>>(C, OFF, BS);
    scan2_kernel<<<1, 1024>>>(BS);
    scan3_kernel<<<SCAN_NB, SCAN_BS>>>(OFF, BS, CUR);
    fill_csr_kernel<<<cb, 256>>>(ei_rr, ei_rr + E, CUR, CSR, E, 0);
    fill_csr_kernel<<<cb, 256>>>(ei_br, ei_br + E, CUR, CSR, E, N_ROBOT);
    fill_csr_kernel<<<cb, 256>>>(ei_rb, ei_rb + E, CUR, CSR, E, 2 * N_ROBOT);

    // ---- one-time weight split (+ folds) ----
    splitw_kernel<128, false><<<64, 256>>>(Wl0_rr, nullptr, WB0_rr);
    splitw_kernel<128, false><<<64, 256>>>(Wl0_br, nullptr, WB0_br);
    splitw_kernel<128, true ><<<64, 256>>>(Wr0_rr, Wr0_br, WBsum0);
    splitw_kernel<128, false><<<64, 256>>>(Wl0_rb, nullptr, WB0_rb);
    splitw_kernel<128, false><<<64, 256>>>(Wr0_rb, nullptr, WBr0_rb);
    splitw_kernel<64,  false><<<32, 256>>>(Wl1_rr, nullptr, WB1_rr);
    splitw_kernel<64,  true ><<<32, 256>>>(Wr1_rr, Wr1_br, WBsum1);
    splitw_kernel<64,  false><<<32, 256>>>(Wl1_br, nullptr, WB1_br);

    // ---- bias folds ----
    add2_kernel<<<1, 128>>>(b0_rr, b0_br, bsum0, 128);
    add2_kernel<<<1, 64>>>(b1_rr, b1_br, bsum1, 64);

    // ---- fused compute ----
    const int gb = (N_ROBOT + 63) / 64;  // 1563
    robot_fused_kernel<<<gb, 256, SMEM_TOTAL>>>(
        x_robot, x_ball, OFF, C, CSR,
        WB0_rr, WB0_br, WBsum0, bsum0, WB1_rr, WBsum1, t_rr, f_r);
    ball_fused_kernel<<<gb, 256, SMEM_TOTAL>>>(
        x_robot, x_ball, OFF + 2 * N_ROBOT, C + 2 * N_ROBOT, CSR,
        WB0_rb, WBr0_rb, b0_rb, WB1_br, t_br);

    // ---- final combine ----
    const int fb = (N_ROBOT * 32 + 255) / 256;
    final_kernel<<<fb, 256>>>(OFF, C, OFF + N_ROBOT, C + N_ROBOT, CSR,
                              t_rr, t_br, f_r, bsum1, out);
}

// round 9
// speedup vs baseline: 3.0088x; 1.2044x over previous
#include <cuda_runtime.h>
#include <cuda_bf16.h>
#include <stdint.h>

// ---------------------------------------------------------------------------
// Problem constants
// ---------------------------------------------------------------------------
#define N_ROBOT 100000
#define N_BALL  100000
#define E_MAX   600000

// ---------------------------------------------------------------------------
// Scratch (device globals; allocation is forbidden)
// ---------------------------------------------------------------------------
#define O_TRR     0ull                            // [100000*64]
#define O_TBR     (O_TRR + 6400000ull)
#define O_FR      (O_TBR + 6400000ull)
#define O_BSUM0   (O_FR  + 6400000ull)            // 128
#define O_BSUM1   (O_BSUM0 + 128ull)              // 64
#define O_WB0_RR  (O_BSUM1 + 64ull)               // 17408 floats each (N=128)
#define O_WB0_BR  (O_WB0_RR + 17408ull)
#define O_WBSUM0  (O_WB0_BR + 17408ull)
#define O_WB0_RB  (O_WBSUM0 + 17408ull)
#define O_WBR0_RB (O_WB0_RB + 17408ull)
#define O_WB1_RR  (O_WBR0_RB + 17408ull)          // 8704 each (N=64)
#define O_WBSUM1  (O_WB1_RR + 8704ull)
#define O_WB1_BR  (O_WBSUM1 + 8704ull)
#define SCRATCH_FLOATS (O_WB1_BR + 8704ull)

__device__ float g_scratch[SCRATCH_FLOATS];
__device__ int   g_cnt[3 * N_ROBOT];
__device__ int   g_off[3 * N_ROBOT];
__device__ int   g_cursor[3 * N_ROBOT];
__device__ int   g_csr[3 * E_MAX + 64];
__device__ int   g_bsum[1024];

#define NSCAN   (3 * N_ROBOT)
#define SCAN_BS 512
#define SCAN_NB ((NSCAN + SCAN_BS - 1) / SCAN_BS)

// ---------------------------------------------------------------------------
// Helpers (baseline PTX only — harness targets compute_103 w/o 'a').
// ---------------------------------------------------------------------------
__device__ __forceinline__ uint32_t smem_u32(const void* p) {
    uint32_t a;
    asm("{ .reg .u64 t; cvta.to.shared.u64 t, %1; cvt.u32.u64 %0, t; }"
        : "=r"(a) : "l"(p));
    return a;
}

#define LDSM_X4(r0, r1, r2, r3, addr) \
    asm volatile("ldmatrix.sync.aligned.m8n8.x4.shared.b16 {%0,%1,%2,%3}, [%4];" \
                 : "=r"(r0), "=r"(r1), "=r"(r2), "=r"(r3) : "r"(addr))

__device__ __forceinline__ void mma_bf16(float* c, const uint32_t* a,
                                         uint32_t b0, uint32_t b1) {
    asm volatile(
        "mma.sync.aligned.m16n8k16.row.col.f32.bf16.bf16.f32 "
        "{%0,%1,%2,%3}, {%4,%5,%6,%7}, {%8,%9}, {%0,%1,%2,%3};"
        : "+f"(c[0]), "+f"(c[1]), "+f"(c[2]), "+f"(c[3])
        : "r"(a[0]), "r"(a[1]), "r"(a[2]), "r"(a[3]), "r"(b0), "r"(b1));
}

__device__ __forceinline__ void split_pack(float x0, float x1,
                                           uint32_t& hp, uint32_t& lp) {
    __nv_bfloat16 h0 = __float2bfloat16(x0);
    __nv_bfloat16 h1 = __float2bfloat16(x1);
    __nv_bfloat16 l0 = __float2bfloat16(x0 - __bfloat162float(h0));
    __nv_bfloat16 l1 = __float2bfloat16(x1 - __bfloat162float(h1));
    hp = ((uint32_t)__bfloat16_as_ushort(h1) << 16) | __bfloat16_as_ushort(h0);
    lp = ((uint32_t)__bfloat16_as_ushort(l1) << 16) | __bfloat16_as_ushort(l0);
}

// SMEM layout constants
#define STRIDE_B 272u
#define A_BYTES  17408u
#define SMEM_TOTAL (2 * 17408 + 69632)   // 104448

// ---------------------------------------------------------------------------
// Stage loaders + mainloop
// ---------------------------------------------------------------------------
__device__ __forceinline__ void store_a_pair(uint32_t AH, uint32_t AL,
                                             uint32_t off, const float4& v) {
    uint32_t h01, l01, h23, l23;
    split_pack(v.x, v.y, h01, l01);
    split_pack(v.z, v.w, h23, l23);
    asm volatile("st.shared.v2.b32 [%0], {%1,%2};"
                 :: "r"(AH + off), "r"(h01), "r"(h23) : "memory");
    asm volatile("st.shared.v2.b32 [%0], {%1,%2};"
                 :: "r"(AL + off), "r"(l01), "r"(l23) : "memory");
}

__device__ __forceinline__ void load_A_direct(const float* __restrict__ A,
                                              int row0, int M,
                                              uint32_t AH, uint32_t AL, int tid) {
#pragma unroll
    for (int i = 0; i < 8; i++) {
        int idx = tid + i * 256;
        int r  = idx >> 5;
        int c4 = idx & 31;
        float4 v = make_float4(0.f, 0.f, 0.f, 0.f);
        if (row0 + r < M)
            v = *(const float4*)(A + (size_t)(row0 + r) * 128 + c4 * 4);
        store_a_pair(AH, AL, (uint32_t)r * STRIDE_B + (uint32_t)c4 * 8, v);
    }
}

// CSR mean-gather, 4-wide unrolled neighbor loop for MLP.
__device__ __forceinline__ void load_A_gather(const float* __restrict__ x,
                                              const int* __restrict__ off,
                                              const int* __restrict__ cnt,
                                              const int* __restrict__ csr,
                                              int row0, int M,
                                              uint32_t AH, uint32_t AL,
                                              int wid, int lane) {
#pragma unroll
    for (int i = 0; i < 8; i++) {
        int r  = wid + i * 8;
        int gr = row0 + r;
        float4 a = make_float4(0.f, 0.f, 0.f, 0.f);
        if (gr < M) {
            int st = off[gr];
            int dg = cnt[gr];
            int j = 0;
            for (; j + 4 <= dg; j += 4) {
                int s0 = csr[st + j];
                int s1 = csr[st + j + 1];
                int s2 = csr[st + j + 2];
                int s3 = csr[st + j + 3];
                float4 v0 = *(const float4*)(x + (size_t)s0 * 128 + lane * 4);
                float4 v1 = *(const float4*)(x + (size_t)s1 * 128 + lane * 4);
                float4 v2 = *(const float4*)(x + (size_t)s2 * 128 + lane * 4);
                float4 v3 = *(const float4*)(x + (size_t)s3 * 128 + lane * 4);
                a.x += (v0.x + v1.x) + (v2.x + v3.x);
                a.y += (v0.y + v1.y) + (v2.y + v3.y);
                a.z += (v0.z + v1.z) + (v2.z + v3.z);
                a.w += (v0.w + v1.w) + (v2.w + v3.w);
            }
            if (j + 2 <= dg) {
                int s0 = csr[st + j];
                int s1 = csr[st + j + 1];
                float4 v0 = *(const float4*)(x + (size_t)s0 * 128 + lane * 4);
                float4 v1 = *(const float4*)(x + (size_t)s1 * 128 + lane * 4);
                a.x += v0.x + v1.x; a.y += v0.y + v1.y;
                a.z += v0.z + v1.z; a.w += v0.w + v1.w;
                j += 2;
            }
            if (j < dg) {
                int s = csr[st + j];
                float4 v = *(const float4*)(x + (size_t)s * 128 + lane * 4);
                a.x += v.x; a.y += v.y; a.z += v.z; a.w += v.w;
            }
            float inv = (dg > 0) ? (1.0f / (float)dg) : 0.0f;
            a.x *= inv; a.y *= inv; a.z *= inv; a.w *= inv;
        }
        store_a_pair(AH, AL, (uint32_t)r * STRIDE_B + (uint32_t)lane * 8, a);
    }
}

// B tile copy via cp.async (issue-only; caller waits before the sync).
template <int N>
__device__ __forceinline__ void load_B_async(const float* __restrict__ src,
                                             uint32_t BB, int tid) {
    constexpr int T4 = (2 * N * 136 * 2) / 16;   // 34*N float4s
#pragma unroll
    for (int i = tid; i < T4; i += 256) {
        asm volatile("cp.async.cg.shared.global [%0], [%1], 16;"
                     :: "r"(BB + (uint32_t)i * 16), "l"(src + (size_t)i * 4)
                     : "memory");
    }
}
__device__ __forceinline__ void cp_commit() {
    asm volatile("cp.async.commit_group;" ::: "memory");
}
__device__ __forceinline__ void cp_wait_all() {
    asm volatile("cp.async.wait_group 0;" ::: "memory");
}

template <int N>
__device__ __forceinline__ void mainloop(uint32_t AH, uint32_t AL,
                                         uint32_t BH, uint32_t BL,
                                         float (*acc)[4],
                                         int a_row, int a_kof,
                                         int b_nof, int b_kof, int wcg) {
    constexpr int NOCT = N / 16;
#pragma unroll
    for (int k0 = 0; k0 < 128; k0 += 16) {
        uint32_t ah[4], al[4];
        uint32_t aoff = (uint32_t)a_row * STRIDE_B + (uint32_t)(k0 + a_kof) * 2;
        LDSM_X4(ah[0], ah[1], ah[2], ah[3], AH + aoff);
        LDSM_X4(al[0], al[1], al[2], al[3], AL + aoff);
#pragma unroll
        for (int op = 0; op < NOCT; op += 2) {
            int nbase = wcg * (N / 2) + op * 8;
            uint32_t boff = (uint32_t)(nbase + b_nof) * STRIDE_B
                          + (uint32_t)(k0 + b_kof) * 2;
            uint32_t bh0, bh1, bh2, bh3, bl0, bl1, bl2, bl3;
            LDSM_X4(bh0, bh1, bh2, bh3, BH + boff);
            LDSM_X4(bl0, bl1, bl2, bl3, BL + boff);
            mma_bf16(acc[op],     ah, bh0, bh1);
            mma_bf16(acc[op],     al, bh0, bh1);
            mma_bf16(acc[op],     ah, bl0, bl1);
            mma_bf16(acc[op + 1], ah, bh2, bh3);
            mma_bf16(acc[op + 1], al, bh2, bh3);
            mma_bf16(acc[op + 1], ah, bl2, bl3);
        }
    }
}

// ---------------------------------------------------------------------------
// Small kernels
// ---------------------------------------------------------------------------
__global__ void count3_kernel(const int* __restrict__ d0,
                              const int* __restrict__ d1,
                              const int* __restrict__ d2,
                              int* __restrict__ cnt, int E) {
    int i = blockIdx.x * blockDim.x + threadIdx.x;
    if (i < E) atomicAdd(&cnt[d0[i]], 1);
    else if (i < 2 * E) atomicAdd(&cnt[N_ROBOT + d1[i - E]], 1);
    else if (i < 3 * E) atomicAdd(&cnt[2 * N_ROBOT + d2[i - 2 * E]], 1);
}

__global__ void fill3_csr_kernel(const int* __restrict__ s0, const int* __restrict__ d0,
                                 const int* __restrict__ s1, const int* __restrict__ d1,
                                 const int* __restrict__ s2, const int* __restrict__ d2,
                                 int* __restrict__ cursor,
                                 int* __restrict__ csr, int E) {
    int i = blockIdx.x * blockDim.x + threadIdx.x;
    int pos;
    if (i < E) {
        pos = atomicAdd(&cursor[d0[i]], 1);
        csr[pos] = s0[i];
    } else if (i < 2 * E) {
        pos = atomicAdd(&cursor[N_ROBOT + d1[i - E]], 1);
        csr[pos] = s1[i - E];
    } else if (i < 3 * E) {
        pos = atomicAdd(&cursor[2 * N_ROBOT + d2[i - 2 * E]], 1);
        csr[pos] = s2[i - 2 * E];
    }
}

__global__ void add2_kernel(const float* __restrict__ a,
                            const float* __restrict__ b,
                            float* __restrict__ o, int n) {
    int i = blockIdx.x * blockDim.x + threadIdx.x;
    if (i < n) o[i] = a[i] + b[i];
}

template <int N, bool FOLD>
__global__ void splitw_kernel(const float* __restrict__ A,
                              const float* __restrict__ B2,
                              float* __restrict__ outf) {
    int e = blockIdx.x * blockDim.x + threadIdx.x;
    if (e >= 128 * N) return;
    int k = e / N;
    int n = e - k * N;
    float w = A[e];
    if (FOLD) w += B2[e];
    __nv_bfloat16 h = __float2bfloat16(w);
    __nv_bfloat16 l = __float2bfloat16(w - __bfloat162float(h));
    __nv_bfloat16* out = (__nv_bfloat16*)outf;
    out[n * 136 + k] = h;
    out[N * 136 + n * 136 + k] = l;
}

__global__ void scan1_kernel(const int* __restrict__ cnt,
                             int* __restrict__ out, int* __restrict__ bsum) {
    __shared__ int sh[SCAN_BS];
    int gid = blockIdx.x * SCAN_BS + threadIdx.x;
    int v = (gid < NSCAN) ? cnt[gid] : 0;
    sh[threadIdx.x] = v;
    __syncthreads();
#pragma unroll
    for (int d = 1; d < SCAN_BS; d <<= 1) {
        int t = (threadIdx.x >= d) ? sh[threadIdx.x - d] : 0;
        __syncthreads();
        sh[threadIdx.x] += t;
        __syncthreads();
    }
    if (gid < NSCAN) out[gid] = sh[threadIdx.x] - v;
    if (threadIdx.x == SCAN_BS - 1) bsum[blockIdx.x] = sh[threadIdx.x];
}

__global__ void scan2_kernel(int* __restrict__ bsum) {
    __shared__ int sh[1024];
    int i = threadIdx.x;
    int v = (i < SCAN_NB) ? bsum[i] : 0;
    sh[i] = v;
    __syncthreads();
#pragma unroll
    for (int d = 1; d < 1024; d <<= 1) {
        int t = (i >= d) ? sh[i - d] : 0;
        __syncthreads();
        sh[i] += t;
        __syncthreads();
    }
    if (i < SCAN_NB) bsum[i] = sh[i] - v;
}

__global__ void scan3_kernel(int* __restrict__ out, const int* __restrict__ bsum,
                             int* __restrict__ cursor) {
    int gid = blockIdx.x * SCAN_BS + threadIdx.x;
    if (gid < NSCAN) {
        int o = out[gid] + bsum[blockIdx.x];
        out[gid] = o;
        cursor[gid] = o;
    }
}

// ---------------------------------------------------------------------------
// Fused robot kernel
// ---------------------------------------------------------------------------
__global__ void __launch_bounds__(256, 2)
robot_fused_kernel(const float* __restrict__ x_robot,
                   const float* __restrict__ x_ball,
                   const int* __restrict__ off, const int* __restrict__ cnt,
                   const int* __restrict__ csr,
                   const float* __restrict__ WB0_rr,
                   const float* __restrict__ WB0_br,
                   const float* __restrict__ WBsum0,
                   const float* __restrict__ bsum0,
                   const float* __restrict__ WB1_rr,
                   const float* __restrict__ WBsum1,
                   float* __restrict__ t_rr,
                   float* __restrict__ f_r) {
    extern __shared__ char smem[];
    const uint32_t AH = smem_u32(smem);
    const uint32_t AL = AH + A_BYTES;
    const uint32_t BB = AL + A_BYTES;

    const int tid  = threadIdx.x;
    const int wid  = tid >> 5;
    const int lane = tid & 31;
    const int wr   = wid & 3;
    const int wcg  = wid >> 2;
    const int row0 = blockIdx.x * 64;
    const int M    = N_ROBOT;

    const int a_row = wr * 16 + ((lane >> 3) & 1) * 8 + (lane & 7);
    const int a_kof = (lane >> 4) * 8;
    const int b_nof = ((lane >> 4) & 1) * 8 + (lane & 7);
    const int b_kof = ((lane >> 3) & 1) * 8;

    float acc[8][4];
#pragma unroll
    for (int o = 0; o < 8; o++)
#pragma unroll
        for (int j = 0; j < 4; j++) acc[o][j] = 0.0f;

    // term 0
    load_B_async<128>(WB0_rr, BB, tid);
    cp_commit();
    load_A_gather(x_robot, off, cnt, csr, row0, M, AH, AL, wid, lane);
    cp_wait_all();
    __syncthreads();
    mainloop<128>(AH, AL, BB, BB + 34816, acc, a_row, a_kof, b_nof, b_kof, wcg);
    __syncthreads();
    // term 1
    load_B_async<128>(WB0_br, BB, tid);
    cp_commit();
    load_A_gather(x_ball, off + N_ROBOT, cnt + N_ROBOT, csr, row0, M, AH, AL, wid, lane);
    cp_wait_all();
    __syncthreads();
    mainloop<128>(AH, AL, BB, BB + 34816, acc, a_row, a_kof, b_nof, b_kof, wcg);
    __syncthreads();
    // term 2
    load_B_async<128>(WBsum0, BB, tid);
    cp_commit();
    load_A_direct(x_robot, row0, M, AH, AL, tid);
    cp_wait_all();
    __syncthreads();
    mainloop<128>(AH, AL, BB, BB + 34816, acc, a_row, a_kof, b_nof, b_kof, wcg);
    __syncthreads();

    // stage-2 B copies overlap epilogue-1
    load_B_async<64>(WB1_rr, BB, tid);
    load_B_async<64>(WBsum1, BB + 2 * 17408, tid);
    cp_commit();

    // epilogue 1: bias + relu -> SMEM r tile (bf16 hi/lo)
    {
        const int rAl = wr * 16 + (lane >> 2);
        const int rBl = rAl + 8;
#pragma unroll
        for (int o = 0; o < 8; o++) {
            int col = wcg * 64 + o * 8 + (lane & 3) * 2;
            float2 bv = *(const float2*)(bsum0 + col);
            float v0 = fmaxf(acc[o][0] + bv.x, 0.f);
            float v1 = fmaxf(acc[o][1] + bv.y, 0.f);
            float v2 = fmaxf(acc[o][2] + bv.x, 0.f);
            float v3 = fmaxf(acc[o][3] + bv.y, 0.f);
            uint32_t h, l;
            uint32_t offA = (uint32_t)rAl * STRIDE_B + (uint32_t)col * 2;
            split_pack(v0, v1, h, l);
            asm volatile("st.shared.b32 [%0], %1;" :: "r"(AH + offA), "r"(h) : "memory");
            asm volatile("st.shared.b32 [%0], %1;" :: "r"(AL + offA), "r"(l) : "memory");
            uint32_t offB = (uint32_t)rBl * STRIDE_B + (uint32_t)col * 2;
            split_pack(v2, v3, h, l);
            asm volatile("st.shared.b32 [%0], %1;" :: "r"(AH + offB), "r"(h) : "memory");
            asm volatile("st.shared.b32 [%0], %1;" :: "r"(AL + offB), "r"(l) : "memory");
        }
    }
    cp_wait_all();
    __syncthreads();

    float acc2a[4][4], acc2b[4][4];
#pragma unroll
    for (int o = 0; o < 4; o++)
#pragma unroll
        for (int j = 0; j < 4; j++) { acc2a[o][j] = 0.f; acc2b[o][j] = 0.f; }

    mainloop<64>(AH, AL, BB,             BB + 17408,     acc2a,
                 a_row, a_kof, b_nof, b_kof, wcg);
    mainloop<64>(AH, AL, BB + 2 * 17408, BB + 3 * 17408, acc2b,
                 a_row, a_kof, b_nof, b_kof, wcg);

    const int rA = row0 + wr * 16 + (lane >> 2);
    const int rB = rA + 8;
#pragma unroll
    for (int o = 0; o < 4; o++) {
        int col = wcg * 32 + o * 8 + (lane & 3) * 2;
        if (rA < M) {
            *(float2*)(t_rr + (size_t)rA * 64 + col) = make_float2(acc2a[o][0], acc2a[o][1]);
            *(float2*)(f_r  + (size_t)rA * 64 + col) = make_float2(acc2b[o][0], acc2b[o][1]);
        }
        if (rB < M) {
            *(float2*)(t_rr + (size_t)rB * 64 + col) = make_float2(acc2a[o][2], acc2a[o][3]);
            *(float2*)(f_r  + (size_t)rB * 64 + col) = make_float2(acc2b[o][2], acc2b[o][3]);
        }
    }
}

// ---------------------------------------------------------------------------
// Fused ball kernel
// ---------------------------------------------------------------------------
__global__ void __launch_bounds__(256, 2)
ball_fused_kernel(const float* __restrict__ x_robot,
                  const float* __restrict__ x_ball,
                  const int* __restrict__ off, const int* __restrict__ cnt,
                  const int* __restrict__ csr,
                  const float* __restrict__ WB0_rb,
                  const float* __restrict__ WBr0_rb,
                  const float* __restrict__ b0_rb,
                  const float* __restrict__ WB1_br,
                  float* __restrict__ t_br) {
    extern __shared__ char smem[];
    const uint32_t AH = smem_u32(smem);
    const uint32_t AL = AH + A_BYTES;
    const uint32_t BB = AL + A_BYTES;

    const int tid  = threadIdx.x;
    const int wid  = tid >> 5;
    const int lane = tid & 31;
    const int wr   = wid & 3;
    const int wcg  = wid >> 2;
    const int row0 = blockIdx.x * 64;
    const int M    = N_BALL;

    const int a_row = wr * 16 + ((lane >> 3) & 1) * 8 + (lane & 7);
    const int a_kof = (lane >> 4) * 8;
    const int b_nof = ((lane >> 4) & 1) * 8 + (lane & 7);
    const int b_kof = ((lane >> 3) & 1) * 8;

    float acc[8][4];
#pragma unroll
    for (int o = 0; o < 8; o++)
#pragma unroll
        for (int j = 0; j < 4; j++) acc[o][j] = 0.0f;

    load_B_async<128>(WB0_rb, BB, tid);
    cp_commit();
    load_A_gather(x_robot, off, cnt, csr, row0, M, AH, AL, wid, lane);
    cp_wait_all();
    __syncthreads();
    mainloop<128>(AH, AL, BB, BB + 34816, acc, a_row, a_kof, b_nof, b_kof, wcg);
    __syncthreads();
    load_B_async<128>(WBr0_rb, BB, tid);
    cp_commit();
    load_A_direct(x_ball, row0, M, AH, AL, tid);
    cp_wait_all();
    __syncthreads();
    mainloop<128>(AH, AL, BB, BB + 34816, acc, a_row, a_kof, b_nof, b_kof, wcg);
    __syncthreads();

    load_B_async<64>(WB1_br, BB, tid);
    cp_commit();
    {
        const int rAl = wr * 16 + (lane >> 2);
        const int rBl = rAl + 8;
#pragma unroll
        for (int o = 0; o < 8; o++) {
            int col = wcg * 64 + o * 8 + (lane & 3) * 2;
            float2 bv = *(const float2*)(b0_rb + col);
            float v0 = fmaxf(acc[o][0] + bv.x, 0.f);
            float v1 = fmaxf(acc[o][1] + bv.y, 0.f);
            float v2 = fmaxf(acc[o][2] + bv.x, 0.f);
            float v3 = fmaxf(acc[o][3] + bv.y, 0.f);
            uint32_t h, l;
            uint32_t offA = (uint32_t)rAl * STRIDE_B + (uint32_t)col * 2;
            split_pack(v0, v1, h, l);
            asm volatile("st.shared.b32 [%0], %1;" :: "r"(AH + offA), "r"(h) : "memory");
            asm volatile("st.shared.b32 [%0], %1;" :: "r"(AL + offA), "r"(l) : "memory");
            uint32_t offB = (uint32_t)rBl * STRIDE_B + (uint32_t)col * 2;
            split_pack(v2, v3, h, l);
            asm volatile("st.shared.b32 [%0], %1;" :: "r"(AH + offB), "r"(h) : "memory");
            asm volatile("st.shared.b32 [%0], %1;" :: "r"(AL + offB), "r"(l) : "memory");
        }
    }
    cp_wait_all();
    __syncthreads();

    float acc2[4][4];
#pragma unroll
    for (int o = 0; o < 4; o++)
#pragma unroll
        for (int j = 0; j < 4; j++) acc2[o][j] = 0.f;

    mainloop<64>(AH, AL, BB, BB + 17408, acc2, a_row, a_kof, b_nof, b_kof, wcg);

    const int rA = row0 + wr * 16 + (lane >> 2);
    const int rB = rA + 8;
#pragma unroll
    for (int o = 0; o < 4; o++) {
        int col = wcg * 32 + o * 8 + (lane & 3) * 2;
        if (rA < M)
            *(float2*)(t_br + (size_t)rA * 64 + col) = make_float2(acc2[o][0], acc2[o][1]);
        if (rB < M)
            *(float2*)(t_br + (size_t)rB * 64 + col) = make_float2(acc2[o][2], acc2[o][3]);
    }
}

// ---------------------------------------------------------------------------
// Final: out[d] = mean_rr(t_rr) + mean_br(t_br) + f_r[d] + bsum1
// ---------------------------------------------------------------------------
__device__ __forceinline__ void gather_mean64(const int* __restrict__ off,
                                              const int* __restrict__ cnt,
                                              const int* __restrict__ csr,
                                              const float* __restrict__ t,
                                              int warp, int lane, float2& res) {
    int st = off[warp], dg = cnt[warp];
    float2 a = make_float2(0.f, 0.f);
    int j = 0;
    for (; j + 4 <= dg; j += 4) {
        int s0 = csr[st + j], s1 = csr[st + j + 1];
        int s2 = csr[st + j + 2], s3 = csr[st + j + 3];
        float2 v0 = *(const float2*)(t + (size_t)s0 * 64 + lane * 2);
        float2 v1 = *(const float2*)(t + (size_t)s1 * 64 + lane * 2);
        float2 v2 = *(const float2*)(t + (size_t)s2 * 64 + lane * 2);
        float2 v3 = *(const float2*)(t + (size_t)s3 * 64 + lane * 2);
        a.x += (v0.x + v1.x) + (v2.x + v3.x);
        a.y += (v0.y + v1.y) + (v2.y + v3.y);
    }
    if (j + 2 <= dg) {
        int s0 = csr[st + j], s1 = csr[st + j + 1];
        float2 v0 = *(const float2*)(t + (size_t)s0 * 64 + lane * 2);
        float2 v1 = *(const float2*)(t + (size_t)s1 * 64 + lane * 2);
        a.x += v0.x + v1.x; a.y += v0.y + v1.y;
        j += 2;
    }
    if (j < dg) {
        int s = csr[st + j];
        float2 v = *(const float2*)(t + (size_t)s * 64 + lane * 2);
        a.x += v.x; a.y += v.y;
    }
    float inv = (dg > 0) ? (1.0f / (float)dg) : 0.0f;
    res.x += a.x * inv; res.y += a.y * inv;
}

__global__ void __launch_bounds__(256)
final_kernel(const int* __restrict__ off_rr, const int* __restrict__ cnt_rr,
             const int* __restrict__ off_br, const int* __restrict__ cnt_br,
             const int* __restrict__ csr,
             const float* __restrict__ t_rr, const float* __restrict__ t_br,
             const float* __restrict__ f_r, const float* __restrict__ bsum1,
             float* __restrict__ out) {
    int warp = (blockIdx.x * blockDim.x + threadIdx.x) >> 5;
    int lane = threadIdx.x & 31;
    if (warp >= N_ROBOT) return;

    float2 res = *(const float2*)(f_r + (size_t)warp * 64 + lane * 2);
    float2 bv  = *(const float2*)(bsum1 + lane * 2);
    res.x += bv.x; res.y += bv.y;

    gather_mean64(off_rr, cnt_rr, csr, t_rr, warp, lane, res);
    gather_mean64(off_br, cnt_br, csr, t_br, warp, lane, res);

    *(float2*)(out + (size_t)warp * 64 + lane * 2) = res;
}

// ---------------------------------------------------------------------------
// Launch
// ---------------------------------------------------------------------------
extern "C" void kernel_launch(void* const* d_in, const int* in_sizes, int n_in,
                              void* d_out, int out_size) {
    (void)n_in; (void)out_size;

    const float* x_robot = (const float*)d_in[0];
    const float* x_ball  = (const float*)d_in[1];
    const int* ei_rr = (const int*)d_in[2];
    const int* ei_rb = (const int*)d_in[3];
    const int* ei_br = (const int*)d_in[4];
    const float* Wl0_rr = (const float*)d_in[5];
    const float* Wr0_rr = (const float*)d_in[6];
    const float* b0_rr  = (const float*)d_in[7];
    const float* Wl0_rb = (const float*)d_in[8];
    const float* Wr0_rb = (const float*)d_in[9];
    const float* b0_rb  = (const float*)d_in[10];
    const float* Wl0_br = (const float*)d_in[11];
    const float* Wr0_br = (const float*)d_in[12];
    const float* b0_br  = (const float*)d_in[13];
    const float* Wl1_rr = (const float*)d_in[14];
    const float* Wr1_rr = (const float*)d_in[15];
    const float* b1_rr  = (const float*)d_in[16];
    const float* Wl1_br = (const float*)d_in[20];
    const float* Wr1_br = (const float*)d_in[21];
    const float* b1_br  = (const float*)d_in[22];

    float* out = (float*)d_out;
    const int E = in_sizes[2] / 2;

    float* S = nullptr;
    int *C = nullptr, *OFF = nullptr, *CUR = nullptr, *CSR = nullptr, *BS = nullptr;
    {
        void* p = nullptr;
        cudaGetSymbolAddress(&p, g_scratch); S = (float*)p;
        cudaGetSymbolAddress(&p, g_cnt);     C = (int*)p;
        cudaGetSymbolAddress(&p, g_off);     OFF = (int*)p;
        cudaGetSymbolAddress(&p, g_cursor);  CUR = (int*)p;
        cudaGetSymbolAddress(&p, g_csr);     CSR = (int*)p;
        cudaGetSymbolAddress(&p, g_bsum);    BS = (int*)p;
    }

    float* t_rr    = S + O_TRR;
    float* t_br    = S + O_TBR;
    float* f_r     = S + O_FR;
    float* bsum0   = S + O_BSUM0;
    float* bsum1   = S + O_BSUM1;
    float* WB0_rr  = S + O_WB0_RR;
    float* WB0_br  = S + O_WB0_BR;
    float* WBsum0  = S + O_WBSUM0;
    float* WB0_rb  = S + O_WB0_RB;
    float* WBr0_rb = S + O_WBR0_RB;
    float* WB1_rr  = S + O_WB1_RR;
    float* WBsum1  = S + O_WBSUM1;
    float* WB1_br  = S + O_WB1_BR;

    cudaFuncSetAttribute(robot_fused_kernel,
                         cudaFuncAttributeMaxDynamicSharedMemorySize, SMEM_TOTAL);
    cudaFuncSetAttribute(ball_fused_kernel,
                         cudaFuncAttributeMaxDynamicSharedMemorySize, SMEM_TOTAL);

    // ---- counts (fused) ----
    cudaMemsetAsync(C, 0, 3ull * N_ROBOT * sizeof(int), 0);
    const int cb3 = (3 * E + 255) / 256;
    count3_kernel<<<cb3, 256>>>(ei_rr + E, ei_br + E, ei_rb + E, C, E);

    // ---- CSR build ----
    scan1_kernel<<<SCAN_NB, SCAN_BS>>>(C, OFF, BS);
    scan2_kernel<<<1, 1024>>>(BS);
    scan3_kernel<<<SCAN_NB, SCAN_BS>>>(OFF, BS, CUR);
    fill3_csr_kernel<<<cb3, 256>>>(ei_rr, ei_rr + E, ei_br, ei_br + E,
                                   ei_rb, ei_rb + E, CUR, CSR, E);

    // ---- one-time weight split (+ folds) ----
    splitw_kernel<128, false><<<64, 256>>>(Wl0_rr, nullptr, WB0_rr);
    splitw_kernel<128, false><<<64, 256>>>(Wl0_br, nullptr, WB0_br);
    splitw_kernel<128, true ><<<64, 256>>>(Wr0_rr, Wr0_br, WBsum0);
    splitw_kernel<128, false><<<64, 256>>>(Wl0_rb, nullptr, WB0_rb);
    splitw_kernel<128, false><<<64, 256>>>(Wr0_rb, nullptr, WBr0_rb);
    splitw_kernel<64,  false><<<32, 256>>>(Wl1_rr, nullptr, WB1_rr);
    splitw_kernel<64,  true ><<<32, 256>>>(Wr1_rr, Wr1_br, WBsum1);
    splitw_kernel<64,  false><<<32, 256>>>(Wl1_br, nullptr, WB1_br);

    // ---- bias folds ----
    add2_kernel<<<1, 128>>>(b0_rr, b0_br, bsum0, 128);
    add2_kernel<<<1, 64>>>(b1_rr, b1_br, bsum1, 64);

    // ---- fused compute ----
    const int gb = (N_ROBOT + 63) / 64;  // 1563
    robot_fused_kernel<<<gb, 256, SMEM_TOTAL>>>(
        x_robot, x_ball, OFF, C, CSR,
        WB0_rr, WB0_br, WBsum0, bsum0, WB1_rr, WBsum1, t_rr, f_r);
    ball_fused_kernel<<<gb, 256, SMEM_TOTAL>>>(
        x_robot, x_ball, OFF + 2 * N_ROBOT, C + 2 * N_ROBOT, CSR,
        WB0_rb, WBr0_rb, b0_rb, WB1_br, t_br);

    // ---- final combine ----
    const int fb = (N_ROBOT * 32 + 255) / 256;
    final_kernel<<<fb, 256>>>(OFF, C, OFF + N_ROBOT, C + N_ROBOT, CSR,
                              t_rr, t_br, f_r, bsum1, out);
}

// round 10
// speedup vs baseline: 3.3861x; 1.1254x over previous
#include <cuda_runtime.h>
#include <cuda_bf16.h>
#include <stdint.h>

// ---------------------------------------------------------------------------
// Problem constants
// ---------------------------------------------------------------------------
#define N_ROBOT 100000
#define N_BALL  100000
#define E_MAX   600000
#define GB_ROBOT ((N_ROBOT + 63) / 64)   // 1563
#define GB_BALL  ((N_BALL + 63) / 64)    // 1563

// ---------------------------------------------------------------------------
// Scratch (device globals; allocation is forbidden)
// ---------------------------------------------------------------------------
#define O_TRR     0ull
#define O_TBR     (O_TRR + 6400000ull)
#define O_FR      (O_TBR + 6400000ull)
#define O_BSUM0   (O_FR  + 6400000ull)
#define O_BSUM1   (O_BSUM0 + 128ull)
#define O_WB0_RR  (O_BSUM1 + 64ull)
#define O_WB0_BR  (O_WB0_RR + 17408ull)
#define O_WBSUM0  (O_WB0_BR + 17408ull)
#define O_WB0_RB  (O_WBSUM0 + 17408ull)
#define O_WBR0_RB (O_WB0_RB + 17408ull)
#define O_WB1_RR  (O_WBR0_RB + 17408ull)
#define O_WBSUM1  (O_WB1_RR + 8704ull)
#define O_WB1_BR  (O_WBSUM1 + 8704ull)
#define SCRATCH_FLOATS (O_WB1_BR + 8704ull)

__device__ float g_scratch[SCRATCH_FLOATS];
__device__ int   g_cnt[3 * N_ROBOT];
__device__ int   g_off[3 * N_ROBOT];
__device__ int   g_cursor[3 * N_ROBOT];
__device__ int   g_csr[3 * E_MAX + 64];
__device__ int   g_bsum[1024];

#define NSCAN   (3 * N_ROBOT)
#define SCAN_BS 512
#define SCAN_NB ((NSCAN + SCAN_BS - 1) / SCAN_BS)

// ---------------------------------------------------------------------------
// Helpers (baseline PTX only)
// ---------------------------------------------------------------------------
__device__ __forceinline__ uint32_t smem_u32(const void* p) {
    uint32_t a;
    asm("{ .reg .u64 t; cvta.to.shared.u64 t, %1; cvt.u32.u64 %0, t; }"
        : "=r"(a) : "l"(p));
    return a;
}

#define LDSM_X4(r0, r1, r2, r3, addr) \
    asm volatile("ldmatrix.sync.aligned.m8n8.x4.shared.b16 {%0,%1,%2,%3}, [%4];" \
                 : "=r"(r0), "=r"(r1), "=r"(r2), "=r"(r3) : "r"(addr))

__device__ __forceinline__ void mma_bf16(float* c, const uint32_t* a,
                                         uint32_t b0, uint32_t b1) {
    asm volatile(
        "mma.sync.aligned.m16n8k16.row.col.f32.bf16.bf16.f32 "
        "{%0,%1,%2,%3}, {%4,%5,%6,%7}, {%8,%9}, {%0,%1,%2,%3};"
        : "+f"(c[0]), "+f"(c[1]), "+f"(c[2]), "+f"(c[3])
        : "r"(a[0]), "r"(a[1]), "r"(a[2]), "r"(a[3]), "r"(b0), "r"(b1));
}

__device__ __forceinline__ void split_pack(float x0, float x1,
                                           uint32_t& hp, uint32_t& lp) {
    __nv_bfloat16 h0 = __float2bfloat16(x0);
    __nv_bfloat16 h1 = __float2bfloat16(x1);
    __nv_bfloat16 l0 = __float2bfloat16(x0 - __bfloat162float(h0));
    __nv_bfloat16 l1 = __float2bfloat16(x1 - __bfloat162float(h1));
    hp = ((uint32_t)__bfloat16_as_ushort(h1) << 16) | __bfloat16_as_ushort(h0);
    lp = ((uint32_t)__bfloat16_as_ushort(l1) << 16) | __bfloat16_as_ushort(l0);
}

#define STRIDE_B 272u
#define A_BYTES  17408u
#define SMEM_TOTAL (2 * 17408 + 69632)   // 104448

// ---------------------------------------------------------------------------
// Stage loaders + mainloop
// ---------------------------------------------------------------------------
__device__ __forceinline__ void store_a_pair(uint32_t AH, uint32_t AL,
                                             uint32_t off, const float4& v) {
    uint32_t h01, l01, h23, l23;
    split_pack(v.x, v.y, h01, l01);
    split_pack(v.z, v.w, h23, l23);
    asm volatile("st.shared.v2.b32 [%0], {%1,%2};"
                 :: "r"(AH + off), "r"(h01), "r"(h23) : "memory");
    asm volatile("st.shared.v2.b32 [%0], {%1,%2};"
                 :: "r"(AL + off), "r"(l01), "r"(l23) : "memory");
}

__device__ __forceinline__ void load_A_direct(const float* __restrict__ A,
                                              int row0, int M,
                                              uint32_t AH, uint32_t AL, int tid) {
#pragma unroll
    for (int i = 0; i < 8; i++) {
        int idx = tid + i * 256;
        int r  = idx >> 5;
        int c4 = idx & 31;
        float4 v = make_float4(0.f, 0.f, 0.f, 0.f);
        if (row0 + r < M)
            v = *(const float4*)(A + (size_t)(row0 + r) * 128 + c4 * 4);
        store_a_pair(AH, AL, (uint32_t)r * STRIDE_B + (uint32_t)c4 * 8, v);
    }
}

__device__ __forceinline__ void load_A_gather(const float* __restrict__ x,
                                              const int* __restrict__ off,
                                              const int* __restrict__ cnt,
                                              const int* __restrict__ csr,
                                              int row0, int M,
                                              uint32_t AH, uint32_t AL,
                                              int wid, int lane) {
#pragma unroll
    for (int i = 0; i < 8; i++) {
        int r  = wid + i * 8;
        int gr = row0 + r;
        float4 a = make_float4(0.f, 0.f, 0.f, 0.f);
        if (gr < M) {
            int st = off[gr];
            int dg = cnt[gr];
            int j = 0;
            for (; j + 4 <= dg; j += 4) {
                int s0 = csr[st + j];
                int s1 = csr[st + j + 1];
                int s2 = csr[st + j + 2];
                int s3 = csr[st + j + 3];
                float4 v0 = *(const float4*)(x + (size_t)s0 * 128 + lane * 4);
                float4 v1 = *(const float4*)(x + (size_t)s1 * 128 + lane * 4);
                float4 v2 = *(const float4*)(x + (size_t)s2 * 128 + lane * 4);
                float4 v3 = *(const float4*)(x + (size_t)s3 * 128 + lane * 4);
                a.x += (v0.x + v1.x) + (v2.x + v3.x);
                a.y += (v0.y + v1.y) + (v2.y + v3.y);
                a.z += (v0.z + v1.z) + (v2.z + v3.z);
                a.w += (v0.w + v1.w) + (v2.w + v3.w);
            }
            if (j + 2 <= dg) {
                int s0 = csr[st + j];
                int s1 = csr[st + j + 1];
                float4 v0 = *(const float4*)(x + (size_t)s0 * 128 + lane * 4);
                float4 v1 = *(const float4*)(x + (size_t)s1 * 128 + lane * 4);
                a.x += v0.x + v1.x; a.y += v0.y + v1.y;
                a.z += v0.z + v1.z; a.w += v0.w + v1.w;
                j += 2;
            }
            if (j < dg) {
                int s = csr[st + j];
                float4 v = *(const float4*)(x + (size_t)s * 128 + lane * 4);
                a.x += v.x; a.y += v.y; a.z += v.z; a.w += v.w;
            }
            float inv = (dg > 0) ? (1.0f / (float)dg) : 0.0f;
            a.x *= inv; a.y *= inv; a.z *= inv; a.w *= inv;
        }
        store_a_pair(AH, AL, (uint32_t)r * STRIDE_B + (uint32_t)lane * 8, a);
    }
}

template <int N>
__device__ __forceinline__ void load_B_async(const float* __restrict__ src,
                                             uint32_t BB, int tid) {
    constexpr int T4 = (2 * N * 136 * 2) / 16;
#pragma unroll
    for (int i = tid; i < T4; i += 256) {
        asm volatile("cp.async.cg.shared.global [%0], [%1], 16;"
                     :: "r"(BB + (uint32_t)i * 16), "l"(src + (size_t)i * 4)
                     : "memory");
    }
}
__device__ __forceinline__ void cp_commit() {
    asm volatile("cp.async.commit_group;" ::: "memory");
}
__device__ __forceinline__ void cp_wait_all() {
    asm volatile("cp.async.wait_group 0;" ::: "memory");
}

template <int N>
__device__ __forceinline__ void mainloop(uint32_t AH, uint32_t AL,
                                         uint32_t BH, uint32_t BL,
                                         float (*acc)[4],
                                         int a_row, int a_kof,
                                         int b_nof, int b_kof, int wcg) {
    constexpr int NOCT = N / 16;
#pragma unroll
    for (int k0 = 0; k0 < 128; k0 += 16) {
        uint32_t ah[4], al[4];
        uint32_t aoff = (uint32_t)a_row * STRIDE_B + (uint32_t)(k0 + a_kof) * 2;
        LDSM_X4(ah[0], ah[1], ah[2], ah[3], AH + aoff);
        LDSM_X4(al[0], al[1], al[2], al[3], AL + aoff);
#pragma unroll
        for (int op = 0; op < NOCT; op += 2) {
            int nbase = wcg * (N / 2) + op * 8;
            uint32_t boff = (uint32_t)(nbase + b_nof) * STRIDE_B
                          + (uint32_t)(k0 + b_kof) * 2;
            uint32_t bh0, bh1, bh2, bh3, bl0, bl1, bl2, bl3;
            LDSM_X4(bh0, bh1, bh2, bh3, BH + boff);
            LDSM_X4(bl0, bl1, bl2, bl3, BL + boff);
            mma_bf16(acc[op],     ah, bh0, bh1);
            mma_bf16(acc[op],     al, bh0, bh1);
            mma_bf16(acc[op],     ah, bl0, bl1);
            mma_bf16(acc[op + 1], ah, bh2, bh3);
            mma_bf16(acc[op + 1], al, bh2, bh3);
            mma_bf16(acc[op + 1], ah, bl2, bl3);
        }
    }
}

// ---------------------------------------------------------------------------
// Small kernels: counts / CSR build
// ---------------------------------------------------------------------------
__global__ void count3_kernel(const int* __restrict__ d0,
                              const int* __restrict__ d1,
                              const int* __restrict__ d2,
                              int* __restrict__ cnt, int E) {
    int i = blockIdx.x * blockDim.x + threadIdx.x;
    if (i < E) atomicAdd(&cnt[d0[i]], 1);
    else if (i < 2 * E) atomicAdd(&cnt[N_ROBOT + d1[i - E]], 1);
    else if (i < 3 * E) atomicAdd(&cnt[2 * N_ROBOT + d2[i - 2 * E]], 1);
}

__global__ void fill3_csr_kernel(const int* __restrict__ s0, const int* __restrict__ d0,
                                 const int* __restrict__ s1, const int* __restrict__ d1,
                                 const int* __restrict__ s2, const int* __restrict__ d2,
                                 int* __restrict__ cursor,
                                 int* __restrict__ csr, int E) {
    int i = blockIdx.x * blockDim.x + threadIdx.x;
    int pos;
    if (i < E) {
        pos = atomicAdd(&cursor[d0[i]], 1);
        csr[pos] = s0[i];
    } else if (i < 2 * E) {
        pos = atomicAdd(&cursor[N_ROBOT + d1[i - E]], 1);
        csr[pos] = s1[i - E];
    } else if (i < 3 * E) {
        pos = atomicAdd(&cursor[2 * N_ROBOT + d2[i - 2 * E]], 1);
        csr[pos] = s2[i - 2 * E];
    }
}

__global__ void scan1_kernel(const int* __restrict__ cnt,
                             int* __restrict__ out, int* __restrict__ bsum) {
    __shared__ int sh[SCAN_BS];
    int gid = blockIdx.x * SCAN_BS + threadIdx.x;
    int v = (gid < NSCAN) ? cnt[gid] : 0;
    sh[threadIdx.x] = v;
    __syncthreads();
#pragma unroll
    for (int d = 1; d < SCAN_BS; d <<= 1) {
        int t = (threadIdx.x >= d) ? sh[threadIdx.x - d] : 0;
        __syncthreads();
        sh[threadIdx.x] += t;
        __syncthreads();
    }
    if (gid < NSCAN) out[gid] = sh[threadIdx.x] - v;
    if (threadIdx.x == SCAN_BS - 1) bsum[blockIdx.x] = sh[threadIdx.x];
}

__global__ void scan2_kernel(int* __restrict__ bsum) {
    __shared__ int sh[1024];
    int i = threadIdx.x;
    int v = (i < SCAN_NB) ? bsum[i] : 0;
    sh[i] = v;
    __syncthreads();
#pragma unroll
    for (int d = 1; d < 1024; d <<= 1) {
        int t = (i >= d) ? sh[i - d] : 0;
        __syncthreads();
        sh[i] += t;
        __syncthreads();
    }
    if (i < SCAN_NB) bsum[i] = sh[i] - v;
}

__global__ void scan3_kernel(int* __restrict__ out, const int* __restrict__ bsum,
                             int* __restrict__ cursor) {
    int gid = blockIdx.x * SCAN_BS + threadIdx.x;
    if (gid < NSCAN) {
        int o = out[gid] + bsum[blockIdx.x];
        out[gid] = o;
        cursor[gid] = o;
    }
}

// ---------------------------------------------------------------------------
// Unified prep kernel: 8 weight splits + 2 bias folds in ONE launch.
// Blocks 0..319   : five N=128 splits (64 blocks each)
// Blocks 320..415 : three N=64 splits (32 blocks each)
// Block  416      : bias folds
// ---------------------------------------------------------------------------
__device__ __forceinline__ void split_one(const float* __restrict__ A,
                                          const float* __restrict__ B2,
                                          float* __restrict__ outf,
                                          int N, int e) {
    if (e >= 128 * N) return;
    int k = e / N;
    int n = e - k * N;
    float w = A[e];
    if (B2) w += B2[e];
    __nv_bfloat16 h = __float2bfloat16(w);
    __nv_bfloat16 l = __float2bfloat16(w - __bfloat162float(h));
    __nv_bfloat16* out = (__nv_bfloat16*)outf;
    out[n * 136 + k] = h;
    out[(size_t)N * 136 + n * 136 + k] = l;
}

__global__ void prep_kernel(const float* __restrict__ Wl0_rr,
                            const float* __restrict__ Wl0_br,
                            const float* __restrict__ Wr0_rr,
                            const float* __restrict__ Wr0_br,
                            const float* __restrict__ Wl0_rb,
                            const float* __restrict__ Wr0_rb,
                            const float* __restrict__ Wl1_rr,
                            const float* __restrict__ Wr1_rr,
                            const float* __restrict__ Wr1_br,
                            const float* __restrict__ Wl1_br,
                            const float* __restrict__ b0_rr,
                            const float* __restrict__ b0_br,
                            const float* __restrict__ b1_rr,
                            const float* __restrict__ b1_br,
                            float* __restrict__ WB0_rr,
                            float* __restrict__ WB0_br,
                            float* __restrict__ WBsum0,
                            float* __restrict__ WB0_rb,
                            float* __restrict__ WBr0_rb,
                            float* __restrict__ WB1_rr,
                            float* __restrict__ WBsum1,
                            float* __restrict__ WB1_br,
                            float* __restrict__ bsum0,
                            float* __restrict__ bsum1) {
    int b = blockIdx.x;
    int t = threadIdx.x;
    if (b < 320) {
        int seg = b >> 6;                       // 0..4
        int e = (b & 63) * 256 + t;             // 0..16383
        switch (seg) {
            case 0: split_one(Wl0_rr, nullptr, WB0_rr, 128, e); break;
            case 1: split_one(Wl0_br, nullptr, WB0_br, 128, e); break;
            case 2: split_one(Wr0_rr, Wr0_br, WBsum0, 128, e); break;
            case 3: split_one(Wl0_rb, nullptr, WB0_rb, 128, e); break;
            default: split_one(Wr0_rb, nullptr, WBr0_rb, 128, e); break;
        }
    } else if (b < 416) {
        int seg = (b - 320) >> 5;               // 0..2
        int e = ((b - 320) & 31) * 256 + t;     // 0..8191
        switch (seg) {
            case 0: split_one(Wl1_rr, nullptr, WB1_rr, 64, e); break;
            case 1: split_one(Wr1_rr, Wr1_br, WBsum1, 64, e); break;
            default: split_one(Wl1_br, nullptr, WB1_br, 64, e); break;
        }
    } else {
        if (t < 128) bsum0[t] = b0_rr[t] + b0_br[t];
        else if (t < 192) bsum1[t - 128] = b1_rr[t - 128] + b1_br[t - 128];
    }
}

// ---------------------------------------------------------------------------
// Unified fused GEMM kernel: blocks [0, GB_ROBOT) = robot path,
// blocks [GB_ROBOT, GB_ROBOT+GB_BALL) = ball path.
// ---------------------------------------------------------------------------
__global__ void __launch_bounds__(256, 2)
fused_kernel(const float* __restrict__ x_robot,
             const float* __restrict__ x_ball,
             const int* __restrict__ off, const int* __restrict__ cnt,
             const int* __restrict__ csr,
             const float* __restrict__ WB0_rr,
             const float* __restrict__ WB0_br,
             const float* __restrict__ WBsum0,
             const float* __restrict__ bsum0,
             const float* __restrict__ WB1_rr,
             const float* __restrict__ WBsum1,
             const float* __restrict__ WB0_rb,
             const float* __restrict__ WBr0_rb,
             const float* __restrict__ b0_rb,
             const float* __restrict__ WB1_br,
             float* __restrict__ t_rr,
             float* __restrict__ f_r,
             float* __restrict__ t_br) {
    extern __shared__ char smem[];
    const uint32_t AH = smem_u32(smem);
    const uint32_t AL = AH + A_BYTES;
    const uint32_t BB = AL + A_BYTES;

    const int tid  = threadIdx.x;
    const int wid  = tid >> 5;
    const int lane = tid & 31;
    const int wr   = wid & 3;
    const int wcg  = wid >> 2;

    const int a_row = wr * 16 + ((lane >> 3) & 1) * 8 + (lane & 7);
    const int a_kof = (lane >> 4) * 8;
    const int b_nof = ((lane >> 4) & 1) * 8 + (lane & 7);
    const int b_kof = ((lane >> 3) & 1) * 8;

    float acc[8][4];
#pragma unroll
    for (int o = 0; o < 8; o++)
#pragma unroll
        for (int j = 0; j < 4; j++) acc[o][j] = 0.0f;

    const bool robot = (blockIdx.x < GB_ROBOT);

    if (robot) {
        const int row0 = blockIdx.x * 64;
        const int M    = N_ROBOT;

        // term 0: mean_rr(x_robot) @ Wl0_rr
        load_B_async<128>(WB0_rr, BB, tid);
        cp_commit();
        load_A_gather(x_robot, off, cnt, csr, row0, M, AH, AL, wid, lane);
        cp_wait_all();
        __syncthreads();
        mainloop<128>(AH, AL, BB, BB + 34816, acc, a_row, a_kof, b_nof, b_kof, wcg);
        __syncthreads();
        // term 1: mean_br(x_ball) @ Wl0_br
        load_B_async<128>(WB0_br, BB, tid);
        cp_commit();
        load_A_gather(x_ball, off + N_ROBOT, cnt + N_ROBOT, csr, row0, M, AH, AL, wid, lane);
        cp_wait_all();
        __syncthreads();
        mainloop<128>(AH, AL, BB, BB + 34816, acc, a_row, a_kof, b_nof, b_kof, wcg);
        __syncthreads();
        // term 2: x_robot @ Wsum0
        load_B_async<128>(WBsum0, BB, tid);
        cp_commit();
        load_A_direct(x_robot, row0, M, AH, AL, tid);
        cp_wait_all();
        __syncthreads();
        mainloop<128>(AH, AL, BB, BB + 34816, acc, a_row, a_kof, b_nof, b_kof, wcg);
        __syncthreads();

        // stage-2 B copies overlap epilogue-1
        load_B_async<64>(WB1_rr, BB, tid);
        load_B_async<64>(WBsum1, BB + 2 * 17408, tid);
        cp_commit();

        {
            const int rAl = wr * 16 + (lane >> 2);
            const int rBl = rAl + 8;
#pragma unroll
            for (int o = 0; o < 8; o++) {
                int col = wcg * 64 + o * 8 + (lane & 3) * 2;
                float2 bv = *(const float2*)(bsum0 + col);
                float v0 = fmaxf(acc[o][0] + bv.x, 0.f);
                float v1 = fmaxf(acc[o][1] + bv.y, 0.f);
                float v2 = fmaxf(acc[o][2] + bv.x, 0.f);
                float v3 = fmaxf(acc[o][3] + bv.y, 0.f);
                uint32_t h, l;
                uint32_t offA = (uint32_t)rAl * STRIDE_B + (uint32_t)col * 2;
                split_pack(v0, v1, h, l);
                asm volatile("st.shared.b32 [%0], %1;" :: "r"(AH + offA), "r"(h) : "memory");
                asm volatile("st.shared.b32 [%0], %1;" :: "r"(AL + offA), "r"(l) : "memory");
                uint32_t offB = (uint32_t)rBl * STRIDE_B + (uint32_t)col * 2;
                split_pack(v2, v3, h, l);
                asm volatile("st.shared.b32 [%0], %1;" :: "r"(AH + offB), "r"(h) : "memory");
                asm volatile("st.shared.b32 [%0], %1;" :: "r"(AL + offB), "r"(l) : "memory");
            }
        }
        cp_wait_all();
        __syncthreads();

        float acc2a[4][4], acc2b[4][4];
#pragma unroll
        for (int o = 0; o < 4; o++)
#pragma unroll
            for (int j = 0; j < 4; j++) { acc2a[o][j] = 0.f; acc2b[o][j] = 0.f; }

        mainloop<64>(AH, AL, BB,             BB + 17408,     acc2a,
                     a_row, a_kof, b_nof, b_kof, wcg);
        mainloop<64>(AH, AL, BB + 2 * 17408, BB + 3 * 17408, acc2b,
                     a_row, a_kof, b_nof, b_kof, wcg);

        const int rA = row0 + wr * 16 + (lane >> 2);
        const int rB = rA + 8;
#pragma unroll
        for (int o = 0; o < 4; o++) {
            int col = wcg * 32 + o * 8 + (lane & 3) * 2;
            if (rA < M) {
                *(float2*)(t_rr + (size_t)rA * 64 + col) = make_float2(acc2a[o][0], acc2a[o][1]);
                *(float2*)(f_r  + (size_t)rA * 64 + col) = make_float2(acc2b[o][0], acc2b[o][1]);
            }
            if (rB < M) {
                *(float2*)(t_rr + (size_t)rB * 64 + col) = make_float2(acc2a[o][2], acc2a[o][3]);
                *(float2*)(f_r  + (size_t)rB * 64 + col) = make_float2(acc2b[o][2], acc2b[o][3]);
            }
        }
    } else {
        const int row0 = (blockIdx.x - GB_ROBOT) * 64;
        const int M    = N_BALL;

        load_B_async<128>(WB0_rb, BB, tid);
        cp_commit();
        load_A_gather(x_robot, off + 2 * N_ROBOT, cnt + 2 * N_ROBOT, csr,
                      row0, M, AH, AL, wid, lane);
        cp_wait_all();
        __syncthreads();
        mainloop<128>(AH, AL, BB, BB + 34816, acc, a_row, a_kof, b_nof, b_kof, wcg);
        __syncthreads();
        load_B_async<128>(WBr0_rb, BB, tid);
        cp_commit();
        load_A_direct(x_ball, row0, M, AH, AL, tid);
        cp_wait_all();
        __syncthreads();
        mainloop<128>(AH, AL, BB, BB + 34816, acc, a_row, a_kof, b_nof, b_kof, wcg);
        __syncthreads();

        load_B_async<64>(WB1_br, BB, tid);
        cp_commit();
        {
            const int rAl = wr * 16 + (lane >> 2);
            const int rBl = rAl + 8;
#pragma unroll
            for (int o = 0; o < 8; o++) {
                int col = wcg * 64 + o * 8 + (lane & 3) * 2;
                float2 bv = *(const float2*)(b0_rb + col);
                float v0 = fmaxf(acc[o][0] + bv.x, 0.f);
                float v1 = fmaxf(acc[o][1] + bv.y, 0.f);
                float v2 = fmaxf(acc[o][2] + bv.x, 0.f);
                float v3 = fmaxf(acc[o][3] + bv.y, 0.f);
                uint32_t h, l;
                uint32_t offA = (uint32_t)rAl * STRIDE_B + (uint32_t)col * 2;
                split_pack(v0, v1, h, l);
                asm volatile("st.shared.b32 [%0], %1;" :: "r"(AH + offA), "r"(h) : "memory");
                asm volatile("st.shared.b32 [%0], %1;" :: "r"(AL + offA), "r"(l) : "memory");
                uint32_t offB = (uint32_t)rBl * STRIDE_B + (uint32_t)col * 2;
                split_pack(v2, v3, h, l);
                asm volatile("st.shared.b32 [%0], %1;" :: "r"(AH + offB), "r"(h) : "memory");
                asm volatile("st.shared.b32 [%0], %1;" :: "r"(AL + offB), "r"(l) : "memory");
            }
        }
        cp_wait_all();
        __syncthreads();

        float acc2[4][4];
#pragma unroll
        for (int o = 0; o < 4; o++)
#pragma unroll
            for (int j = 0; j < 4; j++) acc2[o][j] = 0.f;

        mainloop<64>(AH, AL, BB, BB + 17408, acc2, a_row, a_kof, b_nof, b_kof, wcg);

        const int rA = row0 + wr * 16 + (lane >> 2);
        const int rB = rA + 8;
#pragma unroll
        for (int o = 0; o < 4; o++) {
            int col = wcg * 32 + o * 8 + (lane & 3) * 2;
            if (rA < M)
                *(float2*)(t_br + (size_t)rA * 64 + col) = make_float2(acc2[o][0], acc2[o][1]);
            if (rB < M)
                *(float2*)(t_br + (size_t)rB * 64 + col) = make_float2(acc2[o][2], acc2[o][3]);
        }
    }
}

// ---------------------------------------------------------------------------
// Final: out[d] = mean_rr(t_rr) + mean_br(t_br) + f_r[d] + bsum1
// ---------------------------------------------------------------------------
__device__ __forceinline__ void gather_mean64(const int* __restrict__ off,
                                              const int* __restrict__ cnt,
                                              const int* __restrict__ csr,
                                              const float* __restrict__ t,
                                              int warp, int lane, float2& res) {
    int st = off[warp], dg = cnt[warp];
    float2 a = make_float2(0.f, 0.f);
    int j = 0;
    for (; j + 4 <= dg; j += 4) {
        int s0 = csr[st + j], s1 = csr[st + j + 1];
        int s2 = csr[st + j + 2], s3 = csr[st + j + 3];
        float2 v0 = *(const float2*)(t + (size_t)s0 * 64 + lane * 2);
        float2 v1 = *(const float2*)(t + (size_t)s1 * 64 + lane * 2);
        float2 v2 = *(const float2*)(t + (size_t)s2 * 64 + lane * 2);
        float2 v3 = *(const float2*)(t + (size_t)s3 * 64 + lane * 2);
        a.x += (v0.x + v1.x) + (v2.x + v3.x);
        a.y += (v0.y + v1.y) + (v2.y + v3.y);
    }
    if (j + 2 <= dg) {
        int s0 = csr[st + j], s1 = csr[st + j + 1];
        float2 v0 = *(const float2*)(t + (size_t)s0 * 64 + lane * 2);
        float2 v1 = *(const float2*)(t + (size_t)s1 * 64 + lane * 2);
        a.x += v0.x + v1.x; a.y += v0.y + v1.y;
        j += 2;
    }
    if (j < dg) {
        int s = csr[st + j];
        float2 v = *(const float2*)(t + (size_t)s * 64 + lane * 2);
        a.x += v.x; a.y += v.y;
    }
    float inv = (dg > 0) ? (1.0f / (float)dg) : 0.0f;
    res.x += a.x * inv; res.y += a.y * inv;
}

__global__ void __launch_bounds__(256)
final_kernel(const int* __restrict__ off_rr, const int* __restrict__ cnt_rr,
             const int* __restrict__ off_br, const int* __restrict__ cnt_br,
             const int* __restrict__ csr,
             const float* __restrict__ t_rr, const float* __restrict__ t_br,
             const float* __restrict__ f_r, const float* __restrict__ bsum1,
             float* __restrict__ out) {
    int warp = (blockIdx.x * blockDim.x + threadIdx.x) >> 5;
    int lane = threadIdx.x & 31;
    if (warp >= N_ROBOT) return;

    float2 res = *(const float2*)(f_r + (size_t)warp * 64 + lane * 2);
    float2 bv  = *(const float2*)(bsum1 + lane * 2);
    res.x += bv.x; res.y += bv.y;

    gather_mean64(off_rr, cnt_rr, csr, t_rr, warp, lane, res);
    gather_mean64(off_br, cnt_br, csr, t_br, warp, lane, res);

    *(float2*)(out + (size_t)warp * 64 + lane * 2) = res;
}

// ---------------------------------------------------------------------------
// Launch
// ---------------------------------------------------------------------------
extern "C" void kernel_launch(void* const* d_in, const int* in_sizes, int n_in,
                              void* d_out, int out_size) {
    (void)n_in; (void)out_size;

    const float* x_robot = (const float*)d_in[0];
    const float* x_ball  = (const float*)d_in[1];
    const int* ei_rr = (const int*)d_in[2];
    const int* ei_rb = (const int*)d_in[3];
    const int* ei_br = (const int*)d_in[4];
    const float* Wl0_rr = (const float*)d_in[5];
    const float* Wr0_rr = (const float*)d_in[6];
    const float* b0_rr  = (const float*)d_in[7];
    const float* Wl0_rb = (const float*)d_in[8];
    const float* Wr0_rb = (const float*)d_in[9];
    const float* b0_rb  = (const float*)d_in[10];
    const float* Wl0_br = (const float*)d_in[11];
    const float* Wr0_br = (const float*)d_in[12];
    const float* b0_br  = (const float*)d_in[13];
    const float* Wl1_rr = (const float*)d_in[14];
    const float* Wr1_rr = (const float*)d_in[15];
    const float* b1_rr  = (const float*)d_in[16];
    const float* Wl1_br = (const float*)d_in[20];
    const float* Wr1_br = (const float*)d_in[21];
    const float* b1_br  = (const float*)d_in[22];

    float* out = (float*)d_out;
    const int E = in_sizes[2] / 2;

    float* S = nullptr;
    int *C = nullptr, *OFF = nullptr, *CUR = nullptr, *CSR = nullptr, *BS = nullptr;
    {
        void* p = nullptr;
        cudaGetSymbolAddress(&p, g_scratch); S = (float*)p;
        cudaGetSymbolAddress(&p, g_cnt);     C = (int*)p;
        cudaGetSymbolAddress(&p, g_off);     OFF = (int*)p;
        cudaGetSymbolAddress(&p, g_cursor);  CUR = (int*)p;
        cudaGetSymbolAddress(&p, g_csr);     CSR = (int*)p;
        cudaGetSymbolAddress(&p, g_bsum);    BS = (int*)p;
    }

    float* t_rr    = S + O_TRR;
    float* t_br    = S + O_TBR;
    float* f_r     = S + O_FR;
    float* bsum0   = S + O_BSUM0;
    float* bsum1   = S + O_BSUM1;
    float* WB0_rr  = S + O_WB0_RR;
    float* WB0_br  = S + O_WB0_BR;
    float* WBsum0  = S + O_WBSUM0;
    float* WB0_rb  = S + O_WB0_RB;
    float* WBr0_rb = S + O_WBR0_RB;
    float* WB1_rr  = S + O_WB1_RR;
    float* WBsum1  = S + O_WBSUM1;
    float* WB1_br  = S + O_WB1_BR;

    cudaFuncSetAttribute(fused_kernel,
                         cudaFuncAttributeMaxDynamicSharedMemorySize, SMEM_TOTAL);

    // ---- counts ----
    cudaMemsetAsync(C, 0, 3ull * N_ROBOT * sizeof(int), 0);
    const int cb3 = (3 * E + 255) / 256;
    count3_kernel<<<cb3, 256>>>(ei_rr + E, ei_br + E, ei_rb + E, C, E);

    // ---- CSR build ----
    scan1_kernel<<<SCAN_NB, SCAN_BS>>>(C, OFF, BS);
    scan2_kernel<<<1, 1024>>>(BS);
    scan3_kernel<<<SCAN_NB, SCAN_BS>>>(OFF, BS, CUR);
    fill3_csr_kernel<<<cb3, 256>>>(ei_rr, ei_rr + E, ei_br, ei_br + E,
                                   ei_rb, ei_rb + E, CUR, CSR, E);

    // ---- unified weight/bias prep (1 launch) ----
    prep_kernel<<<417, 256>>>(Wl0_rr, Wl0_br, Wr0_rr, Wr0_br, Wl0_rb, Wr0_rb,
                              Wl1_rr, Wr1_rr, Wr1_br, Wl1_br,
                              b0_rr, b0_br, b1_rr, b1_br,
                              WB0_rr, WB0_br, WBsum0, WB0_rb, WBr0_rb,
                              WB1_rr, WBsum1, WB1_br, bsum0, bsum1);

    // ---- unified fused compute (robot + ball in one grid) ----
    fused_kernel<<<GB_ROBOT + GB_BALL, 256, SMEM_TOTAL>>>(
        x_robot, x_ball, OFF, C, CSR,
        WB0_rr, WB0_br, WBsum0, bsum0, WB1_rr, WBsum1,
        WB0_rb, WBr0_rb, b0_rb, WB1_br,
        t_rr, f_r, t_br);

    // ---- final combine ----
    const int fb = (N_ROBOT * 32 + 255) / 256;
    final_kernel<<<fb, 256>>>(OFF, C, OFF + N_ROBOT, C + N_ROBOT, CSR,
                              t_rr, t_br, f_r, bsum1, out);
}

// round 11
// speedup vs baseline: 3.3893x; 1.0009x over previous
#include <cuda_runtime.h>
#include <cuda_bf16.h>
#include <stdint.h>

// ---------------------------------------------------------------------------
// Problem constants
// ---------------------------------------------------------------------------
#define N_ROBOT 100000
#define N_BALL  100000
#define E_MAX   600000
#define GB_ROBOT ((N_ROBOT + 63) / 64)   // 1563
#define GB_BALL  ((N_BALL + 63) / 64)    // 1563

// ---------------------------------------------------------------------------
// Scratch (device globals; allocation is forbidden)
// ---------------------------------------------------------------------------
#define O_TRR     0ull
#define O_TBR     (O_TRR + 6400000ull)
#define O_FR      (O_TBR + 6400000ull)
#define O_BSUM0   (O_FR  + 6400000ull)
#define O_BSUM1   (O_BSUM0 + 128ull)
#define O_WB0_RR  (O_BSUM1 + 64ull)
#define O_WB0_BR  (O_WB0_RR + 17408ull)
#define O_WBSUM0  (O_WB0_BR + 17408ull)
#define O_WB0_RB  (O_WBSUM0 + 17408ull)
#define O_WBR0_RB (O_WB0_RB + 17408ull)
#define O_WB1_RR  (O_WBR0_RB + 17408ull)
#define O_WBSUM1  (O_WB1_RR + 8704ull)
#define O_WB1_BR  (O_WBSUM1 + 8704ull)
#define SCRATCH_FLOATS (O_WB1_BR + 8704ull)

__device__ float g_scratch[SCRATCH_FLOATS];
__device__ int   g_cnt[3 * N_ROBOT];
__device__ int   g_off[3 * N_ROBOT];
__device__ int   g_cursor[3 * N_ROBOT];
__device__ int   g_csr[3 * E_MAX + 64];
__device__ int   g_bsum[1024];

#define NSCAN   (3 * N_ROBOT)
#define SCAN_BS 512
#define SCAN_NB ((NSCAN + SCAN_BS - 1) / SCAN_BS)

// ---------------------------------------------------------------------------
// Helpers (baseline PTX only)
// ---------------------------------------------------------------------------
__device__ __forceinline__ uint32_t smem_u32(const void* p) {
    uint32_t a;
    asm("{ .reg .u64 t; cvta.to.shared.u64 t, %1; cvt.u32.u64 %0, t; }"
        : "=r"(a) : "l"(p));
    return a;
}

#define LDSM_X4(r0, r1, r2, r3, addr) \
    asm volatile("ldmatrix.sync.aligned.m8n8.x4.shared.b16 {%0,%1,%2,%3}, [%4];" \
                 : "=r"(r0), "=r"(r1), "=r"(r2), "=r"(r3) : "r"(addr))

__device__ __forceinline__ void mma_bf16(float* c, const uint32_t* a,
                                         uint32_t b0, uint32_t b1) {
    asm volatile(
        "mma.sync.aligned.m16n8k16.row.col.f32.bf16.bf16.f32 "
        "{%0,%1,%2,%3}, {%4,%5,%6,%7}, {%8,%9}, {%0,%1,%2,%3};"
        : "+f"(c[0]), "+f"(c[1]), "+f"(c[2]), "+f"(c[3])
        : "r"(a[0]), "r"(a[1]), "r"(a[2]), "r"(a[3]), "r"(b0), "r"(b1));
}

__device__ __forceinline__ void split_pack(float x0, float x1,
                                           uint32_t& hp, uint32_t& lp) {
    __nv_bfloat16 h0 = __float2bfloat16(x0);
    __nv_bfloat16 h1 = __float2bfloat16(x1);
    __nv_bfloat16 l0 = __float2bfloat16(x0 - __bfloat162float(h0));
    __nv_bfloat16 l1 = __float2bfloat16(x1 - __bfloat162float(h1));
    hp = ((uint32_t)__bfloat16_as_ushort(h1) << 16) | __bfloat16_as_ushort(h0);
    lp = ((uint32_t)__bfloat16_as_ushort(l1) << 16) | __bfloat16_as_ushort(l0);
}

#define STRIDE_B 272u
#define A_BYTES  17408u
#define SMEM_TOTAL (2 * 17408 + 69632)   // 104448

// ---------------------------------------------------------------------------
// Stage loaders + mainloop
// ---------------------------------------------------------------------------
__device__ __forceinline__ void store_a_pair(uint32_t AH, uint32_t AL,
                                             uint32_t off, const float4& v) {
    uint32_t h01, l01, h23, l23;
    split_pack(v.x, v.y, h01, l01);
    split_pack(v.z, v.w, h23, l23);
    asm volatile("st.shared.v2.b32 [%0], {%1,%2};"
                 :: "r"(AH + off), "r"(h01), "r"(h23) : "memory");
    asm volatile("st.shared.v2.b32 [%0], {%1,%2};"
                 :: "r"(AL + off), "r"(l01), "r"(l23) : "memory");
}

__device__ __forceinline__ void load_A_direct(const float* __restrict__ A,
                                              int row0, int M,
                                              uint32_t AH, uint32_t AL, int tid) {
#pragma unroll
    for (int i = 0; i < 8; i++) {
        int idx = tid + i * 256;
        int r  = idx >> 5;
        int c4 = idx & 31;
        float4 v = make_float4(0.f, 0.f, 0.f, 0.f);
        if (row0 + r < M)
            v = *(const float4*)(A + (size_t)(row0 + r) * 128 + c4 * 4);
        store_a_pair(AH, AL, (uint32_t)r * STRIDE_B + (uint32_t)c4 * 8, v);
    }
}

__device__ __forceinline__ float4 row_load128(const float* __restrict__ x,
                                              int s, int lane) {
    return *(const float4*)(x + (size_t)s * 128 + lane * 4);
}

__device__ __forceinline__ void acc_add(float4& a, const float4& v) {
    a.x += v.x; a.y += v.y; a.z += v.z; a.w += v.w;
}

// 4-wide tail for one row.
__device__ __forceinline__ void gather_tail128(const float* __restrict__ x,
                                               const int* __restrict__ csr,
                                               int st, int& j, int dg,
                                               int lane, float4& a) {
    for (; j + 4 <= dg; j += 4) {
        int s0 = csr[st + j],     s1 = csr[st + j + 1];
        int s2 = csr[st + j + 2], s3 = csr[st + j + 3];
        float4 v0 = row_load128(x, s0, lane);
        float4 v1 = row_load128(x, s1, lane);
        float4 v2 = row_load128(x, s2, lane);
        float4 v3 = row_load128(x, s3, lane);
        a.x += (v0.x + v1.x) + (v2.x + v3.x);
        a.y += (v0.y + v1.y) + (v2.y + v3.y);
        a.z += (v0.z + v1.z) + (v2.z + v3.z);
        a.w += (v0.w + v1.w) + (v2.w + v3.w);
    }
    if (j + 2 <= dg) {
        int s0 = csr[st + j], s1 = csr[st + j + 1];
        float4 v0 = row_load128(x, s0, lane);
        float4 v1 = row_load128(x, s1, lane);
        a.x += v0.x + v1.x; a.y += v0.y + v1.y;
        a.z += v0.z + v1.z; a.w += v0.w + v1.w;
        j += 2;
    }
    if (j < dg) {
        float4 v = row_load128(x, csr[st + j], lane);
        acc_add(a, v);
        j++;
    }
}

// CSR mean-gather, PAIRWISE-interleaved rows: two independent neighbor chains
// in flight per warp -> 2x the memory-level parallelism of the serial version.
__device__ __forceinline__ void load_A_gather(const float* __restrict__ x,
                                              const int* __restrict__ off,
                                              const int* __restrict__ cnt,
                                              const int* __restrict__ csr,
                                              int row0, int M,
                                              uint32_t AH, uint32_t AL,
                                              int wid, int lane) {
#pragma unroll
    for (int p = 0; p < 4; p++) {
        int rA  = wid + (2 * p) * 8;
        int rB  = rA + 8;
        int grA = row0 + rA;
        int grB = row0 + rB;
        float4 aA = make_float4(0.f, 0.f, 0.f, 0.f);
        float4 aB = make_float4(0.f, 0.f, 0.f, 0.f);
        int stA = 0, dgA = 0, stB = 0, dgB = 0;
        if (grA < M) { stA = off[grA]; dgA = cnt[grA]; }
        if (grB < M) { stB = off[grB]; dgB = cnt[grB]; }
        int ja = 0, jb = 0;
        // fused main loop: 8 index loads + 8 row loads per iteration
        while (ja + 4 <= dgA && jb + 4 <= dgB) {
            int a0 = csr[stA + ja],     a1 = csr[stA + ja + 1];
            int a2 = csr[stA + ja + 2], a3 = csr[stA + ja + 3];
            int b0 = csr[stB + jb],     b1 = csr[stB + jb + 1];
            int b2 = csr[stB + jb + 2], b3 = csr[stB + jb + 3];
            float4 va0 = row_load128(x, a0, lane);
            float4 va1 = row_load128(x, a1, lane);
            float4 va2 = row_load128(x, a2, lane);
            float4 va3 = row_load128(x, a3, lane);
            float4 vb0 = row_load128(x, b0, lane);
            float4 vb1 = row_load128(x, b1, lane);
            float4 vb2 = row_load128(x, b2, lane);
            float4 vb3 = row_load128(x, b3, lane);
            aA.x += (va0.x + va1.x) + (va2.x + va3.x);
            aA.y += (va0.y + va1.y) + (va2.y + va3.y);
            aA.z += (va0.z + va1.z) + (va2.z + va3.z);
            aA.w += (va0.w + va1.w) + (va2.w + va3.w);
            aB.x += (vb0.x + vb1.x) + (vb2.x + vb3.x);
            aB.y += (vb0.y + vb1.y) + (vb2.y + vb3.y);
            aB.z += (vb0.z + vb1.z) + (vb2.z + vb3.z);
            aB.w += (vb0.w + vb1.w) + (vb2.w + vb3.w);
            ja += 4; jb += 4;
        }
        gather_tail128(x, csr, stA, ja, dgA, lane, aA);
        gather_tail128(x, csr, stB, jb, dgB, lane, aB);
        {
            float inv = (dgA > 0) ? (1.0f / (float)dgA) : 0.0f;
            aA.x *= inv; aA.y *= inv; aA.z *= inv; aA.w *= inv;
            store_a_pair(AH, AL, (uint32_t)rA * STRIDE_B + (uint32_t)lane * 8, aA);
        }
        {
            float inv = (dgB > 0) ? (1.0f / (float)dgB) : 0.0f;
            aB.x *= inv; aB.y *= inv; aB.z *= inv; aB.w *= inv;
            store_a_pair(AH, AL, (uint32_t)rB * STRIDE_B + (uint32_t)lane * 8, aB);
        }
    }
}

template <int N>
__device__ __forceinline__ void load_B_async(const float* __restrict__ src,
                                             uint32_t BB, int tid) {
    constexpr int T4 = (2 * N * 136 * 2) / 16;
#pragma unroll
    for (int i = tid; i < T4; i += 256) {
        asm volatile("cp.async.cg.shared.global [%0], [%1], 16;"
                     :: "r"(BB + (uint32_t)i * 16), "l"(src + (size_t)i * 4)
                     : "memory");
    }
}
__device__ __forceinline__ void cp_commit() {
    asm volatile("cp.async.commit_group;" ::: "memory");
}
__device__ __forceinline__ void cp_wait_all() {
    asm volatile("cp.async.wait_group 0;" ::: "memory");
}

template <int N>
__device__ __forceinline__ void mainloop(uint32_t AH, uint32_t AL,
                                         uint32_t BH, uint32_t BL,
                                         float (*acc)[4],
                                         int a_row, int a_kof,
                                         int b_nof, int b_kof, int wcg) {
    constexpr int NOCT = N / 16;
#pragma unroll
    for (int k0 = 0; k0 < 128; k0 += 16) {
        uint32_t ah[4], al[4];
        uint32_t aoff = (uint32_t)a_row * STRIDE_B + (uint32_t)(k0 + a_kof) * 2;
        LDSM_X4(ah[0], ah[1], ah[2], ah[3], AH + aoff);
        LDSM_X4(al[0], al[1], al[2], al[3], AL + aoff);
#pragma unroll
        for (int op = 0; op < NOCT; op += 2) {
            int nbase = wcg * (N / 2) + op * 8;
            uint32_t boff = (uint32_t)(nbase + b_nof) * STRIDE_B
                          + (uint32_t)(k0 + b_kof) * 2;
            uint32_t bh0, bh1, bh2, bh3, bl0, bl1, bl2, bl3;
            LDSM_X4(bh0, bh1, bh2, bh3, BH + boff);
            LDSM_X4(bl0, bl1, bl2, bl3, BL + boff);
            mma_bf16(acc[op],     ah, bh0, bh1);
            mma_bf16(acc[op],     al, bh0, bh1);
            mma_bf16(acc[op],     ah, bl0, bl1);
            mma_bf16(acc[op + 1], ah, bh2, bh3);
            mma_bf16(acc[op + 1], al, bh2, bh3);
            mma_bf16(acc[op + 1], ah, bl2, bl3);
        }
    }
}

// ---------------------------------------------------------------------------
// Small kernels: counts / CSR build
// ---------------------------------------------------------------------------
__global__ void count3_kernel(const int* __restrict__ d0,
                              const int* __restrict__ d1,
                              const int* __restrict__ d2,
                              int* __restrict__ cnt, int E) {
    int i = blockIdx.x * blockDim.x + threadIdx.x;
    if (i < E) atomicAdd(&cnt[d0[i]], 1);
    else if (i < 2 * E) atomicAdd(&cnt[N_ROBOT + d1[i - E]], 1);
    else if (i < 3 * E) atomicAdd(&cnt[2 * N_ROBOT + d2[i - 2 * E]], 1);
}

__global__ void fill3_csr_kernel(const int* __restrict__ s0, const int* __restrict__ d0,
                                 const int* __restrict__ s1, const int* __restrict__ d1,
                                 const int* __restrict__ s2, const int* __restrict__ d2,
                                 int* __restrict__ cursor,
                                 int* __restrict__ csr, int E) {
    int i = blockIdx.x * blockDim.x + threadIdx.x;
    int pos;
    if (i < E) {
        pos = atomicAdd(&cursor[d0[i]], 1);
        csr[pos] = s0[i];
    } else if (i < 2 * E) {
        pos = atomicAdd(&cursor[N_ROBOT + d1[i - E]], 1);
        csr[pos] = s1[i - E];
    } else if (i < 3 * E) {
        pos = atomicAdd(&cursor[2 * N_ROBOT + d2[i - 2 * E]], 1);
        csr[pos] = s2[i - 2 * E];
    }
}

__global__ void scan1_kernel(const int* __restrict__ cnt,
                             int* __restrict__ out, int* __restrict__ bsum) {
    __shared__ int sh[SCAN_BS];
    int gid = blockIdx.x * SCAN_BS + threadIdx.x;
    int v = (gid < NSCAN) ? cnt[gid] : 0;
    sh[threadIdx.x] = v;
    __syncthreads();
#pragma unroll
    for (int d = 1; d < SCAN_BS; d <<= 1) {
        int t = (threadIdx.x >= d) ? sh[threadIdx.x - d] : 0;
        __syncthreads();
        sh[threadIdx.x] += t;
        __syncthreads();
    }
    if (gid < NSCAN) out[gid] = sh[threadIdx.x] - v;
    if (threadIdx.x == SCAN_BS - 1) bsum[blockIdx.x] = sh[threadIdx.x];
}

__global__ void scan2_kernel(int* __restrict__ bsum) {
    __shared__ int sh[1024];
    int i = threadIdx.x;
    int v = (i < SCAN_NB) ? bsum[i] : 0;
    sh[i] = v;
    __syncthreads();
#pragma unroll
    for (int d = 1; d < 1024; d <<= 1) {
        int t = (i >= d) ? sh[i - d] : 0;
        __syncthreads();
        sh[i] += t;
        __syncthreads();
    }
    if (i < SCAN_NB) bsum[i] = sh[i] - v;
}

__global__ void scan3_kernel(int* __restrict__ out, const int* __restrict__ bsum,
                             int* __restrict__ cursor) {
    int gid = blockIdx.x * SCAN_BS + threadIdx.x;
    if (gid < NSCAN) {
        int o = out[gid] + bsum[blockIdx.x];
        out[gid] = o;
        cursor[gid] = o;
    }
}

// ---------------------------------------------------------------------------
// Unified prep kernel: 8 weight splits + 2 bias folds in ONE launch.
// ---------------------------------------------------------------------------
__device__ __forceinline__ void split_one(const float* __restrict__ A,
                                          const float* __restrict__ B2,
                                          float* __restrict__ outf,
                                          int N, int e) {
    if (e >= 128 * N) return;
    int k = e / N;
    int n = e - k * N;
    float w = A[e];
    if (B2) w += B2[e];
    __nv_bfloat16 h = __float2bfloat16(w);
    __nv_bfloat16 l = __float2bfloat16(w - __bfloat162float(h));
    __nv_bfloat16* out = (__nv_bfloat16*)outf;
    out[n * 136 + k] = h;
    out[(size_t)N * 136 + n * 136 + k] = l;
}

__global__ void prep_kernel(const float* __restrict__ Wl0_rr,
                            const float* __restrict__ Wl0_br,
                            const float* __restrict__ Wr0_rr,
                            const float* __restrict__ Wr0_br,
                            const float* __restrict__ Wl0_rb,
                            const float* __restrict__ Wr0_rb,
                            const float* __restrict__ Wl1_rr,
                            const float* __restrict__ Wr1_rr,
                            const float* __restrict__ Wr1_br,
                            const float* __restrict__ Wl1_br,
                            const float* __restrict__ b0_rr,
                            const float* __restrict__ b0_br,
                            const float* __restrict__ b1_rr,
                            const float* __restrict__ b1_br,
                            float* __restrict__ WB0_rr,
                            float* __restrict__ WB0_br,
                            float* __restrict__ WBsum0,
                            float* __restrict__ WB0_rb,
                            float* __restrict__ WBr0_rb,
                            float* __restrict__ WB1_rr,
                            float* __restrict__ WBsum1,
                            float* __restrict__ WB1_br,
                            float* __restrict__ bsum0,
                            float* __restrict__ bsum1) {
    int b = blockIdx.x;
    int t = threadIdx.x;
    if (b < 320) {
        int seg = b >> 6;
        int e = (b & 63) * 256 + t;
        switch (seg) {
            case 0: split_one(Wl0_rr, nullptr, WB0_rr, 128, e); break;
            case 1: split_one(Wl0_br, nullptr, WB0_br, 128, e); break;
            case 2: split_one(Wr0_rr, Wr0_br, WBsum0, 128, e); break;
            case 3: split_one(Wl0_rb, nullptr, WB0_rb, 128, e); break;
            default: split_one(Wr0_rb, nullptr, WBr0_rb, 128, e); break;
        }
    } else if (b < 416) {
        int seg = (b - 320) >> 5;
        int e = ((b - 320) & 31) * 256 + t;
        switch (seg) {
            case 0: split_one(Wl1_rr, nullptr, WB1_rr, 64, e); break;
            case 1: split_one(Wr1_rr, Wr1_br, WBsum1, 64, e); break;
            default: split_one(Wl1_br, nullptr, WB1_br, 64, e); break;
        }
    } else {
        if (t < 128) bsum0[t] = b0_rr[t] + b0_br[t];
        else if (t < 192) bsum1[t - 128] = b1_rr[t - 128] + b1_br[t - 128];
    }
}

// ---------------------------------------------------------------------------
// Unified fused GEMM kernel
// ---------------------------------------------------------------------------
__global__ void __launch_bounds__(256, 2)
fused_kernel(const float* __restrict__ x_robot,
             const float* __restrict__ x_ball,
             const int* __restrict__ off, const int* __restrict__ cnt,
             const int* __restrict__ csr,
             const float* __restrict__ WB0_rr,
             const float* __restrict__ WB0_br,
             const float* __restrict__ WBsum0,
             const float* __restrict__ bsum0,
             const float* __restrict__ WB1_rr,
             const float* __restrict__ WBsum1,
             const float* __restrict__ WB0_rb,
             const float* __restrict__ WBr0_rb,
             const float* __restrict__ b0_rb,
             const float* __restrict__ WB1_br,
             float* __restrict__ t_rr,
             float* __restrict__ f_r,
             float* __restrict__ t_br) {
    extern __shared__ char smem[];
    const uint32_t AH = smem_u32(smem);
    const uint32_t AL = AH + A_BYTES;
    const uint32_t BB = AL + A_BYTES;

    const int tid  = threadIdx.x;
    const int wid  = tid >> 5;
    const int lane = tid & 31;
    const int wr   = wid & 3;
    const int wcg  = wid >> 2;

    const int a_row = wr * 16 + ((lane >> 3) & 1) * 8 + (lane & 7);
    const int a_kof = (lane >> 4) * 8;
    const int b_nof = ((lane >> 4) & 1) * 8 + (lane & 7);
    const int b_kof = ((lane >> 3) & 1) * 8;

    float acc[8][4];
#pragma unroll
    for (int o = 0; o < 8; o++)
#pragma unroll
        for (int j = 0; j < 4; j++) acc[o][j] = 0.0f;

    const bool robot = (blockIdx.x < GB_ROBOT);

    if (robot) {
        const int row0 = blockIdx.x * 64;
        const int M    = N_ROBOT;

        load_B_async<128>(WB0_rr, BB, tid);
        cp_commit();
        load_A_gather(x_robot, off, cnt, csr, row0, M, AH, AL, wid, lane);
        cp_wait_all();
        __syncthreads();
        mainloop<128>(AH, AL, BB, BB + 34816, acc, a_row, a_kof, b_nof, b_kof, wcg);
        __syncthreads();
        load_B_async<128>(WB0_br, BB, tid);
        cp_commit();
        load_A_gather(x_ball, off + N_ROBOT, cnt + N_ROBOT, csr, row0, M, AH, AL, wid, lane);
        cp_wait_all();
        __syncthreads();
        mainloop<128>(AH, AL, BB, BB + 34816, acc, a_row, a_kof, b_nof, b_kof, wcg);
        __syncthreads();
        load_B_async<128>(WBsum0, BB, tid);
        cp_commit();
        load_A_direct(x_robot, row0, M, AH, AL, tid);
        cp_wait_all();
        __syncthreads();
        mainloop<128>(AH, AL, BB, BB + 34816, acc, a_row, a_kof, b_nof, b_kof, wcg);
        __syncthreads();

        load_B_async<64>(WB1_rr, BB, tid);
        load_B_async<64>(WBsum1, BB + 2 * 17408, tid);
        cp_commit();

        {
            const int rAl = wr * 16 + (lane >> 2);
            const int rBl = rAl + 8;
#pragma unroll
            for (int o = 0; o < 8; o++) {
                int col = wcg * 64 + o * 8 + (lane & 3) * 2;
                float2 bv = *(const float2*)(bsum0 + col);
                float v0 = fmaxf(acc[o][0] + bv.x, 0.f);
                float v1 = fmaxf(acc[o][1] + bv.y, 0.f);
                float v2 = fmaxf(acc[o][2] + bv.x, 0.f);
                float v3 = fmaxf(acc[o][3] + bv.y, 0.f);
                uint32_t h, l;
                uint32_t offA = (uint32_t)rAl * STRIDE_B + (uint32_t)col * 2;
                split_pack(v0, v1, h, l);
                asm volatile("st.shared.b32 [%0], %1;" :: "r"(AH + offA), "r"(h) : "memory");
                asm volatile("st.shared.b32 [%0], %1;" :: "r"(AL + offA), "r"(l) : "memory");
                uint32_t offB = (uint32_t)rBl * STRIDE_B + (uint32_t)col * 2;
                split_pack(v2, v3, h, l);
                asm volatile("st.shared.b32 [%0], %1;" :: "r"(AH + offB), "r"(h) : "memory");
                asm volatile("st.shared.b32 [%0], %1;" :: "r"(AL + offB), "r"(l) : "memory");
            }
        }
        cp_wait_all();
        __syncthreads();

        float acc2a[4][4], acc2b[4][4];
#pragma unroll
        for (int o = 0; o < 4; o++)
#pragma unroll
            for (int j = 0; j < 4; j++) { acc2a[o][j] = 0.f; acc2b[o][j] = 0.f; }

        mainloop<64>(AH, AL, BB,             BB + 17408,     acc2a,
                     a_row, a_kof, b_nof, b_kof, wcg);
        mainloop<64>(AH, AL, BB + 2 * 17408, BB + 3 * 17408, acc2b,
                     a_row, a_kof, b_nof, b_kof, wcg);

        const int rA = row0 + wr * 16 + (lane >> 2);
        const int rB = rA + 8;
#pragma unroll
        for (int o = 0; o < 4; o++) {
            int col = wcg * 32 + o * 8 + (lane & 3) * 2;
            if (rA < M) {
                *(float2*)(t_rr + (size_t)rA * 64 + col) = make_float2(acc2a[o][0], acc2a[o][1]);
                *(float2*)(f_r  + (size_t)rA * 64 + col) = make_float2(acc2b[o][0], acc2b[o][1]);
            }
            if (rB < M) {
                *(float2*)(t_rr + (size_t)rB * 64 + col) = make_float2(acc2a[o][2], acc2a[o][3]);
                *(float2*)(f_r  + (size_t)rB * 64 + col) = make_float2(acc2b[o][2], acc2b[o][3]);
            }
        }
    } else {
        const int row0 = (blockIdx.x - GB_ROBOT) * 64;
        const int M    = N_BALL;

        load_B_async<128>(WB0_rb, BB, tid);
        cp_commit();
        load_A_gather(x_robot, off + 2 * N_ROBOT, cnt + 2 * N_ROBOT, csr,
                      row0, M, AH, AL, wid, lane);
        cp_wait_all();
        __syncthreads();
        mainloop<128>(AH, AL, BB, BB + 34816, acc, a_row, a_kof, b_nof, b_kof, wcg);
        __syncthreads();
        load_B_async<128>(WBr0_rb, BB, tid);
        cp_commit();
        load_A_direct(x_ball, row0, M, AH, AL, tid);
        cp_wait_all();
        __syncthreads();
        mainloop<128>(AH, AL, BB, BB + 34816, acc, a_row, a_kof, b_nof, b_kof, wcg);
        __syncthreads();

        load_B_async<64>(WB1_br, BB, tid);
        cp_commit();
        {
            const int rAl = wr * 16 + (lane >> 2);
            const int rBl = rAl + 8;
#pragma unroll
            for (int o = 0; o < 8; o++) {
                int col = wcg * 64 + o * 8 + (lane & 3) * 2;
                float2 bv = *(const float2*)(b0_rb + col);
                float v0 = fmaxf(acc[o][0] + bv.x, 0.f);
                float v1 = fmaxf(acc[o][1] + bv.y, 0.f);
                float v2 = fmaxf(acc[o][2] + bv.x, 0.f);
                float v3 = fmaxf(acc[o][3] + bv.y, 0.f);
                uint32_t h, l;
                uint32_t offA = (uint32_t)rAl * STRIDE_B + (uint32_t)col * 2;
                split_pack(v0, v1, h, l);
                asm volatile("st.shared.b32 [%0], %1;" :: "r"(AH + offA), "r"(h) : "memory");
                asm volatile("st.shared.b32 [%0], %1;" :: "r"(AL + offA), "r"(l) : "memory");
                uint32_t offB = (uint32_t)rBl * STRIDE_B + (uint32_t)col * 2;
                split_pack(v2, v3, h, l);
                asm volatile("st.shared.b32 [%0], %1;" :: "r"(AH + offB), "r"(h) : "memory");
                asm volatile("st.shared.b32 [%0], %1;" :: "r"(AL + offB), "r"(l) : "memory");
            }
        }
        cp_wait_all();
        __syncthreads();

        float acc2[4][4];
#pragma unroll
        for (int o = 0; o < 4; o++)
#pragma unroll
            for (int j = 0; j < 4; j++) acc2[o][j] = 0.f;

        mainloop<64>(AH, AL, BB, BB + 17408, acc2, a_row, a_kof, b_nof, b_kof, wcg);

        const int rA = row0 + wr * 16 + (lane >> 2);
        const int rB = rA + 8;
#pragma unroll
        for (int o = 0; o < 4; o++) {
            int col = wcg * 32 + o * 8 + (lane & 3) * 2;
            if (rA < M)
                *(float2*)(t_br + (size_t)rA * 64 + col) = make_float2(acc2[o][0], acc2[o][1]);
            if (rB < M)
                *(float2*)(t_br + (size_t)rB * 64 + col) = make_float2(acc2[o][2], acc2[o][3]);
        }
    }
}

// ---------------------------------------------------------------------------
// Final: out[d] = mean_rr(t_rr) + mean_br(t_br) + f_r[d] + bsum1
// rr and br gathers fused into one interleaved loop (2x MLP).
// ---------------------------------------------------------------------------
__device__ __forceinline__ float2 row_load64(const float* __restrict__ t,
                                             int s, int lane) {
    return *(const float2*)(t + (size_t)s * 64 + lane * 2);
}

__device__ __forceinline__ void tail64(const float* __restrict__ t,
                                       const int* __restrict__ csr,
                                       int st, int& j, int dg,
                                       int lane, float2& a) {
    for (; j + 4 <= dg; j += 4) {
        int s0 = csr[st + j], s1 = csr[st + j + 1];
        int s2 = csr[st + j + 2], s3 = csr[st + j + 3];
        float2 v0 = row_load64(t, s0, lane);
        float2 v1 = row_load64(t, s1, lane);
        float2 v2 = row_load64(t, s2, lane);
        float2 v3 = row_load64(t, s3, lane);
        a.x += (v0.x + v1.x) + (v2.x + v3.x);
        a.y += (v0.y + v1.y) + (v2.y + v3.y);
    }
    if (j + 2 <= dg) {
        int s0 = csr[st + j], s1 = csr[st + j + 1];
        float2 v0 = row_load64(t, s0, lane);
        float2 v1 = row_load64(t, s1, lane);
        a.x += v0.x + v1.x; a.y += v0.y + v1.y;
        j += 2;
    }
    if (j < dg) {
        float2 v = row_load64(t, csr[st + j], lane);
        a.x += v.x; a.y += v.y;
    }
}

__global__ void __launch_bounds__(256)
final_kernel(const int* __restrict__ off_rr, const int* __restrict__ cnt_rr,
             const int* __restrict__ off_br, const int* __restrict__ cnt_br,
             const int* __restrict__ csr,
             const float* __restrict__ t_rr, const float* __restrict__ t_br,
             const float* __restrict__ f_r, const float* __restrict__ bsum1,
             float* __restrict__ out) {
    int warp = (blockIdx.x * blockDim.x + threadIdx.x) >> 5;
    int lane = threadIdx.x & 31;
    if (warp >= N_ROBOT) return;

    float2 res = *(const float2*)(f_r + (size_t)warp * 64 + lane * 2);
    float2 bv  = *(const float2*)(bsum1 + lane * 2);
    res.x += bv.x; res.y += bv.y;

    int st0 = off_rr[warp], dg0 = cnt_rr[warp];
    int st1 = off_br[warp], dg1 = cnt_br[warp];
    float2 a0 = make_float2(0.f, 0.f);
    float2 a1 = make_float2(0.f, 0.f);
    int j0 = 0, j1 = 0;
    while (j0 + 4 <= dg0 && j1 + 4 <= dg1) {
        int r0 = csr[st0 + j0],     r1 = csr[st0 + j0 + 1];
        int r2 = csr[st0 + j0 + 2], r3 = csr[st0 + j0 + 3];
        int b0 = csr[st1 + j1],     b1 = csr[st1 + j1 + 1];
        int b2 = csr[st1 + j1 + 2], b3 = csr[st1 + j1 + 3];
        float2 u0 = row_load64(t_rr, r0, lane);
        float2 u1 = row_load64(t_rr, r1, lane);
        float2 u2 = row_load64(t_rr, r2, lane);
        float2 u3 = row_load64(t_rr, r3, lane);
        float2 w0 = row_load64(t_br, b0, lane);
        float2 w1 = row_load64(t_br, b1, lane);
        float2 w2 = row_load64(t_br, b2, lane);
        float2 w3 = row_load64(t_br, b3, lane);
        a0.x += (u0.x + u1.x) + (u2.x + u3.x);
        a0.y += (u0.y + u1.y) + (u2.y + u3.y);
        a1.x += (w0.x + w1.x) + (w2.x + w3.x);
        a1.y += (w0.y + w1.y) + (w2.y + w3.y);
        j0 += 4; j1 += 4;
    }
    tail64(t_rr, csr, st0, j0, dg0, lane, a0);
    tail64(t_br, csr, st1, j1, dg1, lane, a1);

    float inv0 = (dg0 > 0) ? (1.0f / (float)dg0) : 0.0f;
    float inv1 = (dg1 > 0) ? (1.0f / (float)dg1) : 0.0f;
    res.x += a0.x * inv0 + a1.x * inv1;
    res.y += a0.y * inv0 + a1.y * inv1;

    *(float2*)(out + (size_t)warp * 64 + lane * 2) = res;
}

// ---------------------------------------------------------------------------
// Launch
// ---------------------------------------------------------------------------
extern "C" void kernel_launch(void* const* d_in, const int* in_sizes, int n_in,
                              void* d_out, int out_size) {
    (void)n_in; (void)out_size;

    const float* x_robot = (const float*)d_in[0];
    const float* x_ball  = (const float*)d_in[1];
    const int* ei_rr = (const int*)d_in[2];
    const int* ei_rb = (const int*)d_in[3];
    const int* ei_br = (const int*)d_in[4];
    const float* Wl0_rr = (const float*)d_in[5];
    const float* Wr0_rr = (const float*)d_in[6];
    const float* b0_rr  = (const float*)d_in[7];
    const float* Wl0_rb = (const float*)d_in[8];
    const float* Wr0_rb = (const float*)d_in[9];
    const float* b0_rb  = (const float*)d_in[10];
    const float* Wl0_br = (const float*)d_in[11];
    const float* Wr0_br = (const float*)d_in[12];
    const float* b0_br  = (const float*)d_in[13];
    const float* Wl1_rr = (const float*)d_in[14];
    const float* Wr1_rr = (const float*)d_in[15];
    const float* b1_rr  = (const float*)d_in[16];
    const float* Wl1_br = (const float*)d_in[20];
    const float* Wr1_br = (const float*)d_in[21];
    const float* b1_br  = (const float*)d_in[22];

    float* out = (float*)d_out;
    const int E = in_sizes[2] / 2;

    float* S = nullptr;
    int *C = nullptr, *OFF = nullptr, *CUR = nullptr, *CSR = nullptr, *BS = nullptr;
    {
        void* p = nullptr;
        cudaGetSymbolAddress(&p, g_scratch); S = (float*)p;
        cudaGetSymbolAddress(&p, g_cnt);     C = (int*)p;
        cudaGetSymbolAddress(&p, g_off);     OFF = (int*)p;
        cudaGetSymbolAddress(&p, g_cursor);  CUR = (int*)p;
        cudaGetSymbolAddress(&p, g_csr);     CSR = (int*)p;
        cudaGetSymbolAddress(&p, g_bsum);    BS = (int*)p;
    }

    float* t_rr    = S + O_TRR;
    float* t_br    = S + O_TBR;
    float* f_r     = S + O_FR;
    float* bsum0   = S + O_BSUM0;
    float* bsum1   = S + O_BSUM1;
    float* WB0_rr  = S + O_WB0_RR;
    float* WB0_br  = S + O_WB0_BR;
    float* WBsum0  = S + O_WBSUM0;
    float* WB0_rb  = S + O_WB0_RB;
    float* WBr0_rb = S + O_WBR0_RB;
    float* WB1_rr  = S + O_WB1_RR;
    float* WBsum1  = S + O_WBSUM1;
    float* WB1_br  = S + O_WB1_BR;

    cudaFuncSetAttribute(fused_kernel,
                         cudaFuncAttributeMaxDynamicSharedMemorySize, SMEM_TOTAL);

    // ---- counts ----
    cudaMemsetAsync(C, 0, 3ull * N_ROBOT * sizeof(int), 0);
    const int cb3 = (3 * E + 255) / 256;
    count3_kernel<<<cb3, 256>>>(ei_rr + E, ei_br + E, ei_rb + E, C, E);

    // ---- CSR build ----
    scan1_kernel<<<SCAN_NB, SCAN_BS>>>(C, OFF, BS);
    scan2_kernel<<<1, 1024>>>(BS);
    scan3_kernel<<<SCAN_NB, SCAN_BS>>>(OFF, BS, CUR);
    fill3_csr_kernel<<<cb3, 256>>>(ei_rr, ei_rr + E, ei_br, ei_br + E,
                                   ei_rb, ei_rb + E, CUR, CSR, E);

    // ---- unified weight/bias prep ----
    prep_kernel<<<417, 256>>>(Wl0_rr, Wl0_br, Wr0_rr, Wr0_br, Wl0_rb, Wr0_rb,
                              Wl1_rr, Wr1_rr, Wr1_br, Wl1_br,
                              b0_rr, b0_br, b1_rr, b1_br,
                              WB0_rr, WB0_br, WBsum0, WB0_rb, WBr0_rb,
                              WB1_rr, WBsum1, WB1_br, bsum0, bsum1);

    // ---- unified fused compute ----
    fused_kernel<<<GB_ROBOT + GB_BALL, 256, SMEM_TOTAL>>>(
        x_robot, x_ball, OFF, C, CSR,
        WB0_rr, WB0_br, WBsum0, bsum0, WB1_rr, WBsum1,
        WB0_rb, WBr0_rb, b0_rb, WB1_br,
        t_rr, f_r, t_br);

    // ---- final combine ----
    const int fb = (N_ROBOT * 32 + 255) / 256;
    final_kernel<<<fb, 256>>>(OFF, C, OFF + N_ROBOT, C + N_ROBOT, CSR,
                              t_rr, t_br, f_r, bsum1, out);
}